// round 14
// baseline (speedup 1.0000x reference)
#include <cuda_runtime.h>
#include <math.h>
#include <stdint.h>

// ---------------- problem constants ----------------
#define BATCH   8
#define CCH     640
#define HW      1024
#define MTOK    (BATCH*HW)
#define HEADS   8
#define DH      80
#define CTX     77
#define CTXD    768
#define FF      2560
#define GROUPS  32
#define CPG     (CCH/GROUPS)

// arch-feature gate: tcgen05 only exists in the sm_103a pass
#if defined(__CUDA_ARCH__) && (defined(__CUDA_ARCH_FEAT_SM103_ALL) || defined(__CUDA_ARCH_SPECIFIC__))
#define HAS_TCGEN05 1
#else
#define HAS_TCGEN05 0
#endif

// ---------------- scratch ----------------
__device__ float g_t   [MTOK*CCH];
__device__ float g_tn  [MTOK*CCH];
__device__ float g_q   [MTOK*CCH];
__device__ float g_ao  [MTOK*CCH];
__device__ float g_qkv [(size_t)MTOK*1920];
__device__ float g_kv  [BATCH*CTX*1280];
__device__ float g_ff  [(size_t)MTOK*FF];
__device__ float g_wt  [(size_t)5120*640];
__device__ float g_stats[BATCH*GROUPS*2];

// ================= common PTX helpers =================
__device__ __forceinline__ uint32_t smem_u32(const void* p) {
    uint32_t a;
    asm("{ .reg .u64 t; cvta.to.shared.u64 t, %1; cvt.u32.u64 %0, t; }" : "=r"(a) : "l"(p));
    return a;
}
__device__ __forceinline__ void cp_async16(void* smem_ptr, const float* gptr, bool pred)
{
    uint32_t saddr = smem_u32(smem_ptr);
    int sz = pred ? 16 : 0;
    asm volatile("cp.async.cg.shared.global [%0], [%1], 16, %2;\n"
                 :: "r"(saddr), "l"(gptr), "r"(sz));
}
__device__ __forceinline__ void cp_commit() { asm volatile("cp.async.commit_group;\n" ::: "memory"); }
__device__ __forceinline__ void cp_wait0()  { asm volatile("cp.async.wait_group 0;\n" ::: "memory"); }
__device__ __forceinline__ void cp_wait1()  { asm volatile("cp.async.wait_group 1;\n" ::: "memory"); }

__device__ __forceinline__ void mma_tf32(float& d0, float& d1, float& d2, float& d3,
                                         uint32_t a0, uint32_t a1, uint32_t a2, uint32_t a3,
                                         uint32_t b0, uint32_t b1)
{
    asm volatile(
        "mma.sync.aligned.m16n8k8.row.col.f32.tf32.tf32.f32 "
        "{%0,%1,%2,%3}, {%4,%5,%6,%7}, {%8,%9}, {%0,%1,%2,%3};\n"
        : "+f"(d0), "+f"(d1), "+f"(d2), "+f"(d3)
        : "r"(a0), "r"(a1), "r"(a2), "r"(a3), "r"(b0), "r"(b1));
}

#if HAS_TCGEN05
__device__ __forceinline__ uint32_t elect_one() {
    uint32_t p;
    asm volatile("{\n\t.reg .pred p;\n\telect.sync _|p, 0xFFFFFFFF;\n\tselp.b32 %0, 1, 0, p;\n\t}" : "=r"(p));
    return p;
}
#define TCGEN05_ALLOC(smem_addr, nCols) \
    asm volatile("tcgen05.alloc.cta_group::1.sync.aligned.shared::cta.b32 [%0], %1;" \
                 :: "r"((uint32_t)(smem_addr)), "r"((uint32_t)(nCols)) : "memory")
#define TCGEN05_DEALLOC(tmem, nCols) \
    asm volatile("tcgen05.dealloc.cta_group::1.sync.aligned.b32 %0, %1;" :: "r"(tmem), "r"((uint32_t)(nCols)))
#define TCGEN05_RELINQ() \
    asm volatile("tcgen05.relinquish_alloc_permit.cta_group::1.sync.aligned;")
#define TCGEN05_COMMIT(mbar) \
    asm volatile("tcgen05.commit.cta_group::1.mbarrier::arrive::one.shared::cluster.b64 [%0];" \
                 :: "r"((uint32_t)(mbar)) : "memory")
#define TCGEN05_FENCE_AFTER() asm volatile("tcgen05.fence::after_thread_sync;" ::: "memory")
#define TCGEN05_WAIT_LD()     asm volatile("tcgen05.wait::ld.sync.aligned;" ::: "memory")
#define FENCE_ASYNC_SHARED()  asm volatile("fence.proxy.async.shared::cta;" ::: "memory")
#define MBARRIER_INIT(mbar, cnt) \
    asm volatile("mbarrier.init.shared.b64 [%0], %1;" :: "r"((uint32_t)(mbar)), "r"((uint32_t)(cnt)) : "memory")
#define MBARRIER_WAIT_PARITY(mbar, ph) do {                                           \
    uint32_t _m = (uint32_t)(mbar), _p = (uint32_t)(ph), _d;                          \
    asm volatile("{\n\t.reg .pred p;\n\t"                                             \
        "mbarrier.try_wait.parity.acquire.cta.shared::cta.b64 p, [%1], %2;\n\t"       \
        "selp.b32 %0, 1, 0, p;\n\t}" : "=r"(_d) : "r"(_m), "r"(_p) : "memory");       \
    if (!_d) {                                                                        \
        asm volatile("{\n\t.reg .pred P1;\n\t"                                        \
            "WL_%=:\n\t"                                                              \
            "mbarrier.try_wait.parity.acquire.cta.shared::cta.b64 P1, [%0], %1, 0x989680;\n\t" \
            "@P1 bra.uni WD_%=;\n\t"                                                  \
            "bra.uni WL_%=;\n\t"                                                      \
            "WD_%=:\n\t}" :: "r"(_m), "r"(_p) : "memory");                            \
    }                                                                                 \
} while (0)
#define TCGEN05_LD_X32(r, tmem)                                                        \
    asm volatile("tcgen05.ld.sync.aligned.32x32b.x32.b32 "                             \
        "{%0, %1, %2, %3, %4, %5, %6, %7, "                                            \
        " %8, %9, %10, %11, %12, %13, %14, %15, "                                      \
        " %16, %17, %18, %19, %20, %21, %22, %23, "                                    \
        " %24, %25, %26, %27, %28, %29, %30, %31}, [%32];"                             \
        : "=r"((r)[0]),  "=r"((r)[1]),  "=r"((r)[2]),  "=r"((r)[3]),                   \
          "=r"((r)[4]),  "=r"((r)[5]),  "=r"((r)[6]),  "=r"((r)[7]),                   \
          "=r"((r)[8]),  "=r"((r)[9]),  "=r"((r)[10]), "=r"((r)[11]),                  \
          "=r"((r)[12]), "=r"((r)[13]), "=r"((r)[14]), "=r"((r)[15]),                  \
          "=r"((r)[16]), "=r"((r)[17]), "=r"((r)[18]), "=r"((r)[19]),                  \
          "=r"((r)[20]), "=r"((r)[21]), "=r"((r)[22]), "=r"((r)[23]),                  \
          "=r"((r)[24]), "=r"((r)[25]), "=r"((r)[26]), "=r"((r)[27]),                  \
          "=r"((r)[28]), "=r"((r)[29]), "=r"((r)[30]), "=r"((r)[31])                   \
        : "r"(tmem))

__device__ __forceinline__ void tc_mma_tf32_ss(uint32_t d, uint64_t ad, uint64_t bd,
                                               uint32_t idesc, uint32_t en)
{
    asm volatile("{\n\t.reg .pred p;\n\tsetp.ne.u32 p, %4, 0;\n\t"
        "tcgen05.mma.cta_group::1.kind::tf32 [%0], %1, %2, %3, {%5,%5,%5,%5}, p;\n\t}"
        :: "r"(d), "l"(ad), "l"(bd), "r"(idesc), "r"(en), "r"(0u) : "memory");
}
__device__ __forceinline__ uint64_t make_desc(uint32_t saddr)
{
    return (uint64_t(2) << 61) | (uint64_t(1) << 46) | (uint64_t(64) << 32)
         | (uint64_t(1) << 16) | ((uint64_t)(saddr >> 4) & 0x3FFF);
}
#define TC_IDESC ((1u<<4)|(2u<<7)|(2u<<10)|((128u/8u)<<17)|((128u/16u)<<24))
#endif  // HAS_TCGEN05

// ================= GroupNorm =================
__global__ void gn_stats_kernel(const float* __restrict__ x, float* __restrict__ stats)
{
    int bg = blockIdx.x;
    int b = bg / GROUPS, g = bg % GROUPS;
    const float* base = x + (size_t)b*CCH*HW + (size_t)g*CPG*HW;
    int tid = threadIdx.x;
    float s = 0.f, ss = 0.f;
    for (int i = tid; i < CPG*HW; i += 256) { float v = base[i]; s += v; ss += v*v; }
    __shared__ float r1[256], r2[256];
    r1[tid] = s; r2[tid] = ss; __syncthreads();
    for (int st = 128; st > 0; st >>= 1) {
        if (tid < st) { r1[tid] += r1[tid+st]; r2[tid] += r2[tid+st]; }
        __syncthreads();
    }
    if (tid == 0) {
        const float inv = 1.f / (float)(CPG*HW);
        float mean = r1[0]*inv;
        float var  = r2[0]*inv - mean*mean;
        stats[bg*2]   = mean;
        stats[bg*2+1] = rsqrtf(var + 1e-6f);
    }
}

__global__ void gn_apply_kernel(const float* __restrict__ x,
                                const float* __restrict__ gamma,
                                const float* __restrict__ beta,
                                const float* __restrict__ stats,
                                float* __restrict__ out)
{
    __shared__ float tile[32][33];
    int b  = blockIdx.z;
    int c0 = blockIdx.y*32, hw0 = blockIdx.x*32;
    int tx = threadIdx.x, ty = threadIdx.y;
    #pragma unroll
    for (int i = 0; i < 32; i += 8) {
        int c = c0 + ty + i;
        int bg = b*GROUPS + c/CPG;
        float mean = stats[bg*2], rstd = stats[bg*2+1];
        float v = x[((size_t)b*CCH + c)*HW + hw0 + tx];
        tile[ty+i][tx] = (v - mean)*rstd*gamma[c] + beta[c];
    }
    __syncthreads();
    #pragma unroll
    for (int i = 0; i < 32; i += 8) {
        int hw = hw0 + ty + i;
        out[((size_t)b*HW + hw)*CCH + c0 + tx] = tile[tx][ty+i];
    }
}

// ================= weight transpose w[K][N] -> wt[N][K] =================
__global__ void transpose_w(const float* __restrict__ w, float* __restrict__ wt, int K, int N)
{
    __shared__ float t[32][33];
    int k0 = blockIdx.y*32, n0 = blockIdx.x*32;
    int tx = threadIdx.x, ty = threadIdx.y;
    #pragma unroll
    for (int i = 0; i < 32; i += 8)
        t[ty+i][tx] = w[(size_t)(k0+ty+i)*N + n0 + tx];
    __syncthreads();
    #pragma unroll
    for (int i = 0; i < 32; i += 8)
        wt[(size_t)(n0+ty+i)*K + k0 + tx] = t[tx][ty+i];
}

// ================= GEMM 128x128: C = A @ Bt^T (+bias)(+=) =====
#define TCG_STAGE 65536
#define TCG_CTRL  (3*TCG_STAGE)
#define GEMM_SMEM (3*TCG_STAGE + 64)

__global__ __launch_bounds__(256, 1)
void gemm_tc_kernel(const float* __restrict__ A, const float* __restrict__ Bt,
                    const float* __restrict__ bias, float* __restrict__ C,
                    int M, int N, int K, int accumulate)
{
    extern __shared__ float smem[];
    int tid = threadIdx.x, lane = tid & 31;
    int m0 = blockIdx.y * 128, n0 = blockIdx.x * 128;

#if HAS_TCGEN05
    char* sbase = (char*)smem;
    uint32_t sb = smem_u32(smem);
    int w = tid >> 5;
    int rows_valid = M - m0; if (rows_valid > 128) rows_valid = 128;

    if (w == 0) {
        TCGEN05_ALLOC(sb + TCG_CTRL + 24, 128);
        TCGEN05_RELINQ();
    }
    if (tid == 0) {
        #pragma unroll
        for (int s = 0; s < 3; s++) MBARRIER_INIT(sb + TCG_CTRL + s*8, 1);
    }
    __syncthreads();
    uint32_t tmem;
    asm volatile("ld.shared.b32 %0, [%1];" : "=r"(tmem) : "r"(sb + TCG_CTRL + 24));

    const float* Ab = A  + (size_t)m0*K;
    const float* Bb = Bt + (size_t)n0*K;
    int r_ld = tid >> 3, c_ld = tid & 7;

    auto load_tiles = [&](int slot, int k0) {
        char* st = sbase + slot*TCG_STAGE;
        #pragma unroll
        for (int p = 0; p < 4; p++) {
            int r = r_ld + p*32;
            uint32_t off = (uint32_t)(r*128 + c_ld*16);
            off ^= ((off >> 3) & 0x70);
            int gr = (r < rows_valid) ? r : (rows_valid - 1);
            const float* arow = Ab + (size_t)gr*K + k0 + c_ld*4;
            const float* brow = Bb + (size_t)r*K  + k0 + c_ld*4;
            bool ap = (r < rows_valid);
            cp_async16(st + off,         arow,      ap);
            cp_async16(st + 16384 + off, arow + 32, ap);
            cp_async16(st + 32768 + off, brow,      true);
            cp_async16(st + 49152 + off, brow + 32, true);
        }
    };

    int nk = K / 64;
    uint32_t ph = 0;
    load_tiles(0, 0);   cp_commit();
    load_tiles(1, 64);  cp_commit();

    for (int it = 0; it < nk; it++) {
        int slot = it % 3;
        int rem = nk - 1 - it;
        if (rem >= 1) cp_wait1(); else cp_wait0();
        __syncthreads();
        FENCE_ASYNC_SHARED();

        if (w == 0 && elect_one()) {
            uint32_t stb = sb + slot*TCG_STAGE;
            #pragma unroll
            for (int s = 0; s < 8; s++) {
                uint64_t ad = make_desc(stb + (s >> 2)*16384)         + (uint64_t)(s & 3)*2;
                uint64_t bd = make_desc(stb + 32768 + (s >> 2)*16384) + (uint64_t)(s & 3)*2;
                tc_mma_tf32_ss(tmem, ad, bd, TC_IDESC, (it > 0 || s > 0));
            }
            TCGEN05_COMMIT(sb + TCG_CTRL + slot*8);
        }

        int j = it + 2;
        if (j < nk) {
            int ns = j % 3;
            if (j >= 3) {
                MBARRIER_WAIT_PARITY(sb + TCG_CTRL + ns*8, (ph >> ns) & 1);
                ph ^= (1u << ns);
            }
            load_tiles(ns, j*64);
            cp_commit();
        }
    }
    {
        int sl = (nk - 1) % 3;
        MBARRIER_WAIT_PARITY(sb + TCG_CTRL + sl*8, (ph >> sl) & 1);
    }
    TCGEN05_FENCE_AFTER();
    __syncthreads();

    float* tile = smem;
    {
        int subp = w & 3, half = w >> 2;
        int erow = subp*32 + lane;
        uint32_t ra[32], rb[32];
        TCGEN05_LD_X32(ra, tmem + half*64);
        TCGEN05_LD_X32(rb, tmem + half*64 + 32);
        TCGEN05_WAIT_LD();
        float* dst = tile + (size_t)erow*129 + half*64;
        #pragma unroll
        for (int c = 0; c < 32; c++) {
            dst[c]      = __uint_as_float(ra[c]);
            dst[32 + c] = __uint_as_float(rb[c]);
        }
    }
    __syncthreads();
    {
        float4 bv = make_float4(0.f, 0.f, 0.f, 0.f);
        if (bias) bv = *(const float4*)(bias + n0 + lane*4);
        #pragma unroll
        for (int p = 0; p < 16; p++) {
            int r = p*8 + w;
            int gm = m0 + r;
            if (gm < M) {
                const float* src = tile + (size_t)r*129 + lane*4;
                float4 v = make_float4(src[0]+bv.x, src[1]+bv.y, src[2]+bv.z, src[3]+bv.w);
                float4* op = (float4*)(C + (size_t)gm*N + n0 + lane*4);
                if (accumulate) {
                    float4 o = *op;
                    v.x += o.x; v.y += o.y; v.z += o.z; v.w += o.w;
                }
                *op = v;
            }
        }
    }
    if (w == 0) TCGEN05_DEALLOC(tmem, 128);

#else
    // mma.sync fallback (8 warps, 64x32 warp tiles) — PTX pass only
    float* Abuf = smem;
    float* Bbuf = smem + 2*(128*36);
    int warp = tid >> 5;
    int wm = warp & 1, wn = warp >> 1;
    int grp = lane >> 2, tg = lane & 3;

    float acc[4][4][4];
    #pragma unroll
    for (int mi = 0; mi < 4; mi++)
        #pragma unroll
        for (int ni = 0; ni < 4; ni++)
            #pragma unroll
            for (int r = 0; r < 4; r++) acc[mi][ni][r] = 0.f;

    int r_ld = tid >> 3, c_ld = tid & 7;
    auto load_tile = [&](int buf, int k0) {
        float* as = Abuf + buf*(128*36);
        float* bs = Bbuf + buf*(128*36);
        #pragma unroll
        for (int p = 0; p < 4; p++) {
            int r = r_ld + p*32;
            int gm = m0 + r;
            int gmc = (gm < M) ? gm : (M-1);
            cp_async16(as + r*36 + c_ld*4, A  + (size_t)gmc*K + k0 + c_ld*4, gm < M);
            cp_async16(bs + r*36 + c_ld*4, Bt + (size_t)(n0+r)*K + k0 + c_ld*4, true);
        }
    };

    int nk = K / 32;
    load_tile(0, 0);
    cp_commit();
    for (int it = 0; it < nk; it++) {
        int buf = it & 1;
        cp_wait0();
        __syncthreads();
        if (it + 1 < nk) { load_tile(buf^1, (it+1)*32); cp_commit(); }

        float* as = Abuf + buf*(128*36);
        float* bs = Bbuf + buf*(128*36);
        #pragma unroll
        for (int kk = 0; kk < 32; kk += 8) {
            uint32_t af[4][4], bf[4][2];
            #pragma unroll
            for (int mi = 0; mi < 4; mi++) {
                int m = wm*64 + mi*16 + grp;
                af[mi][0] = __float_as_uint(as[m*36 + kk + tg]);
                af[mi][1] = __float_as_uint(as[(m+8)*36 + kk + tg]);
                af[mi][2] = __float_as_uint(as[m*36 + kk + tg + 4]);
                af[mi][3] = __float_as_uint(as[(m+8)*36 + kk + tg + 4]);
            }
            #pragma unroll
            for (int ni = 0; ni < 4; ni++) {
                int n = wn*32 + ni*8 + grp;
                bf[ni][0] = __float_as_uint(bs[n*36 + kk + tg]);
                bf[ni][1] = __float_as_uint(bs[n*36 + kk + tg + 4]);
            }
            #pragma unroll
            for (int mi = 0; mi < 4; mi++)
                #pragma unroll
                for (int ni = 0; ni < 4; ni++)
                    mma_tf32(acc[mi][ni][0], acc[mi][ni][1], acc[mi][ni][2], acc[mi][ni][3],
                             af[mi][0], af[mi][1], af[mi][2], af[mi][3],
                             bf[ni][0], bf[ni][1]);
        }
    }

    #pragma unroll
    for (int mi = 0; mi < 4; mi++) {
        int r0 = m0 + wm*64 + mi*16 + grp;
        #pragma unroll
        for (int ni = 0; ni < 4; ni++) {
            int c0 = n0 + wn*32 + ni*8 + tg*2;
            float bv0 = bias ? bias[c0]   : 0.f;
            float bv1 = bias ? bias[c0+1] : 0.f;
            if (r0 < M) {
                size_t o = (size_t)r0*N + c0;
                float v0 = acc[mi][ni][0] + bv0;
                float v1 = acc[mi][ni][1] + bv1;
                if (accumulate) { C[o] += v0; C[o+1] += v1; }
                else            { C[o]  = v0; C[o+1]  = v1; }
            }
            if (r0 + 8 < M) {
                size_t o = (size_t)(r0+8)*N + c0;
                float v2 = acc[mi][ni][2] + bv0;
                float v3 = acc[mi][ni][3] + bv1;
                if (accumulate) { C[o] += v2; C[o+1] += v3; }
                else            { C[o]  = v2; C[o+1]  = v3; }
            }
        }
    }
#endif
}

// ================= GEMM 256x128 (BM=256, K64 stages, 2-stage) ===============
#define T256_STAGE 98304
#define T256_CTRL  (2*T256_STAGE)
#define GEMM256_SMEM (2*T256_STAGE + 64)

__global__ __launch_bounds__(256, 1)
void gemm_tc256_kernel(const float* __restrict__ A, const float* __restrict__ Bt,
                       const float* __restrict__ bias, float* __restrict__ C,
                       int M, int N, int K, int accumulate)
{
    extern __shared__ float smem[];
    int tid = threadIdx.x, lane = tid & 31;
    int m0 = blockIdx.y * 256, n0 = blockIdx.x * 128;

#if HAS_TCGEN05
    char* sbase = (char*)smem;
    uint32_t sb = smem_u32(smem);
    int w = tid >> 5;

    if (w == 0) {
        TCGEN05_ALLOC(sb + T256_CTRL + 16, 256);
        TCGEN05_RELINQ();
    }
    if (tid == 0) {
        MBARRIER_INIT(sb + T256_CTRL,     1);
        MBARRIER_INIT(sb + T256_CTRL + 8, 1);
    }
    __syncthreads();
    uint32_t tmem;
    asm volatile("ld.shared.b32 %0, [%1];" : "=r"(tmem) : "r"(sb + T256_CTRL + 16));

    const float* Ab = A  + (size_t)m0*K;
    const float* Bb = Bt + (size_t)n0*K;
    int r_ld = tid >> 3, c_ld = tid & 7;

    auto load_tiles = [&](int slot, int k0) {
        char* st = sbase + slot*T256_STAGE;
        #pragma unroll
        for (int p = 0; p < 8; p++) {
            int r = r_ld + p*32;
            int half = r >> 7, rr = r & 127;
            uint32_t off = (uint32_t)(rr*128 + c_ld*16);
            off ^= ((off >> 3) & 0x70);
            const float* arow = Ab + (size_t)r*K + k0 + c_ld*4;
            cp_async16(st + half*32768 + off,         arow,      true);
            cp_async16(st + half*32768 + 16384 + off, arow + 32, true);
        }
        #pragma unroll
        for (int p = 0; p < 4; p++) {
            int r = r_ld + p*32;
            uint32_t off = (uint32_t)(r*128 + c_ld*16);
            off ^= ((off >> 3) & 0x70);
            const float* brow = Bb + (size_t)r*K + k0 + c_ld*4;
            cp_async16(st + 65536 + off, brow,      true);
            cp_async16(st + 81920 + off, brow + 32, true);
        }
    };

    int nk = K / 64;
    uint32_t ph = 0;
    load_tiles(0, 0);   cp_commit();
    if (nk > 1) { load_tiles(1, 64); cp_commit(); }

    for (int it = 0; it < nk; it++) {
        int slot = it & 1;
        int rem = nk - 1 - it;
        if (rem >= 1) cp_wait1(); else cp_wait0();
        __syncthreads();
        FENCE_ASYNC_SHARED();

        if (w == 0 && elect_one()) {
            uint32_t stb = sb + slot*T256_STAGE;
            #pragma unroll
            for (int s = 0; s < 8; s++) {
                int kb = s >> 2;
                uint64_t step = (uint64_t)(s & 3)*2;
                uint64_t ad0 = make_desc(stb + kb*16384)         + step;
                uint64_t ad1 = make_desc(stb + 32768 + kb*16384) + step;
                uint64_t bd  = make_desc(stb + 65536 + kb*16384) + step;
                uint32_t en = (it > 0 || s > 0);
                tc_mma_tf32_ss(tmem,       ad0, bd, TC_IDESC, en);
                tc_mma_tf32_ss(tmem + 128, ad1, bd, TC_IDESC, en);
            }
            TCGEN05_COMMIT(sb + T256_CTRL + slot*8);
        }

        int j = it + 2;
        if (j < nk) {
            int ns = j & 1;
            MBARRIER_WAIT_PARITY(sb + T256_CTRL + ns*8, (ph >> ns) & 1);
            ph ^= (1u << ns);
            load_tiles(ns, j*64);
            cp_commit();
        }
    }
    {
        int sl = (nk - 1) & 1;
        MBARRIER_WAIT_PARITY(sb + T256_CTRL + sl*8, (ph >> sl) & 1);
    }
    TCGEN05_FENCE_AFTER();
    __syncthreads();

    float* tile = smem;
    float4 bv = make_float4(0.f, 0.f, 0.f, 0.f);
    if (bias) bv = *(const float4*)(bias + n0 + lane*4);

    for (int acc = 0; acc < 2; acc++) {
        {
            int subp = w & 3, half = w >> 2;
            int erow = subp*32 + lane;
            uint32_t ra[32], rb[32];
            TCGEN05_LD_X32(ra, tmem + acc*128 + half*64);
            TCGEN05_LD_X32(rb, tmem + acc*128 + half*64 + 32);
            TCGEN05_WAIT_LD();
            float* dst = tile + (size_t)erow*129 + half*64;
            #pragma unroll
            for (int c = 0; c < 32; c++) {
                dst[c]      = __uint_as_float(ra[c]);
                dst[32 + c] = __uint_as_float(rb[c]);
            }
        }
        __syncthreads();
        #pragma unroll
        for (int p = 0; p < 16; p++) {
            int r = p*8 + w;
            int gm = m0 + acc*128 + r;
            const float* src = tile + (size_t)r*129 + lane*4;
            float4 v = make_float4(src[0]+bv.x, src[1]+bv.y, src[2]+bv.z, src[3]+bv.w);
            float4* op = (float4*)(C + (size_t)gm*N + n0 + lane*4);
            if (accumulate) {
                float4 o = *op;
                v.x += o.x; v.y += o.y; v.z += o.z; v.w += o.w;
            }
            *op = v;
        }
        __syncthreads();
    }
    if (w == 0) TCGEN05_DEALLOC(tmem, 256);

#else
    for (int idx = tid; idx < 256*128; idx += 256) {
        int r = idx >> 7, c = idx & 127;
        float s = bias ? bias[n0 + c] : 0.f;
        for (int k = 0; k < K; k++)
            s += A[(size_t)(m0 + r)*K + k] * Bt[(size_t)(n0 + c)*K + k];
        size_t o = (size_t)(m0 + r)*N + n0 + c;
        if (accumulate) C[o] += s; else C[o] = s;
    }
#endif
}

// ================= fused GEGLU GEMM: ff = a * gelu(gate) ====================
#define GG_STAGE 65536
#define GG_CTRL  (3*GG_STAGE)
#define GEGLU_SMEM (3*GG_STAGE + 64)

__global__ __launch_bounds__(256, 1)
void geglu_tc_kernel(const float* __restrict__ A, const float* __restrict__ Bta,
                     const float* __restrict__ Btg, const float* __restrict__ bias,
                     float* __restrict__ FFo, int M, int K)
{
    extern __shared__ float smem[];
    int tid = threadIdx.x, lane = tid & 31;
    int m0 = blockIdx.y * 256, n0 = blockIdx.x * 128;

#if HAS_TCGEN05
    char* sbase = (char*)smem;
    uint32_t sb = smem_u32(smem);
    int w = tid >> 5;

    if (w == 0) {
        TCGEN05_ALLOC(sb + GG_CTRL + 24, 512);
        TCGEN05_RELINQ();
    }
    if (tid == 0) {
        #pragma unroll
        for (int s = 0; s < 3; s++) MBARRIER_INIT(sb + GG_CTRL + s*8, 1);
    }
    __syncthreads();
    uint32_t tmem;
    asm volatile("ld.shared.b32 %0, [%1];" : "=r"(tmem) : "r"(sb + GG_CTRL + 24));

    const float* Ab  = A   + (size_t)m0*K;
    const float* Bab = Bta + (size_t)n0*K;
    const float* Bgb = Btg + (size_t)n0*K;
    int r_ld = tid >> 3, c_ld = tid & 7;

    auto load_tiles = [&](int slot, int k0) {
        char* st = sbase + slot*GG_STAGE;
        #pragma unroll
        for (int p = 0; p < 8; p++) {
            int r = r_ld + p*32;
            int blk = r >> 7, rr = r & 127;
            uint32_t off = (uint32_t)(rr*128 + c_ld*16);
            off ^= ((off >> 3) & 0x70);
            cp_async16(st + blk*16384 + off, Ab + (size_t)r*K + k0 + c_ld*4, true);
        }
        #pragma unroll
        for (int p = 0; p < 4; p++) {
            int r = r_ld + p*32;
            uint32_t off = (uint32_t)(r*128 + c_ld*16);
            off ^= ((off >> 3) & 0x70);
            cp_async16(st + 32768 + off, Bab + (size_t)r*K + k0 + c_ld*4, true);
            cp_async16(st + 49152 + off, Bgb + (size_t)r*K + k0 + c_ld*4, true);
        }
    };

    int nk = K / 32;
    uint32_t ph = 0;
    load_tiles(0, 0);   cp_commit();
    load_tiles(1, 32);  cp_commit();

    for (int it = 0; it < nk; it++) {
        int slot = it % 3;
        int rem = nk - 1 - it;
        if (rem >= 1) cp_wait1(); else cp_wait0();
        __syncthreads();
        FENCE_ASYNC_SHARED();

        if (w == 0 && elect_one()) {
            uint32_t stb = sb + slot*GG_STAGE;
            #pragma unroll
            for (int s = 0; s < 4; s++) {
                uint64_t ad0 = make_desc(stb)          + (uint64_t)s*2;
                uint64_t ad1 = make_desc(stb + 16384)  + (uint64_t)s*2;
                uint64_t bad = make_desc(stb + 32768)  + (uint64_t)s*2;
                uint64_t bgd = make_desc(stb + 49152)  + (uint64_t)s*2;
                uint32_t en = (it > 0 || s > 0);
                tc_mma_tf32_ss(tmem,       ad0, bad, TC_IDESC, en);
                tc_mma_tf32_ss(tmem + 128, ad1, bad, TC_IDESC, en);
                tc_mma_tf32_ss(tmem + 256, ad0, bgd, TC_IDESC, en);
                tc_mma_tf32_ss(tmem + 384, ad1, bgd, TC_IDESC, en);
            }
            TCGEN05_COMMIT(sb + GG_CTRL + slot*8);
        }

        int j = it + 2;
        if (j < nk) {
            int ns = j % 3;
            if (j >= 3) {
                MBARRIER_WAIT_PARITY(sb + GG_CTRL + ns*8, (ph >> ns) & 1);
                ph ^= (1u << ns);
            }
            load_tiles(ns, j*32);
            cp_commit();
        }
    }
    {
        int sl = (nk - 1) % 3;
        MBARRIER_WAIT_PARITY(sb + GG_CTRL + sl*8, (ph >> sl) & 1);
    }
    TCGEN05_FENCE_AFTER();
    __syncthreads();

    float* tile = smem;
    const float inv_sqrt2 = 0.70710678118654752f;

    for (int h = 0; h < 2; h++) {
        {
            int subp = w & 3, ch = w >> 2;
            int erow = subp*32 + lane;
            float* dst = tile + (size_t)erow*129 + ch*64;
            #pragma unroll
            for (int cc = 0; cc < 2; cc++) {
                uint32_t ra[32], rg[32];
                TCGEN05_LD_X32(ra, tmem + h*128 + ch*64 + cc*32);
                TCGEN05_LD_X32(rg, tmem + 256 + h*128 + ch*64 + cc*32);
                TCGEN05_WAIT_LD();
                #pragma unroll
                for (int c = 0; c < 32; c++) {
                    int col = ch*64 + cc*32 + c;
                    float av = __uint_as_float(ra[c]) + __ldg(bias + n0 + col);
                    float gv = __uint_as_float(rg[c]) + __ldg(bias + FF + n0 + col);
                    float gel = 0.5f*gv*(1.f + erff(gv*inv_sqrt2));
                    dst[cc*32 + c] = av * gel;
                }
            }
        }
        __syncthreads();
        #pragma unroll
        for (int p = 0; p < 16; p++) {
            int r = p*8 + w;
            int gm = m0 + h*128 + r;
            const float* src = tile + (size_t)r*129 + lane*4;
            *(float4*)(FFo + (size_t)gm*FF + n0 + lane*4) =
                make_float4(src[0], src[1], src[2], src[3]);
        }
        __syncthreads();
    }
    if (w == 0) TCGEN05_DEALLOC(tmem, 512);

#else
    for (int idx = tid; idx < 256*128; idx += 256) {
        int r = idx >> 7, c = idx & 127;
        float sa = bias[n0 + c], sg = bias[FF + n0 + c];
        for (int k = 0; k < K; k++) {
            float av = A[(size_t)(m0 + r)*K + k];
            sa += av * Bta[(size_t)(n0 + c)*K + k];
            sg += av * Btg[(size_t)(n0 + c)*K + k];
        }
        float gel = 0.5f*sg*(1.f + erff(sg*0.70710678118654752f));
        FFo[(size_t)(m0 + r)*FF + n0 + c] = sa * gel;
    }
#endif
}

// ================= LayerNorm (warp per row) =================
__global__ void layernorm_kernel(const float* __restrict__ in,
                                 const float* __restrict__ g,
                                 const float* __restrict__ bta,
                                 float* __restrict__ out)
{
    int w = threadIdx.x >> 5, lane = threadIdx.x & 31;
    size_t row = (size_t)blockIdx.x*8 + w;
    const float4* p = (const float4*)(in + row*CCH);
    float4 v[5];
    float s = 0.f, ss = 0.f;
    #pragma unroll
    for (int i = 0; i < 5; i++) {
        v[i] = p[lane + 32*i];
        s  += v[i].x + v[i].y + v[i].z + v[i].w;
        ss += v[i].x*v[i].x + v[i].y*v[i].y + v[i].z*v[i].z + v[i].w*v[i].w;
    }
    #pragma unroll
    for (int o = 16; o >= 1; o >>= 1) {
        s  += __shfl_xor_sync(0xffffffffu, s, o);
        ss += __shfl_xor_sync(0xffffffffu, ss, o);
    }
    float mean = s * (1.f/CCH);
    float rstd = rsqrtf(ss * (1.f/CCH) - mean*mean + 1e-5f);
    const float4* g4 = (const float4*)g;
    const float4* b4 = (const float4*)bta;
    float4* o4 = (float4*)(out + row*CCH);
    #pragma unroll
    for (int i = 0; i < 5; i++) {
        float4 gg = g4[lane + 32*i], bb = b4[lane + 32*i];
        float4 r;
        r.x = (v[i].x - mean)*rstd*gg.x + bb.x;
        r.y = (v[i].y - mean)*rstd*gg.y + bb.y;
        r.z = (v[i].z - mean)*rstd*gg.z + bb.z;
        r.w = (v[i].w - mean)*rstd*gg.w + bb.w;
        o4[lane + 32*i] = r;
    }
}

// ================= flash attention (mma.sync tf32, double-buffered KV) ======
#define FTQ 128
#define FTJ 64
#define QS_STR 84
#define KS_STR 84
#define VS_STR 88
#define PS_STR 68
#define KVBUF (FTJ*KS_STR + FTJ*VS_STR)
#define FLASH_SMEM ((FTQ*QS_STR + 2*KVBUF) * (int)sizeof(float))

__global__ __launch_bounds__(256, 1)
void flash_attn_mma_kernel(const float* __restrict__ Q, const float* __restrict__ K,
                           const float* __restrict__ V, float* __restrict__ O,
                           int Lk, int qRow, int kvRow, size_t kvBatch, int oRow)
{
    extern __shared__ float sm[];
    float* QPs = sm;
    float* KV0 = sm + FTQ*QS_STR;

    int tid = threadIdx.x, lane = tid & 31, w = tid >> 5;
    int qr = lane >> 2, qc = lane & 3;
    int bh = blockIdx.y;
    int b = bh / HEADS, h = bh % HEADS;
    int i0 = blockIdx.x * FTQ;
    const float scale = 0.1118033988749895f;

    const float* qb = Q + ((size_t)(b*HW) + i0)*qRow + h*DH;
    const float* kb = K + (size_t)b*kvBatch + h*DH;
    const float* vb = V + (size_t)b*kvBatch + h*DH;

    int kv_r = tid >> 2, kv_c = tid & 3;
    auto load_kv = [&](int buf, int j0) {
        float* Ks = KV0 + buf*KVBUF;
        float* Vs = Ks + FTJ*KS_STR;
        #pragma unroll
        for (int q4 = kv_c; q4 < 20; q4 += 4) {
            int gj = j0 + kv_r;
            int gjc = (gj < Lk) ? gj : (Lk - 1);
            cp_async16(Ks + kv_r*KS_STR + q4*4, kb + (size_t)gjc*kvRow + q4*4, true);
            cp_async16(Vs + kv_r*VS_STR + q4*4, vb + (size_t)gjc*kvRow + q4*4, true);
        }
    };

    load_kv(0, 0);
    cp_commit();
    for (int idx = tid; idx < FTQ*20; idx += 256) {
        int i = idx / 20, q4 = (idx % 20)*4;
        float4 qv = *(const float4*)(qb + (size_t)i*qRow + q4);
        qv.x *= scale; qv.y *= scale; qv.z *= scale; qv.w *= scale;
        *(float4*)(QPs + i*QS_STR + q4) = qv;
    }
    __syncthreads();

    int r0 = w*16 + qr;
    uint32_t qf[10][4];
    #pragma unroll
    for (int kk = 0; kk < 10; kk++) {
        int d0 = kk*8 + qc;
        qf[kk][0] = __float_as_uint(QPs[(size_t)r0*QS_STR + d0]);
        qf[kk][1] = __float_as_uint(QPs[(size_t)(r0+8)*QS_STR + d0]);
        qf[kk][2] = __float_as_uint(QPs[(size_t)r0*QS_STR + d0+4]);
        qf[kk][3] = __float_as_uint(QPs[(size_t)(r0+8)*QS_STR + d0+4]);
    }
    __syncthreads();

    float m0v = -1e30f, m1v = -1e30f, l0 = 0.f, l1 = 0.f;
    float oacc[10][4];
    #pragma unroll
    for (int nt = 0; nt < 10; nt++)
        #pragma unroll
        for (int r = 0; r < 4; r++) oacc[nt][r] = 0.f;

    int nchunks = (Lk + FTJ - 1) / FTJ;
    for (int c = 0; c < nchunks; c++) {
        int buf = c & 1;
        if (c + 1 < nchunks) {
            load_kv(buf ^ 1, (c + 1)*FTJ);
            cp_commit();
            cp_wait1();
        } else {
            cp_wait0();
        }
        __syncthreads();

        float* Ks = KV0 + buf*KVBUF;
        float* Vs = Ks + FTJ*KS_STR;
        int j0 = c*FTJ;

        float sc[8][4];
        #pragma unroll
        for (int nt = 0; nt < 8; nt++)
            #pragma unroll
            for (int r = 0; r < 4; r++) sc[nt][r] = 0.f;

        #pragma unroll
        for (int kk = 0; kk < 10; kk++) {
            int d0 = kk*8 + qc;
            #pragma unroll
            for (int nt = 0; nt < 8; nt++) {
                int j = nt*8 + qr;
                uint32_t b0 = __float_as_uint(Ks[(size_t)j*KS_STR + d0]);
                uint32_t b1 = __float_as_uint(Ks[(size_t)j*KS_STR + d0+4]);
                mma_tf32(sc[nt][0], sc[nt][1], sc[nt][2], sc[nt][3],
                         qf[kk][0], qf[kk][1], qf[kk][2], qf[kk][3], b0, b1);
            }
        }

        if (j0 + FTJ > Lk) {
            #pragma unroll
            for (int nt = 0; nt < 8; nt++) {
                int jc = j0 + nt*8 + qc*2;
                if (jc   >= Lk) { sc[nt][0] = -1e30f; sc[nt][2] = -1e30f; }
                if (jc+1 >= Lk) { sc[nt][1] = -1e30f; sc[nt][3] = -1e30f; }
            }
        }

        float mx0 = -1e30f, mx1 = -1e30f;
        #pragma unroll
        for (int nt = 0; nt < 8; nt++) {
            mx0 = fmaxf(mx0, fmaxf(sc[nt][0], sc[nt][1]));
            mx1 = fmaxf(mx1, fmaxf(sc[nt][2], sc[nt][3]));
        }
        mx0 = fmaxf(mx0, __shfl_xor_sync(0xffffffffu, mx0, 1));
        mx0 = fmaxf(mx0, __shfl_xor_sync(0xffffffffu, mx0, 2));
        mx1 = fmaxf(mx1, __shfl_xor_sync(0xffffffffu, mx1, 1));
        mx1 = fmaxf(mx1, __shfl_xor_sync(0xffffffffu, mx1, 2));

        float mn0 = fmaxf(m0v, mx0), mn1 = fmaxf(m1v, mx1);
        float al0 = __expf(m0v - mn0), al1 = __expf(m1v - mn1);
        float rs0 = 0.f, rs1 = 0.f;
        #pragma unroll
        for (int nt = 0; nt < 8; nt++) {
            sc[nt][0] = __expf(sc[nt][0] - mn0);
            sc[nt][1] = __expf(sc[nt][1] - mn0);
            sc[nt][2] = __expf(sc[nt][2] - mn1);
            sc[nt][3] = __expf(sc[nt][3] - mn1);
            rs0 += sc[nt][0] + sc[nt][1];
            rs1 += sc[nt][2] + sc[nt][3];
        }
        rs0 += __shfl_xor_sync(0xffffffffu, rs0, 1);
        rs0 += __shfl_xor_sync(0xffffffffu, rs0, 2);
        rs1 += __shfl_xor_sync(0xffffffffu, rs1, 1);
        rs1 += __shfl_xor_sync(0xffffffffu, rs1, 2);

        l0 = l0*al0 + rs0;  m0v = mn0;
        l1 = l1*al1 + rs1;  m1v = mn1;

        #pragma unroll
        for (int nt = 0; nt < 10; nt++) {
            oacc[nt][0] *= al0; oacc[nt][1] *= al0;
            oacc[nt][2] *= al1; oacc[nt][3] *= al1;
        }

        float* Ps = QPs;
        #pragma unroll
        for (int nt = 0; nt < 8; nt++) {
            int jc = nt*8 + qc*2;
            *(float2*)(Ps + (size_t)r0*PS_STR + jc)     = make_float2(sc[nt][0], sc[nt][1]);
            *(float2*)(Ps + (size_t)(r0+8)*PS_STR + jc) = make_float2(sc[nt][2], sc[nt][3]);
        }
        __syncwarp();

        #pragma unroll
        for (int kk = 0; kk < 8; kk++) {
            int jj = kk*8 + qc;
            uint32_t a0 = __float_as_uint(Ps[(size_t)r0*PS_STR + jj]);
            uint32_t a1 = __float_as_uint(Ps[(size_t)(r0+8)*PS_STR + jj]);
            uint32_t a2 = __float_as_uint(Ps[(size_t)r0*PS_STR + jj+4]);
            uint32_t a3 = __float_as_uint(Ps[(size_t)(r0+8)*PS_STR + jj+4]);
            #pragma unroll
            for (int nt = 0; nt < 10; nt++) {
                int d = nt*8 + qr;
                uint32_t b0 = __float_as_uint(Vs[(size_t)jj*VS_STR + d]);
                uint32_t b1 = __float_as_uint(Vs[(size_t)(jj+4)*VS_STR + d]);
                mma_tf32(oacc[nt][0], oacc[nt][1], oacc[nt][2], oacc[nt][3],
                         a0, a1, a2, a3, b0, b1);
            }
        }
        __syncthreads();
    }

    float inv0 = 1.f / l0, inv1 = 1.f / l1;
    float* ob = O + ((size_t)(b*HW) + i0 + r0)*oRow + h*DH;
    #pragma unroll
    for (int nt = 0; nt < 10; nt++) {
        int dc = nt*8 + qc*2;
        *(float2*)(ob + dc)                  = make_float2(oacc[nt][0]*inv0, oacc[nt][1]*inv0);
        *(float2*)(ob + (size_t)8*oRow + dc) = make_float2(oacc[nt][2]*inv1, oacc[nt][3]*inv1);
    }
}

// ================= final: tiled transpose + input residual =================
__global__ void final_add_kernel(const float* __restrict__ tmat,
                                 const float* __restrict__ x,
                                 float* __restrict__ out)
{
    __shared__ float tile[32][33];
    int b  = blockIdx.z;
    int d0 = blockIdx.y*32, hw0 = blockIdx.x*32;
    int tx = threadIdx.x, ty = threadIdx.y;
    #pragma unroll
    for (int i = 0; i < 32; i += 8) {
        int hw = hw0 + ty + i;
        tile[ty+i][tx] = tmat[((size_t)b*HW + hw)*CCH + d0 + tx];
    }
    __syncthreads();
    #pragma unroll
    for (int i = 0; i < 32; i += 8) {
        int d = d0 + ty + i;
        size_t o = ((size_t)b*CCH + d)*HW + hw0 + tx;
        out[o] = tile[tx][ty+i] + x[o];
    }
}

extern "C" void kernel_launch(void* const* d_in, const int* in_sizes, int n_in,
                              void* d_out, int out_size)
{
    const float* x       = (const float*)d_in[0];
    const float* context = (const float*)d_in[1];
    const float* gn_g    = (const float*)d_in[2];
    const float* gn_b    = (const float*)d_in[3];
    const float* w_in    = (const float*)d_in[4];
    const float* b_in    = (const float*)d_in[5];
    const float* ln1_g   = (const float*)d_in[6];
    const float* ln1_b   = (const float*)d_in[7];
    const float* wq1     = (const float*)d_in[8];
    const float* wk1     = (const float*)d_in[9];
    const float* wv1     = (const float*)d_in[10];
    const float* wo1     = (const float*)d_in[11];
    const float* bo1     = (const float*)d_in[12];
    const float* ln2_g   = (const float*)d_in[13];
    const float* ln2_b   = (const float*)d_in[14];
    const float* wq2     = (const float*)d_in[15];
    const float* wk2     = (const float*)d_in[16];
    const float* wv2     = (const float*)d_in[17];
    const float* wo2     = (const float*)d_in[18];
    const float* bo2     = (const float*)d_in[19];
    const float* ln3_g   = (const float*)d_in[20];
    const float* ln3_b   = (const float*)d_in[21];
    const float* w_geglu = (const float*)d_in[22];
    const float* b_geglu = (const float*)d_in[23];
    const float* w_ffo   = (const float*)d_in[24];
    const float* b_ffo   = (const float*)d_in[25];
    const float* w_out   = (const float*)d_in[26];
    const float* b_out   = (const float*)d_in[27];
    float* out = (float*)d_out;

    float *p_t, *p_tn, *p_q, *p_ao, *p_qkv, *p_kv, *p_ff, *p_wt, *p_stats;
    cudaGetSymbolAddress((void**)&p_t,    g_t);
    cudaGetSymbolAddress((void**)&p_tn,   g_tn);
    cudaGetSymbolAddress((void**)&p_q,    g_q);
    cudaGetSymbolAddress((void**)&p_ao,   g_ao);
    cudaGetSymbolAddress((void**)&p_qkv,  g_qkv);
    cudaGetSymbolAddress((void**)&p_kv,   g_kv);
    cudaGetSymbolAddress((void**)&p_ff,   g_ff);
    cudaGetSymbolAddress((void**)&p_wt,   g_wt);
    cudaGetSymbolAddress((void**)&p_stats,g_stats);

    cudaFuncSetAttribute(flash_attn_mma_kernel,
                         cudaFuncAttributeMaxDynamicSharedMemorySize, FLASH_SMEM);
    cudaFuncSetAttribute(gemm_tc_kernel,
                         cudaFuncAttributeMaxDynamicSharedMemorySize, GEMM_SMEM);
    cudaFuncSetAttribute(gemm_tc256_kernel,
                         cudaFuncAttributeMaxDynamicSharedMemorySize, GEMM256_SMEM);
    cudaFuncSetAttribute(geglu_tc_kernel,
                         cudaFuncAttributeMaxDynamicSharedMemorySize, GEGLU_SMEM);

    dim3 tb(32, 8);
    dim3 tp_grid(HW/32, CCH/32, BATCH);

    #define TW(w_, dst_, K_, N_) \
        transpose_w<<<dim3((N_)/32, (K_)/32), tb>>>(w_, dst_, K_, N_)
    #define GEMM_TC(A_, Bt_, bias_, C_, M_, N_, K_, acc_) \
        gemm_tc_kernel<<<dim3((N_)/128, ((M_)+127)/128), 256, GEMM_SMEM>>>( \
            A_, Bt_, bias_, C_, M_, N_, K_, acc_)
    #define GEMM_TC256(A_, Bt_, bias_, C_, M_, N_, K_, acc_) \
        gemm_tc256_kernel<<<dim3((N_)/128, (M_)/256), 256, GEMM256_SMEM>>>( \
            A_, Bt_, bias_, C_, M_, N_, K_, acc_)

    // 1) GroupNorm -> token-major
    gn_stats_kernel<<<BATCH*GROUPS, 256>>>(x, p_stats);
    gn_apply_kernel<<<tp_grid, tb>>>(x, gn_g, gn_b, p_stats, p_tn);

    // 2) proj_in (BM=256/K64)
    TW(w_in, p_wt, CCH, CCH);
    GEMM_TC256(p_tn, p_wt, b_in, p_t, MTOK, CCH, CCH, 0);

    // 3) self-attention (packed QKV on BM=256/K64 kernel, N=1920)
    layernorm_kernel<<<MTOK/8, 256>>>(p_t, ln1_g, ln1_b, p_tn);
    TW(wq1, p_wt,             CCH, CCH);
    TW(wk1, p_wt + 640*640,   CCH, CCH);
    TW(wv1, p_wt + 2*640*640, CCH, CCH);
    GEMM_TC256(p_tn, p_wt, nullptr, p_qkv, MTOK, 1920, CCH, 0);
    flash_attn_mma_kernel<<<dim3(HW/FTQ, BATCH*HEADS), 256, FLASH_SMEM>>>(
        p_qkv, p_qkv + 640, p_qkv + 1280, p_ao, HW, 1920, 1920, (size_t)HW*1920, CCH);
    TW(wo1, p_wt, CCH, CCH);
    GEMM_TC256(p_ao, p_wt, bo1, p_t, MTOK, CCH, CCH, 1);

    // 4) cross-attention
    layernorm_kernel<<<MTOK/8, 256>>>(p_t, ln2_g, ln2_b, p_tn);
    TW(wq2, p_wt, CCH, CCH);
    GEMM_TC256(p_tn, p_wt, nullptr, p_q, MTOK, CCH, CCH, 0);
    TW(wk2, p_wt,           CTXD, CCH);
    TW(wv2, p_wt + 640*768, CTXD, CCH);
    GEMM_TC(context, p_wt, nullptr, p_kv, BATCH*CTX, 1280, CTXD, 0);
    flash_attn_mma_kernel<<<dim3(HW/FTQ, BATCH*HEADS), 256, FLASH_SMEM>>>(
        p_q, p_kv, p_kv + 640, p_ao, CTX, CCH, 1280, (size_t)CTX*1280, CCH);
    TW(wo2, p_wt, CCH, CCH);
    GEMM_TC256(p_ao, p_wt, bo2, p_t, MTOK, CCH, CCH, 1);

    // 5) GEGLU FF (fused a*gelu(gate) GEMM -> g_ff directly; FFO on BM=256/K64)
    layernorm_kernel<<<MTOK/8, 256>>>(p_t, ln3_g, ln3_b, p_tn);
    TW(w_geglu, p_wt, CCH, 2*FF);
    geglu_tc_kernel<<<dim3(FF/128, MTOK/256), 256, GEGLU_SMEM>>>(
        p_tn, p_wt, p_wt + (size_t)FF*CCH, b_geglu, p_ff, MTOK, CCH);
    TW(w_ffo, p_wt, FF, CCH);
    GEMM_TC256(p_ff, p_wt, b_ffo, p_t, MTOK, CCH, FF, 1);

    // 6) proj_out + residual (BM=256/K64)
    TW(w_out, p_wt, CCH, CCH);
    GEMM_TC256(p_t, p_wt, b_out, p_tn, MTOK, CCH, CCH, 0);
    final_add_kernel<<<tp_grid, tb>>>(p_tn, x, out);
}

// round 15
// speedup vs baseline: 1.0907x; 1.0907x over previous
#include <cuda_runtime.h>
#include <math.h>
#include <stdint.h>

// ---------------- problem constants ----------------
#define BATCH   8
#define CCH     640
#define HW      1024
#define MTOK    (BATCH*HW)
#define HEADS   8
#define DH      80
#define CTX     77
#define CTXD    768
#define FF      2560
#define GROUPS  32
#define CPG     (CCH/GROUPS)

// arch-feature gate: tcgen05 only exists in the sm_103a pass
#if defined(__CUDA_ARCH__) && (defined(__CUDA_ARCH_FEAT_SM103_ALL) || defined(__CUDA_ARCH_SPECIFIC__))
#define HAS_TCGEN05 1
#else
#define HAS_TCGEN05 0
#endif

// ---------------- scratch ----------------
__device__ float g_t   [MTOK*CCH];
__device__ float g_tn  [MTOK*CCH];
__device__ float g_q   [MTOK*CCH];
__device__ float g_ao  [MTOK*CCH];
__device__ float g_qkv [(size_t)MTOK*1920];
__device__ float g_kv  [BATCH*CTX*1280];
__device__ float g_ff  [(size_t)MTOK*FF];
__device__ float g_wt  [(size_t)5120*640];
__device__ float g_stats[BATCH*GROUPS*2];

// ================= common PTX helpers =================
__device__ __forceinline__ uint32_t smem_u32(const void* p) {
    uint32_t a;
    asm("{ .reg .u64 t; cvta.to.shared.u64 t, %1; cvt.u32.u64 %0, t; }" : "=r"(a) : "l"(p));
    return a;
}
__device__ __forceinline__ void cp_async16(void* smem_ptr, const float* gptr, bool pred)
{
    uint32_t saddr = smem_u32(smem_ptr);
    int sz = pred ? 16 : 0;
    asm volatile("cp.async.cg.shared.global [%0], [%1], 16, %2;\n"
                 :: "r"(saddr), "l"(gptr), "r"(sz));
}
__device__ __forceinline__ void cp_commit() { asm volatile("cp.async.commit_group;\n" ::: "memory"); }
__device__ __forceinline__ void cp_wait0()  { asm volatile("cp.async.wait_group 0;\n" ::: "memory"); }
__device__ __forceinline__ void cp_wait1()  { asm volatile("cp.async.wait_group 1;\n" ::: "memory"); }

__device__ __forceinline__ void mma_tf32(float& d0, float& d1, float& d2, float& d3,
                                         uint32_t a0, uint32_t a1, uint32_t a2, uint32_t a3,
                                         uint32_t b0, uint32_t b1)
{
    asm volatile(
        "mma.sync.aligned.m16n8k8.row.col.f32.tf32.tf32.f32 "
        "{%0,%1,%2,%3}, {%4,%5,%6,%7}, {%8,%9}, {%0,%1,%2,%3};\n"
        : "+f"(d0), "+f"(d1), "+f"(d2), "+f"(d3)
        : "r"(a0), "r"(a1), "r"(a2), "r"(a3), "r"(b0), "r"(b1));
}

#if HAS_TCGEN05
__device__ __forceinline__ uint32_t elect_one() {
    uint32_t p;
    asm volatile("{\n\t.reg .pred p;\n\telect.sync _|p, 0xFFFFFFFF;\n\tselp.b32 %0, 1, 0, p;\n\t}" : "=r"(p));
    return p;
}
#define TCGEN05_ALLOC(smem_addr, nCols) \
    asm volatile("tcgen05.alloc.cta_group::1.sync.aligned.shared::cta.b32 [%0], %1;" \
                 :: "r"((uint32_t)(smem_addr)), "r"((uint32_t)(nCols)) : "memory")
#define TCGEN05_DEALLOC(tmem, nCols) \
    asm volatile("tcgen05.dealloc.cta_group::1.sync.aligned.b32 %0, %1;" :: "r"(tmem), "r"((uint32_t)(nCols)))
#define TCGEN05_RELINQ() \
    asm volatile("tcgen05.relinquish_alloc_permit.cta_group::1.sync.aligned;")
#define TCGEN05_COMMIT(mbar) \
    asm volatile("tcgen05.commit.cta_group::1.mbarrier::arrive::one.shared::cluster.b64 [%0];" \
                 :: "r"((uint32_t)(mbar)) : "memory")
#define TCGEN05_FENCE_AFTER() asm volatile("tcgen05.fence::after_thread_sync;" ::: "memory")
#define TCGEN05_WAIT_LD()     asm volatile("tcgen05.wait::ld.sync.aligned;" ::: "memory")
#define FENCE_ASYNC_SHARED()  asm volatile("fence.proxy.async.shared::cta;" ::: "memory")
#define MBARRIER_INIT(mbar, cnt) \
    asm volatile("mbarrier.init.shared.b64 [%0], %1;" :: "r"((uint32_t)(mbar)), "r"((uint32_t)(cnt)) : "memory")
#define MBARRIER_WAIT_PARITY(mbar, ph) do {                                           \
    uint32_t _m = (uint32_t)(mbar), _p = (uint32_t)(ph), _d;                          \
    asm volatile("{\n\t.reg .pred p;\n\t"                                             \
        "mbarrier.try_wait.parity.acquire.cta.shared::cta.b64 p, [%1], %2;\n\t"       \
        "selp.b32 %0, 1, 0, p;\n\t}" : "=r"(_d) : "r"(_m), "r"(_p) : "memory");       \
    if (!_d) {                                                                        \
        asm volatile("{\n\t.reg .pred P1;\n\t"                                        \
            "WL_%=:\n\t"                                                              \
            "mbarrier.try_wait.parity.acquire.cta.shared::cta.b64 P1, [%0], %1, 0x989680;\n\t" \
            "@P1 bra.uni WD_%=;\n\t"                                                  \
            "bra.uni WL_%=;\n\t"                                                      \
            "WD_%=:\n\t}" :: "r"(_m), "r"(_p) : "memory");                            \
    }                                                                                 \
} while (0)
#define TCGEN05_LD_X32(r, tmem)                                                        \
    asm volatile("tcgen05.ld.sync.aligned.32x32b.x32.b32 "                             \
        "{%0, %1, %2, %3, %4, %5, %6, %7, "                                            \
        " %8, %9, %10, %11, %12, %13, %14, %15, "                                      \
        " %16, %17, %18, %19, %20, %21, %22, %23, "                                    \
        " %24, %25, %26, %27, %28, %29, %30, %31}, [%32];"                             \
        : "=r"((r)[0]),  "=r"((r)[1]),  "=r"((r)[2]),  "=r"((r)[3]),                   \
          "=r"((r)[4]),  "=r"((r)[5]),  "=r"((r)[6]),  "=r"((r)[7]),                   \
          "=r"((r)[8]),  "=r"((r)[9]),  "=r"((r)[10]), "=r"((r)[11]),                  \
          "=r"((r)[12]), "=r"((r)[13]), "=r"((r)[14]), "=r"((r)[15]),                  \
          "=r"((r)[16]), "=r"((r)[17]), "=r"((r)[18]), "=r"((r)[19]),                  \
          "=r"((r)[20]), "=r"((r)[21]), "=r"((r)[22]), "=r"((r)[23]),                  \
          "=r"((r)[24]), "=r"((r)[25]), "=r"((r)[26]), "=r"((r)[27]),                  \
          "=r"((r)[28]), "=r"((r)[29]), "=r"((r)[30]), "=r"((r)[31])                   \
        : "r"(tmem))

__device__ __forceinline__ void tc_mma_tf32_ss(uint32_t d, uint64_t ad, uint64_t bd,
                                               uint32_t idesc, uint32_t en)
{
    asm volatile("{\n\t.reg .pred p;\n\tsetp.ne.u32 p, %4, 0;\n\t"
        "tcgen05.mma.cta_group::1.kind::tf32 [%0], %1, %2, %3, {%5,%5,%5,%5}, p;\n\t}"
        :: "r"(d), "l"(ad), "l"(bd), "r"(idesc), "r"(en), "r"(0u) : "memory");
}
__device__ __forceinline__ uint64_t make_desc(uint32_t saddr)
{
    return (uint64_t(2) << 61) | (uint64_t(1) << 46) | (uint64_t(64) << 32)
         | (uint64_t(1) << 16) | ((uint64_t)(saddr >> 4) & 0x3FFF);
}
#define TC_IDESC ((1u<<4)|(2u<<7)|(2u<<10)|((128u/8u)<<17)|((128u/16u)<<24))
#endif  // HAS_TCGEN05

// ================= GroupNorm =================
__global__ void gn_stats_kernel(const float* __restrict__ x, float* __restrict__ stats)
{
    int bg = blockIdx.x;
    int b = bg / GROUPS, g = bg % GROUPS;
    const float* base = x + (size_t)b*CCH*HW + (size_t)g*CPG*HW;
    int tid = threadIdx.x;
    float s = 0.f, ss = 0.f;
    for (int i = tid; i < CPG*HW; i += 256) { float v = base[i]; s += v; ss += v*v; }
    __shared__ float r1[256], r2[256];
    r1[tid] = s; r2[tid] = ss; __syncthreads();
    for (int st = 128; st > 0; st >>= 1) {
        if (tid < st) { r1[tid] += r1[tid+st]; r2[tid] += r2[tid+st]; }
        __syncthreads();
    }
    if (tid == 0) {
        const float inv = 1.f / (float)(CPG*HW);
        float mean = r1[0]*inv;
        float var  = r2[0]*inv - mean*mean;
        stats[bg*2]   = mean;
        stats[bg*2+1] = rsqrtf(var + 1e-6f);
    }
}

__global__ void gn_apply_kernel(const float* __restrict__ x,
                                const float* __restrict__ gamma,
                                const float* __restrict__ beta,
                                const float* __restrict__ stats,
                                float* __restrict__ out)
{
    __shared__ float tile[32][33];
    int b  = blockIdx.z;
    int c0 = blockIdx.y*32, hw0 = blockIdx.x*32;
    int tx = threadIdx.x, ty = threadIdx.y;
    #pragma unroll
    for (int i = 0; i < 32; i += 8) {
        int c = c0 + ty + i;
        int bg = b*GROUPS + c/CPG;
        float mean = stats[bg*2], rstd = stats[bg*2+1];
        float v = x[((size_t)b*CCH + c)*HW + hw0 + tx];
        tile[ty+i][tx] = (v - mean)*rstd*gamma[c] + beta[c];
    }
    __syncthreads();
    #pragma unroll
    for (int i = 0; i < 32; i += 8) {
        int hw = hw0 + ty + i;
        out[((size_t)b*HW + hw)*CCH + c0 + tx] = tile[tx][ty+i];
    }
}

// ================= weight transpose w[K][N] -> wt[N][K] =================
__global__ void transpose_w(const float* __restrict__ w, float* __restrict__ wt, int K, int N)
{
    __shared__ float t[32][33];
    int k0 = blockIdx.y*32, n0 = blockIdx.x*32;
    int tx = threadIdx.x, ty = threadIdx.y;
    #pragma unroll
    for (int i = 0; i < 32; i += 8)
        t[ty+i][tx] = w[(size_t)(k0+ty+i)*N + n0 + tx];
    __syncthreads();
    #pragma unroll
    for (int i = 0; i < 32; i += 8)
        wt[(size_t)(n0+ty+i)*K + k0 + tx] = t[tx][ty+i];
}

// ================= GEMM 128x128 (proven): C = A @ Bt^T (+bias)(+=) =====
#define TCG_STAGE 65536
#define TCG_CTRL  (3*TCG_STAGE)
#define GEMM_SMEM (3*TCG_STAGE + 64)

__global__ __launch_bounds__(256, 1)
void gemm_tc_kernel(const float* __restrict__ A, const float* __restrict__ Bt,
                    const float* __restrict__ bias, float* __restrict__ C,
                    int M, int N, int K, int accumulate)
{
    extern __shared__ float smem[];
    int tid = threadIdx.x, lane = tid & 31;
    int m0 = blockIdx.y * 128, n0 = blockIdx.x * 128;

#if HAS_TCGEN05
    char* sbase = (char*)smem;
    uint32_t sb = smem_u32(smem);
    int w = tid >> 5;
    int rows_valid = M - m0; if (rows_valid > 128) rows_valid = 128;

    if (w == 0) {
        TCGEN05_ALLOC(sb + TCG_CTRL + 24, 128);
        TCGEN05_RELINQ();
    }
    if (tid == 0) {
        #pragma unroll
        for (int s = 0; s < 3; s++) MBARRIER_INIT(sb + TCG_CTRL + s*8, 1);
    }
    __syncthreads();
    uint32_t tmem;
    asm volatile("ld.shared.b32 %0, [%1];" : "=r"(tmem) : "r"(sb + TCG_CTRL + 24));

    const float* Ab = A  + (size_t)m0*K;
    const float* Bb = Bt + (size_t)n0*K;
    int r_ld = tid >> 3, c_ld = tid & 7;

    auto load_tiles = [&](int slot, int k0) {
        char* st = sbase + slot*TCG_STAGE;
        #pragma unroll
        for (int p = 0; p < 4; p++) {
            int r = r_ld + p*32;
            uint32_t off = (uint32_t)(r*128 + c_ld*16);
            off ^= ((off >> 3) & 0x70);
            int gr = (r < rows_valid) ? r : (rows_valid - 1);
            const float* arow = Ab + (size_t)gr*K + k0 + c_ld*4;
            const float* brow = Bb + (size_t)r*K  + k0 + c_ld*4;
            bool ap = (r < rows_valid);
            cp_async16(st + off,         arow,      ap);
            cp_async16(st + 16384 + off, arow + 32, ap);
            cp_async16(st + 32768 + off, brow,      true);
            cp_async16(st + 49152 + off, brow + 32, true);
        }
    };

    int nk = K / 64;
    uint32_t ph = 0;
    load_tiles(0, 0);   cp_commit();
    load_tiles(1, 64);  cp_commit();

    for (int it = 0; it < nk; it++) {
        int slot = it % 3;
        int rem = nk - 1 - it;
        if (rem >= 1) cp_wait1(); else cp_wait0();
        __syncthreads();
        FENCE_ASYNC_SHARED();

        if (w == 0 && elect_one()) {
            uint32_t stb = sb + slot*TCG_STAGE;
            #pragma unroll
            for (int s = 0; s < 8; s++) {
                uint64_t ad = make_desc(stb + (s >> 2)*16384)         + (uint64_t)(s & 3)*2;
                uint64_t bd = make_desc(stb + 32768 + (s >> 2)*16384) + (uint64_t)(s & 3)*2;
                tc_mma_tf32_ss(tmem, ad, bd, TC_IDESC, (it > 0 || s > 0));
            }
            TCGEN05_COMMIT(sb + TCG_CTRL + slot*8);
        }

        int j = it + 2;
        if (j < nk) {
            int ns = j % 3;
            if (j >= 3) {
                MBARRIER_WAIT_PARITY(sb + TCG_CTRL + ns*8, (ph >> ns) & 1);
                ph ^= (1u << ns);
            }
            load_tiles(ns, j*64);
            cp_commit();
        }
    }
    {
        int sl = (nk - 1) % 3;
        MBARRIER_WAIT_PARITY(sb + TCG_CTRL + sl*8, (ph >> sl) & 1);
    }
    TCGEN05_FENCE_AFTER();
    __syncthreads();

    float* tile = smem;
    {
        int subp = w & 3, half = w >> 2;
        int erow = subp*32 + lane;
        uint32_t ra[32], rb[32];
        TCGEN05_LD_X32(ra, tmem + half*64);
        TCGEN05_LD_X32(rb, tmem + half*64 + 32);
        TCGEN05_WAIT_LD();
        float* dst = tile + (size_t)erow*129 + half*64;
        #pragma unroll
        for (int c = 0; c < 32; c++) {
            dst[c]      = __uint_as_float(ra[c]);
            dst[32 + c] = __uint_as_float(rb[c]);
        }
    }
    __syncthreads();
    {
        float4 bv = make_float4(0.f, 0.f, 0.f, 0.f);
        if (bias) bv = *(const float4*)(bias + n0 + lane*4);
        #pragma unroll
        for (int p = 0; p < 16; p++) {
            int r = p*8 + w;
            int gm = m0 + r;
            if (gm < M) {
                const float* src = tile + (size_t)r*129 + lane*4;
                float4 v = make_float4(src[0]+bv.x, src[1]+bv.y, src[2]+bv.z, src[3]+bv.w);
                float4* op = (float4*)(C + (size_t)gm*N + n0 + lane*4);
                if (accumulate) {
                    float4 o = *op;
                    v.x += o.x; v.y += o.y; v.z += o.z; v.w += o.w;
                }
                *op = v;
            }
        }
    }
    if (w == 0) TCGEN05_DEALLOC(tmem, 128);

#else
    // mma.sync fallback (8 warps, 64x32 warp tiles) — PTX pass only
    float* Abuf = smem;
    float* Bbuf = smem + 2*(128*36);
    int warp = tid >> 5;
    int wm = warp & 1, wn = warp >> 1;
    int grp = lane >> 2, tg = lane & 3;

    float acc[4][4][4];
    #pragma unroll
    for (int mi = 0; mi < 4; mi++)
        #pragma unroll
        for (int ni = 0; ni < 4; ni++)
            #pragma unroll
            for (int r = 0; r < 4; r++) acc[mi][ni][r] = 0.f;

    int r_ld = tid >> 3, c_ld = tid & 7;
    auto load_tile = [&](int buf, int k0) {
        float* as = Abuf + buf*(128*36);
        float* bs = Bbuf + buf*(128*36);
        #pragma unroll
        for (int p = 0; p < 4; p++) {
            int r = r_ld + p*32;
            int gm = m0 + r;
            int gmc = (gm < M) ? gm : (M-1);
            cp_async16(as + r*36 + c_ld*4, A  + (size_t)gmc*K + k0 + c_ld*4, gm < M);
            cp_async16(bs + r*36 + c_ld*4, Bt + (size_t)(n0+r)*K + k0 + c_ld*4, true);
        }
    };

    int nk = K / 32;
    load_tile(0, 0);
    cp_commit();
    for (int it = 0; it < nk; it++) {
        int buf = it & 1;
        cp_wait0();
        __syncthreads();
        if (it + 1 < nk) { load_tile(buf^1, (it+1)*32); cp_commit(); }

        float* as = Abuf + buf*(128*36);
        float* bs = Bbuf + buf*(128*36);
        #pragma unroll
        for (int kk = 0; kk < 32; kk += 8) {
            uint32_t af[4][4], bf[4][2];
            #pragma unroll
            for (int mi = 0; mi < 4; mi++) {
                int m = wm*64 + mi*16 + grp;
                af[mi][0] = __float_as_uint(as[m*36 + kk + tg]);
                af[mi][1] = __float_as_uint(as[(m+8)*36 + kk + tg]);
                af[mi][2] = __float_as_uint(as[m*36 + kk + tg + 4]);
                af[mi][3] = __float_as_uint(as[(m+8)*36 + kk + tg + 4]);
            }
            #pragma unroll
            for (int ni = 0; ni < 4; ni++) {
                int n = wn*32 + ni*8 + grp;
                bf[ni][0] = __float_as_uint(bs[n*36 + kk + tg]);
                bf[ni][1] = __float_as_uint(bs[n*36 + kk + tg + 4]);
            }
            #pragma unroll
            for (int mi = 0; mi < 4; mi++)
                #pragma unroll
                for (int ni = 0; ni < 4; ni++)
                    mma_tf32(acc[mi][ni][0], acc[mi][ni][1], acc[mi][ni][2], acc[mi][ni][3],
                             af[mi][0], af[mi][1], af[mi][2], af[mi][3],
                             bf[ni][0], bf[ni][1]);
        }
    }

    #pragma unroll
    for (int mi = 0; mi < 4; mi++) {
        int r0 = m0 + wm*64 + mi*16 + grp;
        #pragma unroll
        for (int ni = 0; ni < 4; ni++) {
            int c0 = n0 + wn*32 + ni*8 + tg*2;
            float bv0 = bias ? bias[c0]   : 0.f;
            float bv1 = bias ? bias[c0+1] : 0.f;
            if (r0 < M) {
                size_t o = (size_t)r0*N + c0;
                float v0 = acc[mi][ni][0] + bv0;
                float v1 = acc[mi][ni][1] + bv1;
                if (accumulate) { C[o] += v0; C[o+1] += v1; }
                else            { C[o]  = v0; C[o+1]  = v1; }
            }
            if (r0 + 8 < M) {
                size_t o = (size_t)(r0+8)*N + c0;
                float v2 = acc[mi][ni][2] + bv0;
                float v3 = acc[mi][ni][3] + bv1;
                if (accumulate) { C[o] += v2; C[o+1] += v3; }
                else            { C[o]  = v2; C[o+1]  = v3; }
            }
        }
    }
#endif
}

// ================= GEMM 128x128 with fused transpose+residual output ========
// out[b][n][hw] = (A @ Bt^T)[m][n] + bias[n] + x[b][n][hw],  m = b*HW + hw.
// M = MTOK, N = CCH. Mainloop identical to gemm_tc_kernel.
__global__ __launch_bounds__(256, 1)
void gemm_out_kernel(const float* __restrict__ A, const float* __restrict__ Bt,
                     const float* __restrict__ bias, const float* __restrict__ x,
                     float* __restrict__ outp, int K)
{
    extern __shared__ float smem[];
    int tid = threadIdx.x, lane = tid & 31;
    int m0 = blockIdx.y * 128, n0 = blockIdx.x * 128;

#if HAS_TCGEN05
    char* sbase = (char*)smem;
    uint32_t sb = smem_u32(smem);
    int w = tid >> 5;

    if (w == 0) {
        TCGEN05_ALLOC(sb + TCG_CTRL + 24, 128);
        TCGEN05_RELINQ();
    }
    if (tid == 0) {
        #pragma unroll
        for (int s = 0; s < 3; s++) MBARRIER_INIT(sb + TCG_CTRL + s*8, 1);
    }
    __syncthreads();
    uint32_t tmem;
    asm volatile("ld.shared.b32 %0, [%1];" : "=r"(tmem) : "r"(sb + TCG_CTRL + 24));

    const float* Ab = A  + (size_t)m0*K;
    const float* Bb = Bt + (size_t)n0*K;
    int r_ld = tid >> 3, c_ld = tid & 7;

    auto load_tiles = [&](int slot, int k0) {
        char* st = sbase + slot*TCG_STAGE;
        #pragma unroll
        for (int p = 0; p < 4; p++) {
            int r = r_ld + p*32;
            uint32_t off = (uint32_t)(r*128 + c_ld*16);
            off ^= ((off >> 3) & 0x70);
            const float* arow = Ab + (size_t)r*K + k0 + c_ld*4;
            const float* brow = Bb + (size_t)r*K + k0 + c_ld*4;
            cp_async16(st + off,         arow,      true);
            cp_async16(st + 16384 + off, arow + 32, true);
            cp_async16(st + 32768 + off, brow,      true);
            cp_async16(st + 49152 + off, brow + 32, true);
        }
    };

    int nk = K / 64;
    uint32_t ph = 0;
    load_tiles(0, 0);   cp_commit();
    load_tiles(1, 64);  cp_commit();

    for (int it = 0; it < nk; it++) {
        int slot = it % 3;
        int rem = nk - 1 - it;
        if (rem >= 1) cp_wait1(); else cp_wait0();
        __syncthreads();
        FENCE_ASYNC_SHARED();

        if (w == 0 && elect_one()) {
            uint32_t stb = sb + slot*TCG_STAGE;
            #pragma unroll
            for (int s = 0; s < 8; s++) {
                uint64_t ad = make_desc(stb + (s >> 2)*16384)         + (uint64_t)(s & 3)*2;
                uint64_t bd = make_desc(stb + 32768 + (s >> 2)*16384) + (uint64_t)(s & 3)*2;
                tc_mma_tf32_ss(tmem, ad, bd, TC_IDESC, (it > 0 || s > 0));
            }
            TCGEN05_COMMIT(sb + TCG_CTRL + slot*8);
        }

        int j = it + 2;
        if (j < nk) {
            int ns = j % 3;
            if (j >= 3) {
                MBARRIER_WAIT_PARITY(sb + TCG_CTRL + ns*8, (ph >> ns) & 1);
                ph ^= (1u << ns);
            }
            load_tiles(ns, j*64);
            cp_commit();
        }
    }
    {
        int sl = (nk - 1) % 3;
        MBARRIER_WAIT_PARITY(sb + TCG_CTRL + sl*8, (ph >> sl) & 1);
    }
    TCGEN05_FENCE_AFTER();
    __syncthreads();

    float* tile = smem;
    {
        int subp = w & 3, half = w >> 2;
        int erow = subp*32 + lane;
        uint32_t ra[32], rb[32];
        TCGEN05_LD_X32(ra, tmem + half*64);
        TCGEN05_LD_X32(rb, tmem + half*64 + 32);
        TCGEN05_WAIT_LD();
        float* dst = tile + (size_t)erow*129 + half*64;
        #pragma unroll
        for (int c = 0; c < 32; c++) {
            dst[c]      = __uint_as_float(ra[c]);
            dst[32 + c] = __uint_as_float(rb[c]);
        }
    }
    __syncthreads();

    // transposed epilogue: warp w owns 16 channels; lane owns 4 hw positions
    {
        int b   = m0 >> 10;          // m0 / HW
        int hw0 = m0 & 1023;
        #pragma unroll
        for (int i = 0; i < 16; i++) {
            int cc = w*16 + i;
            int gc = n0 + cc;
            float bv = __ldg(bias + gc);
            size_t gbase = ((size_t)(b*CCH + gc))*HW + hw0 + lane*4;
            float4 xv = *(const float4*)(x + gbase);
            const float* src = tile + (size_t)(lane*4)*129 + cc;
            float4 v;
            v.x = src[0]     + bv + xv.x;
            v.y = src[129]   + bv + xv.y;
            v.z = src[258]   + bv + xv.z;
            v.w = src[387]   + bv + xv.w;
            *(float4*)(outp + gbase) = v;
        }
    }
    if (w == 0) TCGEN05_DEALLOC(tmem, 128);

#else
    // naive fallback (PTX pass only; never executed on sm_103a)
    for (int idx = tid; idx < 128*128; idx += 256) {
        int r = idx >> 7, c = idx & 127;
        int gm = m0 + r;
        int gc = n0 + c;
        float s = bias[gc];
        for (int k = 0; k < K; k++)
            s += A[(size_t)gm*K + k] * Bt[(size_t)gc*K + k];
        int b = gm / HW, hw = gm % HW;
        size_t o = ((size_t)(b*CCH + gc))*HW + hw;
        outp[o] = s + x[o];
    }
#endif
}

// ================= GEMM 256x128 (BM=256, K64 stages, 2-stage) ===============
#define T256_STAGE 98304
#define T256_CTRL  (2*T256_STAGE)
#define GEMM256_SMEM (2*T256_STAGE + 64)

__global__ __launch_bounds__(256, 1)
void gemm_tc256_kernel(const float* __restrict__ A, const float* __restrict__ Bt,
                       const float* __restrict__ bias, float* __restrict__ C,
                       int M, int N, int K, int accumulate)
{
    extern __shared__ float smem[];
    int tid = threadIdx.x, lane = tid & 31;
    int m0 = blockIdx.y * 256, n0 = blockIdx.x * 128;

#if HAS_TCGEN05
    char* sbase = (char*)smem;
    uint32_t sb = smem_u32(smem);
    int w = tid >> 5;

    if (w == 0) {
        TCGEN05_ALLOC(sb + T256_CTRL + 16, 256);
        TCGEN05_RELINQ();
    }
    if (tid == 0) {
        MBARRIER_INIT(sb + T256_CTRL,     1);
        MBARRIER_INIT(sb + T256_CTRL + 8, 1);
    }
    __syncthreads();
    uint32_t tmem;
    asm volatile("ld.shared.b32 %0, [%1];" : "=r"(tmem) : "r"(sb + T256_CTRL + 16));

    const float* Ab = A  + (size_t)m0*K;
    const float* Bb = Bt + (size_t)n0*K;
    int r_ld = tid >> 3, c_ld = tid & 7;

    auto load_tiles = [&](int slot, int k0) {
        char* st = sbase + slot*T256_STAGE;
        #pragma unroll
        for (int p = 0; p < 8; p++) {
            int r = r_ld + p*32;
            int half = r >> 7, rr = r & 127;
            uint32_t off = (uint32_t)(rr*128 + c_ld*16);
            off ^= ((off >> 3) & 0x70);
            const float* arow = Ab + (size_t)r*K + k0 + c_ld*4;
            cp_async16(st + half*32768 + off,         arow,      true);
            cp_async16(st + half*32768 + 16384 + off, arow + 32, true);
        }
        #pragma unroll
        for (int p = 0; p < 4; p++) {
            int r = r_ld + p*32;
            uint32_t off = (uint32_t)(r*128 + c_ld*16);
            off ^= ((off >> 3) & 0x70);
            const float* brow = Bb + (size_t)r*K + k0 + c_ld*4;
            cp_async16(st + 65536 + off, brow,      true);
            cp_async16(st + 81920 + off, brow + 32, true);
        }
    };

    int nk = K / 64;
    uint32_t ph = 0;
    load_tiles(0, 0);   cp_commit();
    if (nk > 1) { load_tiles(1, 64); cp_commit(); }

    for (int it = 0; it < nk; it++) {
        int slot = it & 1;
        int rem = nk - 1 - it;
        if (rem >= 1) cp_wait1(); else cp_wait0();
        __syncthreads();
        FENCE_ASYNC_SHARED();

        if (w == 0 && elect_one()) {
            uint32_t stb = sb + slot*T256_STAGE;
            #pragma unroll
            for (int s = 0; s < 8; s++) {
                int kb = s >> 2;
                uint64_t step = (uint64_t)(s & 3)*2;
                uint64_t ad0 = make_desc(stb + kb*16384)         + step;
                uint64_t ad1 = make_desc(stb + 32768 + kb*16384) + step;
                uint64_t bd  = make_desc(stb + 65536 + kb*16384) + step;
                uint32_t en = (it > 0 || s > 0);
                tc_mma_tf32_ss(tmem,       ad0, bd, TC_IDESC, en);
                tc_mma_tf32_ss(tmem + 128, ad1, bd, TC_IDESC, en);
            }
            TCGEN05_COMMIT(sb + T256_CTRL + slot*8);
        }

        int j = it + 2;
        if (j < nk) {
            int ns = j & 1;
            MBARRIER_WAIT_PARITY(sb + T256_CTRL + ns*8, (ph >> ns) & 1);
            ph ^= (1u << ns);
            load_tiles(ns, j*64);
            cp_commit();
        }
    }
    {
        int sl = (nk - 1) & 1;
        MBARRIER_WAIT_PARITY(sb + T256_CTRL + sl*8, (ph >> sl) & 1);
    }
    TCGEN05_FENCE_AFTER();
    __syncthreads();

    float* tile = smem;
    float4 bv = make_float4(0.f, 0.f, 0.f, 0.f);
    if (bias) bv = *(const float4*)(bias + n0 + lane*4);

    for (int acc = 0; acc < 2; acc++) {
        {
            int subp = w & 3, half = w >> 2;
            int erow = subp*32 + lane;
            uint32_t ra[32], rb[32];
            TCGEN05_LD_X32(ra, tmem + acc*128 + half*64);
            TCGEN05_LD_X32(rb, tmem + acc*128 + half*64 + 32);
            TCGEN05_WAIT_LD();
            float* dst = tile + (size_t)erow*129 + half*64;
            #pragma unroll
            for (int c = 0; c < 32; c++) {
                dst[c]      = __uint_as_float(ra[c]);
                dst[32 + c] = __uint_as_float(rb[c]);
            }
        }
        __syncthreads();
        #pragma unroll
        for (int p = 0; p < 16; p++) {
            int r = p*8 + w;
            int gm = m0 + acc*128 + r;
            const float* src = tile + (size_t)r*129 + lane*4;
            float4 v = make_float4(src[0]+bv.x, src[1]+bv.y, src[2]+bv.z, src[3]+bv.w);
            float4* op = (float4*)(C + (size_t)gm*N + n0 + lane*4);
            if (accumulate) {
                float4 o = *op;
                v.x += o.x; v.y += o.y; v.z += o.z; v.w += o.w;
            }
            *op = v;
        }
        __syncthreads();
    }
    if (w == 0) TCGEN05_DEALLOC(tmem, 256);

#else
    for (int idx = tid; idx < 256*128; idx += 256) {
        int r = idx >> 7, c = idx & 127;
        float s = bias ? bias[n0 + c] : 0.f;
        for (int k = 0; k < K; k++)
            s += A[(size_t)(m0 + r)*K + k] * Bt[(size_t)(n0 + c)*K + k];
        size_t o = (size_t)(m0 + r)*N + n0 + c;
        if (accumulate) C[o] += s; else C[o] = s;
    }
#endif
}

// ================= fused GEGLU GEMM: ff = a * gelu(gate) ====================
#define GG_STAGE 65536
#define GG_CTRL  (3*GG_STAGE)
#define GEGLU_SMEM (3*GG_STAGE + 64)

__global__ __launch_bounds__(256, 1)
void geglu_tc_kernel(const float* __restrict__ A, const float* __restrict__ Bta,
                     const float* __restrict__ Btg, const float* __restrict__ bias,
                     float* __restrict__ FFo, int M, int K)
{
    extern __shared__ float smem[];
    int tid = threadIdx.x, lane = tid & 31;
    int m0 = blockIdx.y * 256, n0 = blockIdx.x * 128;

#if HAS_TCGEN05
    char* sbase = (char*)smem;
    uint32_t sb = smem_u32(smem);
    int w = tid >> 5;

    if (w == 0) {
        TCGEN05_ALLOC(sb + GG_CTRL + 24, 512);
        TCGEN05_RELINQ();
    }
    if (tid == 0) {
        #pragma unroll
        for (int s = 0; s < 3; s++) MBARRIER_INIT(sb + GG_CTRL + s*8, 1);
    }
    __syncthreads();
    uint32_t tmem;
    asm volatile("ld.shared.b32 %0, [%1];" : "=r"(tmem) : "r"(sb + GG_CTRL + 24));

    const float* Ab  = A   + (size_t)m0*K;
    const float* Bab = Bta + (size_t)n0*K;
    const float* Bgb = Btg + (size_t)n0*K;
    int r_ld = tid >> 3, c_ld = tid & 7;

    auto load_tiles = [&](int slot, int k0) {
        char* st = sbase + slot*GG_STAGE;
        #pragma unroll
        for (int p = 0; p < 8; p++) {
            int r = r_ld + p*32;
            int blk = r >> 7, rr = r & 127;
            uint32_t off = (uint32_t)(rr*128 + c_ld*16);
            off ^= ((off >> 3) & 0x70);
            cp_async16(st + blk*16384 + off, Ab + (size_t)r*K + k0 + c_ld*4, true);
        }
        #pragma unroll
        for (int p = 0; p < 4; p++) {
            int r = r_ld + p*32;
            uint32_t off = (uint32_t)(r*128 + c_ld*16);
            off ^= ((off >> 3) & 0x70);
            cp_async16(st + 32768 + off, Bab + (size_t)r*K + k0 + c_ld*4, true);
            cp_async16(st + 49152 + off, Bgb + (size_t)r*K + k0 + c_ld*4, true);
        }
    };

    int nk = K / 32;
    uint32_t ph = 0;
    load_tiles(0, 0);   cp_commit();
    load_tiles(1, 32);  cp_commit();

    for (int it = 0; it < nk; it++) {
        int slot = it % 3;
        int rem = nk - 1 - it;
        if (rem >= 1) cp_wait1(); else cp_wait0();
        __syncthreads();
        FENCE_ASYNC_SHARED();

        if (w == 0 && elect_one()) {
            uint32_t stb = sb + slot*GG_STAGE;
            #pragma unroll
            for (int s = 0; s < 4; s++) {
                uint64_t ad0 = make_desc(stb)          + (uint64_t)s*2;
                uint64_t ad1 = make_desc(stb + 16384)  + (uint64_t)s*2;
                uint64_t bad = make_desc(stb + 32768)  + (uint64_t)s*2;
                uint64_t bgd = make_desc(stb + 49152)  + (uint64_t)s*2;
                uint32_t en = (it > 0 || s > 0);
                tc_mma_tf32_ss(tmem,       ad0, bad, TC_IDESC, en);
                tc_mma_tf32_ss(tmem + 128, ad1, bad, TC_IDESC, en);
                tc_mma_tf32_ss(tmem + 256, ad0, bgd, TC_IDESC, en);
                tc_mma_tf32_ss(tmem + 384, ad1, bgd, TC_IDESC, en);
            }
            TCGEN05_COMMIT(sb + GG_CTRL + slot*8);
        }

        int j = it + 2;
        if (j < nk) {
            int ns = j % 3;
            if (j >= 3) {
                MBARRIER_WAIT_PARITY(sb + GG_CTRL + ns*8, (ph >> ns) & 1);
                ph ^= (1u << ns);
            }
            load_tiles(ns, j*32);
            cp_commit();
        }
    }
    {
        int sl = (nk - 1) % 3;
        MBARRIER_WAIT_PARITY(sb + GG_CTRL + sl*8, (ph >> sl) & 1);
    }
    TCGEN05_FENCE_AFTER();
    __syncthreads();

    float* tile = smem;
    const float inv_sqrt2 = 0.70710678118654752f;

    for (int h = 0; h < 2; h++) {
        {
            int subp = w & 3, ch = w >> 2;
            int erow = subp*32 + lane;
            float* dst = tile + (size_t)erow*129 + ch*64;
            #pragma unroll
            for (int cc = 0; cc < 2; cc++) {
                uint32_t ra[32], rg[32];
                TCGEN05_LD_X32(ra, tmem + h*128 + ch*64 + cc*32);
                TCGEN05_LD_X32(rg, tmem + 256 + h*128 + ch*64 + cc*32);
                TCGEN05_WAIT_LD();
                #pragma unroll
                for (int c = 0; c < 32; c++) {
                    int col = ch*64 + cc*32 + c;
                    float av = __uint_as_float(ra[c]) + __ldg(bias + n0 + col);
                    float gv = __uint_as_float(rg[c]) + __ldg(bias + FF + n0 + col);
                    float gel = 0.5f*gv*(1.f + erff(gv*inv_sqrt2));
                    dst[cc*32 + c] = av * gel;
                }
            }
        }
        __syncthreads();
        #pragma unroll
        for (int p = 0; p < 16; p++) {
            int r = p*8 + w;
            int gm = m0 + h*128 + r;
            const float* src = tile + (size_t)r*129 + lane*4;
            *(float4*)(FFo + (size_t)gm*FF + n0 + lane*4) =
                make_float4(src[0], src[1], src[2], src[3]);
        }
        __syncthreads();
    }
    if (w == 0) TCGEN05_DEALLOC(tmem, 512);

#else
    for (int idx = tid; idx < 256*128; idx += 256) {
        int r = idx >> 7, c = idx & 127;
        float sa = bias[n0 + c], sg = bias[FF + n0 + c];
        for (int k = 0; k < K; k++) {
            float av = A[(size_t)(m0 + r)*K + k];
            sa += av * Bta[(size_t)(n0 + c)*K + k];
            sg += av * Btg[(size_t)(n0 + c)*K + k];
        }
        float gel = 0.5f*sg*(1.f + erff(sg*0.70710678118654752f));
        FFo[(size_t)(m0 + r)*FF + n0 + c] = sa * gel;
    }
#endif
}

// ================= LayerNorm (warp per row) =================
__global__ void layernorm_kernel(const float* __restrict__ in,
                                 const float* __restrict__ g,
                                 const float* __restrict__ bta,
                                 float* __restrict__ out)
{
    int w = threadIdx.x >> 5, lane = threadIdx.x & 31;
    size_t row = (size_t)blockIdx.x*8 + w;
    const float4* p = (const float4*)(in + row*CCH);
    float4 v[5];
    float s = 0.f, ss = 0.f;
    #pragma unroll
    for (int i = 0; i < 5; i++) {
        v[i] = p[lane + 32*i];
        s  += v[i].x + v[i].y + v[i].z + v[i].w;
        ss += v[i].x*v[i].x + v[i].y*v[i].y + v[i].z*v[i].z + v[i].w*v[i].w;
    }
    #pragma unroll
    for (int o = 16; o >= 1; o >>= 1) {
        s  += __shfl_xor_sync(0xffffffffu, s, o);
        ss += __shfl_xor_sync(0xffffffffu, ss, o);
    }
    float mean = s * (1.f/CCH);
    float rstd = rsqrtf(ss * (1.f/CCH) - mean*mean + 1e-5f);
    const float4* g4 = (const float4*)g;
    const float4* b4 = (const float4*)bta;
    float4* o4 = (float4*)(out + row*CCH);
    #pragma unroll
    for (int i = 0; i < 5; i++) {
        float4 gg = g4[lane + 32*i], bb = b4[lane + 32*i];
        float4 r;
        r.x = (v[i].x - mean)*rstd*gg.x + bb.x;
        r.y = (v[i].y - mean)*rstd*gg.y + bb.y;
        r.z = (v[i].z - mean)*rstd*gg.z + bb.z;
        r.w = (v[i].w - mean)*rstd*gg.w + bb.w;
        o4[lane + 32*i] = r;
    }
}

// ================= flash attention (mma.sync tf32, double-buffered KV) ======
#define FTQ 128
#define FTJ 64
#define QS_STR 84
#define KS_STR 84
#define VS_STR 88
#define PS_STR 68
#define KVBUF (FTJ*KS_STR + FTJ*VS_STR)
#define FLASH_SMEM ((FTQ*QS_STR + 2*KVBUF) * (int)sizeof(float))

__global__ __launch_bounds__(256, 1)
void flash_attn_mma_kernel(const float* __restrict__ Q, const float* __restrict__ K,
                           const float* __restrict__ V, float* __restrict__ O,
                           int Lk, int qRow, int kvRow, size_t kvBatch, int oRow)
{
    extern __shared__ float sm[];
    float* QPs = sm;
    float* KV0 = sm + FTQ*QS_STR;

    int tid = threadIdx.x, lane = tid & 31, w = tid >> 5;
    int qr = lane >> 2, qc = lane & 3;
    int bh = blockIdx.y;
    int b = bh / HEADS, h = bh % HEADS;
    int i0 = blockIdx.x * FTQ;
    const float scale = 0.1118033988749895f;

    const float* qb = Q + ((size_t)(b*HW) + i0)*qRow + h*DH;
    const float* kb = K + (size_t)b*kvBatch + h*DH;
    const float* vb = V + (size_t)b*kvBatch + h*DH;

    int kv_r = tid >> 2, kv_c = tid & 3;
    auto load_kv = [&](int buf, int j0) {
        float* Ks = KV0 + buf*KVBUF;
        float* Vs = Ks + FTJ*KS_STR;
        #pragma unroll
        for (int q4 = kv_c; q4 < 20; q4 += 4) {
            int gj = j0 + kv_r;
            int gjc = (gj < Lk) ? gj : (Lk - 1);
            cp_async16(Ks + kv_r*KS_STR + q4*4, kb + (size_t)gjc*kvRow + q4*4, true);
            cp_async16(Vs + kv_r*VS_STR + q4*4, vb + (size_t)gjc*kvRow + q4*4, true);
        }
    };

    load_kv(0, 0);
    cp_commit();
    for (int idx = tid; idx < FTQ*20; idx += 256) {
        int i = idx / 20, q4 = (idx % 20)*4;
        float4 qv = *(const float4*)(qb + (size_t)i*qRow + q4);
        qv.x *= scale; qv.y *= scale; qv.z *= scale; qv.w *= scale;
        *(float4*)(QPs + i*QS_STR + q4) = qv;
    }
    __syncthreads();

    int r0 = w*16 + qr;
    uint32_t qf[10][4];
    #pragma unroll
    for (int kk = 0; kk < 10; kk++) {
        int d0 = kk*8 + qc;
        qf[kk][0] = __float_as_uint(QPs[(size_t)r0*QS_STR + d0]);
        qf[kk][1] = __float_as_uint(QPs[(size_t)(r0+8)*QS_STR + d0]);
        qf[kk][2] = __float_as_uint(QPs[(size_t)r0*QS_STR + d0+4]);
        qf[kk][3] = __float_as_uint(QPs[(size_t)(r0+8)*QS_STR + d0+4]);
    }
    __syncthreads();

    float m0v = -1e30f, m1v = -1e30f, l0 = 0.f, l1 = 0.f;
    float oacc[10][4];
    #pragma unroll
    for (int nt = 0; nt < 10; nt++)
        #pragma unroll
        for (int r = 0; r < 4; r++) oacc[nt][r] = 0.f;

    int nchunks = (Lk + FTJ - 1) / FTJ;
    for (int c = 0; c < nchunks; c++) {
        int buf = c & 1;
        if (c + 1 < nchunks) {
            load_kv(buf ^ 1, (c + 1)*FTJ);
            cp_commit();
            cp_wait1();
        } else {
            cp_wait0();
        }
        __syncthreads();

        float* Ks = KV0 + buf*KVBUF;
        float* Vs = Ks + FTJ*KS_STR;
        int j0 = c*FTJ;

        float sc[8][4];
        #pragma unroll
        for (int nt = 0; nt < 8; nt++)
            #pragma unroll
            for (int r = 0; r < 4; r++) sc[nt][r] = 0.f;

        #pragma unroll
        for (int kk = 0; kk < 10; kk++) {
            int d0 = kk*8 + qc;
            #pragma unroll
            for (int nt = 0; nt < 8; nt++) {
                int j = nt*8 + qr;
                uint32_t b0 = __float_as_uint(Ks[(size_t)j*KS_STR + d0]);
                uint32_t b1 = __float_as_uint(Ks[(size_t)j*KS_STR + d0+4]);
                mma_tf32(sc[nt][0], sc[nt][1], sc[nt][2], sc[nt][3],
                         qf[kk][0], qf[kk][1], qf[kk][2], qf[kk][3], b0, b1);
            }
        }

        if (j0 + FTJ > Lk) {
            #pragma unroll
            for (int nt = 0; nt < 8; nt++) {
                int jc = j0 + nt*8 + qc*2;
                if (jc   >= Lk) { sc[nt][0] = -1e30f; sc[nt][2] = -1e30f; }
                if (jc+1 >= Lk) { sc[nt][1] = -1e30f; sc[nt][3] = -1e30f; }
            }
        }

        float mx0 = -1e30f, mx1 = -1e30f;
        #pragma unroll
        for (int nt = 0; nt < 8; nt++) {
            mx0 = fmaxf(mx0, fmaxf(sc[nt][0], sc[nt][1]));
            mx1 = fmaxf(mx1, fmaxf(sc[nt][2], sc[nt][3]));
        }
        mx0 = fmaxf(mx0, __shfl_xor_sync(0xffffffffu, mx0, 1));
        mx0 = fmaxf(mx0, __shfl_xor_sync(0xffffffffu, mx0, 2));
        mx1 = fmaxf(mx1, __shfl_xor_sync(0xffffffffu, mx1, 1));
        mx1 = fmaxf(mx1, __shfl_xor_sync(0xffffffffu, mx1, 2));

        float mn0 = fmaxf(m0v, mx0), mn1 = fmaxf(m1v, mx1);
        float al0 = __expf(m0v - mn0), al1 = __expf(m1v - mn1);
        float rs0 = 0.f, rs1 = 0.f;
        #pragma unroll
        for (int nt = 0; nt < 8; nt++) {
            sc[nt][0] = __expf(sc[nt][0] - mn0);
            sc[nt][1] = __expf(sc[nt][1] - mn0);
            sc[nt][2] = __expf(sc[nt][2] - mn1);
            sc[nt][3] = __expf(sc[nt][3] - mn1);
            rs0 += sc[nt][0] + sc[nt][1];
            rs1 += sc[nt][2] + sc[nt][3];
        }
        rs0 += __shfl_xor_sync(0xffffffffu, rs0, 1);
        rs0 += __shfl_xor_sync(0xffffffffu, rs0, 2);
        rs1 += __shfl_xor_sync(0xffffffffu, rs1, 1);
        rs1 += __shfl_xor_sync(0xffffffffu, rs1, 2);

        l0 = l0*al0 + rs0;  m0v = mn0;
        l1 = l1*al1 + rs1;  m1v = mn1;

        #pragma unroll
        for (int nt = 0; nt < 10; nt++) {
            oacc[nt][0] *= al0; oacc[nt][1] *= al0;
            oacc[nt][2] *= al1; oacc[nt][3] *= al1;
        }

        float* Ps = QPs;
        #pragma unroll
        for (int nt = 0; nt < 8; nt++) {
            int jc = nt*8 + qc*2;
            *(float2*)(Ps + (size_t)r0*PS_STR + jc)     = make_float2(sc[nt][0], sc[nt][1]);
            *(float2*)(Ps + (size_t)(r0+8)*PS_STR + jc) = make_float2(sc[nt][2], sc[nt][3]);
        }
        __syncwarp();

        #pragma unroll
        for (int kk = 0; kk < 8; kk++) {
            int jj = kk*8 + qc;
            uint32_t a0 = __float_as_uint(Ps[(size_t)r0*PS_STR + jj]);
            uint32_t a1 = __float_as_uint(Ps[(size_t)(r0+8)*PS_STR + jj]);
            uint32_t a2 = __float_as_uint(Ps[(size_t)r0*PS_STR + jj+4]);
            uint32_t a3 = __float_as_uint(Ps[(size_t)(r0+8)*PS_STR + jj+4]);
            #pragma unroll
            for (int nt = 0; nt < 10; nt++) {
                int d = nt*8 + qr;
                uint32_t b0 = __float_as_uint(Vs[(size_t)jj*VS_STR + d]);
                uint32_t b1 = __float_as_uint(Vs[(size_t)(jj+4)*VS_STR + d]);
                mma_tf32(oacc[nt][0], oacc[nt][1], oacc[nt][2], oacc[nt][3],
                         a0, a1, a2, a3, b0, b1);
            }
        }
        __syncthreads();
    }

    float inv0 = 1.f / l0, inv1 = 1.f / l1;
    float* ob = O + ((size_t)(b*HW) + i0 + r0)*oRow + h*DH;
    #pragma unroll
    for (int nt = 0; nt < 10; nt++) {
        int dc = nt*8 + qc*2;
        *(float2*)(ob + dc)                  = make_float2(oacc[nt][0]*inv0, oacc[nt][1]*inv0);
        *(float2*)(ob + (size_t)8*oRow + dc) = make_float2(oacc[nt][2]*inv1, oacc[nt][3]*inv1);
    }
}

extern "C" void kernel_launch(void* const* d_in, const int* in_sizes, int n_in,
                              void* d_out, int out_size)
{
    const float* x       = (const float*)d_in[0];
    const float* context = (const float*)d_in[1];
    const float* gn_g    = (const float*)d_in[2];
    const float* gn_b    = (const float*)d_in[3];
    const float* w_in    = (const float*)d_in[4];
    const float* b_in    = (const float*)d_in[5];
    const float* ln1_g   = (const float*)d_in[6];
    const float* ln1_b   = (const float*)d_in[7];
    const float* wq1     = (const float*)d_in[8];
    const float* wk1     = (const float*)d_in[9];
    const float* wv1     = (const float*)d_in[10];
    const float* wo1     = (const float*)d_in[11];
    const float* bo1     = (const float*)d_in[12];
    const float* ln2_g   = (const float*)d_in[13];
    const float* ln2_b   = (const float*)d_in[14];
    const float* wq2     = (const float*)d_in[15];
    const float* wk2     = (const float*)d_in[16];
    const float* wv2     = (const float*)d_in[17];
    const float* wo2     = (const float*)d_in[18];
    const float* bo2     = (const float*)d_in[19];
    const float* ln3_g   = (const float*)d_in[20];
    const float* ln3_b   = (const float*)d_in[21];
    const float* w_geglu = (const float*)d_in[22];
    const float* b_geglu = (const float*)d_in[23];
    const float* w_ffo   = (const float*)d_in[24];
    const float* b_ffo   = (const float*)d_in[25];
    const float* w_out   = (const float*)d_in[26];
    const float* b_out   = (const float*)d_in[27];
    float* out = (float*)d_out;

    float *p_t, *p_tn, *p_q, *p_ao, *p_qkv, *p_kv, *p_ff, *p_wt, *p_stats;
    cudaGetSymbolAddress((void**)&p_t,    g_t);
    cudaGetSymbolAddress((void**)&p_tn,   g_tn);
    cudaGetSymbolAddress((void**)&p_q,    g_q);
    cudaGetSymbolAddress((void**)&p_ao,   g_ao);
    cudaGetSymbolAddress((void**)&p_qkv,  g_qkv);
    cudaGetSymbolAddress((void**)&p_kv,   g_kv);
    cudaGetSymbolAddress((void**)&p_ff,   g_ff);
    cudaGetSymbolAddress((void**)&p_wt,   g_wt);
    cudaGetSymbolAddress((void**)&p_stats,g_stats);

    cudaFuncSetAttribute(flash_attn_mma_kernel,
                         cudaFuncAttributeMaxDynamicSharedMemorySize, FLASH_SMEM);
    cudaFuncSetAttribute(gemm_tc_kernel,
                         cudaFuncAttributeMaxDynamicSharedMemorySize, GEMM_SMEM);
    cudaFuncSetAttribute(gemm_out_kernel,
                         cudaFuncAttributeMaxDynamicSharedMemorySize, GEMM_SMEM);
    cudaFuncSetAttribute(gemm_tc256_kernel,
                         cudaFuncAttributeMaxDynamicSharedMemorySize, GEMM256_SMEM);
    cudaFuncSetAttribute(geglu_tc_kernel,
                         cudaFuncAttributeMaxDynamicSharedMemorySize, GEGLU_SMEM);

    dim3 tb(32, 8);
    dim3 tp_grid(HW/32, CCH/32, BATCH);

    #define TW(w_, dst_, K_, N_) \
        transpose_w<<<dim3((N_)/32, (K_)/32), tb>>>(w_, dst_, K_, N_)
    #define GEMM_TC(A_, Bt_, bias_, C_, M_, N_, K_, acc_) \
        gemm_tc_kernel<<<dim3((N_)/128, ((M_)+127)/128), 256, GEMM_SMEM>>>( \
            A_, Bt_, bias_, C_, M_, N_, K_, acc_)

    // 1) GroupNorm -> token-major
    gn_stats_kernel<<<BATCH*GROUPS, 256>>>(x, p_stats);
    gn_apply_kernel<<<tp_grid, tb>>>(x, gn_g, gn_b, p_stats, p_tn);

    // 2) proj_in (128-kernel — R13 proven mapping)
    TW(w_in, p_wt, CCH, CCH);
    GEMM_TC(p_tn, p_wt, b_in, p_t, MTOK, CCH, CCH, 0);

    // 3) self-attention (packed QKV on BM=256/K64 kernel, N=1920)
    layernorm_kernel<<<MTOK/8, 256>>>(p_t, ln1_g, ln1_b, p_tn);
    TW(wq1, p_wt,             CCH, CCH);
    TW(wk1, p_wt + 640*640,   CCH, CCH);
    TW(wv1, p_wt + 2*640*640, CCH, CCH);
    gemm_tc256_kernel<<<dim3(1920/128, MTOK/256), 256, GEMM256_SMEM>>>(
        p_tn, p_wt, nullptr, p_qkv, MTOK, 1920, CCH, 0);
    flash_attn_mma_kernel<<<dim3(HW/FTQ, BATCH*HEADS), 256, FLASH_SMEM>>>(
        p_qkv, p_qkv + 640, p_qkv + 1280, p_ao, HW, 1920, 1920, (size_t)HW*1920, CCH);
    TW(wo1, p_wt, CCH, CCH);
    GEMM_TC(p_ao, p_wt, bo1, p_t, MTOK, CCH, CCH, 1);

    // 4) cross-attention
    layernorm_kernel<<<MTOK/8, 256>>>(p_t, ln2_g, ln2_b, p_tn);
    TW(wq2, p_wt, CCH, CCH);
    GEMM_TC(p_tn, p_wt, nullptr, p_q, MTOK, CCH, CCH, 0);
    TW(wk2, p_wt,           CTXD, CCH);
    TW(wv2, p_wt + 640*768, CTXD, CCH);
    GEMM_TC(context, p_wt, nullptr, p_kv, BATCH*CTX, 1280, CTXD, 0);
    flash_attn_mma_kernel<<<dim3(HW/FTQ, BATCH*HEADS), 256, FLASH_SMEM>>>(
        p_q, p_kv, p_kv + 640, p_ao, CTX, CCH, 1280, (size_t)CTX*1280, CCH);
    TW(wo2, p_wt, CCH, CCH);
    GEMM_TC(p_ao, p_wt, bo2, p_t, MTOK, CCH, CCH, 1);

    // 5) GEGLU FF (fused a*gelu(gate) GEMM -> g_ff directly; FFO on 128-kernel)
    layernorm_kernel<<<MTOK/8, 256>>>(p_t, ln3_g, ln3_b, p_tn);
    TW(w_geglu, p_wt, CCH, 2*FF);
    geglu_tc_kernel<<<dim3(FF/128, MTOK/256), 256, GEGLU_SMEM>>>(
        p_tn, p_wt, p_wt + (size_t)FF*CCH, b_geglu, p_ff, MTOK, CCH);
    TW(w_ffo, p_wt, FF, CCH);
    GEMM_TC(p_ff, p_wt, b_ffo, p_t, MTOK, CCH, FF, 1);

    // 6) proj_out fused with transpose + input residual (writes `out` directly)
    TW(w_out, p_wt, CCH, CCH);
    gemm_out_kernel<<<dim3(CCH/128, MTOK/128), 256, GEMM_SMEM>>>(
        p_t, p_wt, b_out, x, out, CCH);
}

// round 16
// speedup vs baseline: 1.1744x; 1.0768x over previous
#include <cuda_runtime.h>
#include <cuda_fp16.h>
#include <math.h>
#include <stdint.h>

// ---------------- problem constants ----------------
#define BATCH   8
#define CCH     640
#define HW      1024
#define MTOK    (BATCH*HW)
#define HEADS   8
#define DH      80
#define CTX     77
#define CTXD    768
#define FF      2560
#define GROUPS  32
#define CPG     (CCH/GROUPS)

// arch-feature gate: tcgen05 only exists in the sm_103a pass
#if defined(__CUDA_ARCH__) && (defined(__CUDA_ARCH_FEAT_SM103_ALL) || defined(__CUDA_ARCH_SPECIFIC__))
#define HAS_TCGEN05 1
#else
#define HAS_TCGEN05 0
#endif

// ---------------- scratch ----------------
__device__ float g_t   [MTOK*CCH];
__device__ float g_tn  [MTOK*CCH];
__device__ float g_q   [MTOK*CCH];
__device__ float g_ao  [MTOK*CCH];
__device__ float g_qkv [(size_t)MTOK*1920];
__device__ float g_kv  [BATCH*CTX*1280];
__device__ float g_ff  [(size_t)MTOK*FF];
__device__ float g_wt  [(size_t)5120*640];
__device__ float g_stats[BATCH*GROUPS*2];
__device__ __half g_qh [(size_t)MTOK*CCH];
__device__ __half g_kh [(size_t)MTOK*CCH];
__device__ __half g_vth[(size_t)64*80*1024];

// ================= common PTX helpers =================
__device__ __forceinline__ uint32_t smem_u32(const void* p) {
    uint32_t a;
    asm("{ .reg .u64 t; cvta.to.shared.u64 t, %1; cvt.u32.u64 %0, t; }" : "=r"(a) : "l"(p));
    return a;
}
__device__ __forceinline__ void cp_async16(void* smem_ptr, const void* gptr, bool pred)
{
    uint32_t saddr = smem_u32(smem_ptr);
    int sz = pred ? 16 : 0;
    asm volatile("cp.async.cg.shared.global [%0], [%1], 16, %2;\n"
                 :: "r"(saddr), "l"(gptr), "r"(sz));
}
__device__ __forceinline__ void cp_commit() { asm volatile("cp.async.commit_group;\n" ::: "memory"); }
__device__ __forceinline__ void cp_wait0()  { asm volatile("cp.async.wait_group 0;\n" ::: "memory"); }
__device__ __forceinline__ void cp_wait1()  { asm volatile("cp.async.wait_group 1;\n" ::: "memory"); }

__device__ __forceinline__ void mma_tf32(float& d0, float& d1, float& d2, float& d3,
                                         uint32_t a0, uint32_t a1, uint32_t a2, uint32_t a3,
                                         uint32_t b0, uint32_t b1)
{
    asm volatile(
        "mma.sync.aligned.m16n8k8.row.col.f32.tf32.tf32.f32 "
        "{%0,%1,%2,%3}, {%4,%5,%6,%7}, {%8,%9}, {%0,%1,%2,%3};\n"
        : "+f"(d0), "+f"(d1), "+f"(d2), "+f"(d3)
        : "r"(a0), "r"(a1), "r"(a2), "r"(a3), "r"(b0), "r"(b1));
}
__device__ __forceinline__ void mma_f16(float& d0, float& d1, float& d2, float& d3,
                                        uint32_t a0, uint32_t a1, uint32_t a2, uint32_t a3,
                                        uint32_t b0, uint32_t b1)
{
    asm volatile(
        "mma.sync.aligned.m16n8k16.row.col.f32.f16.f16.f32 "
        "{%0,%1,%2,%3}, {%4,%5,%6,%7}, {%8,%9}, {%0,%1,%2,%3};\n"
        : "+f"(d0), "+f"(d1), "+f"(d2), "+f"(d3)
        : "r"(a0), "r"(a1), "r"(a2), "r"(a3), "r"(b0), "r"(b1));
}

#if HAS_TCGEN05
__device__ __forceinline__ uint32_t elect_one() {
    uint32_t p;
    asm volatile("{\n\t.reg .pred p;\n\telect.sync _|p, 0xFFFFFFFF;\n\tselp.b32 %0, 1, 0, p;\n\t}" : "=r"(p));
    return p;
}
#define TCGEN05_ALLOC(smem_addr, nCols) \
    asm volatile("tcgen05.alloc.cta_group::1.sync.aligned.shared::cta.b32 [%0], %1;" \
                 :: "r"((uint32_t)(smem_addr)), "r"((uint32_t)(nCols)) : "memory")
#define TCGEN05_DEALLOC(tmem, nCols) \
    asm volatile("tcgen05.dealloc.cta_group::1.sync.aligned.b32 %0, %1;" :: "r"(tmem), "r"((uint32_t)(nCols)))
#define TCGEN05_RELINQ() \
    asm volatile("tcgen05.relinquish_alloc_permit.cta_group::1.sync.aligned;")
#define TCGEN05_COMMIT(mbar) \
    asm volatile("tcgen05.commit.cta_group::1.mbarrier::arrive::one.shared::cluster.b64 [%0];" \
                 :: "r"((uint32_t)(mbar)) : "memory")
#define TCGEN05_FENCE_AFTER() asm volatile("tcgen05.fence::after_thread_sync;" ::: "memory")
#define TCGEN05_WAIT_LD()     asm volatile("tcgen05.wait::ld.sync.aligned;" ::: "memory")
#define FENCE_ASYNC_SHARED()  asm volatile("fence.proxy.async.shared::cta;" ::: "memory")
#define MBARRIER_INIT(mbar, cnt) \
    asm volatile("mbarrier.init.shared.b64 [%0], %1;" :: "r"((uint32_t)(mbar)), "r"((uint32_t)(cnt)) : "memory")
#define MBARRIER_WAIT_PARITY(mbar, ph) do {                                           \
    uint32_t _m = (uint32_t)(mbar), _p = (uint32_t)(ph), _d;                          \
    asm volatile("{\n\t.reg .pred p;\n\t"                                             \
        "mbarrier.try_wait.parity.acquire.cta.shared::cta.b64 p, [%1], %2;\n\t"       \
        "selp.b32 %0, 1, 0, p;\n\t}" : "=r"(_d) : "r"(_m), "r"(_p) : "memory");       \
    if (!_d) {                                                                        \
        asm volatile("{\n\t.reg .pred P1;\n\t"                                        \
            "WL_%=:\n\t"                                                              \
            "mbarrier.try_wait.parity.acquire.cta.shared::cta.b64 P1, [%0], %1, 0x989680;\n\t" \
            "@P1 bra.uni WD_%=;\n\t"                                                  \
            "bra.uni WL_%=;\n\t"                                                      \
            "WD_%=:\n\t}" :: "r"(_m), "r"(_p) : "memory");                            \
    }                                                                                 \
} while (0)
#define TCGEN05_LD_X32(r, tmem)                                                        \
    asm volatile("tcgen05.ld.sync.aligned.32x32b.x32.b32 "                             \
        "{%0, %1, %2, %3, %4, %5, %6, %7, "                                            \
        " %8, %9, %10, %11, %12, %13, %14, %15, "                                      \
        " %16, %17, %18, %19, %20, %21, %22, %23, "                                    \
        " %24, %25, %26, %27, %28, %29, %30, %31}, [%32];"                             \
        : "=r"((r)[0]),  "=r"((r)[1]),  "=r"((r)[2]),  "=r"((r)[3]),                   \
          "=r"((r)[4]),  "=r"((r)[5]),  "=r"((r)[6]),  "=r"((r)[7]),                   \
          "=r"((r)[8]),  "=r"((r)[9]),  "=r"((r)[10]), "=r"((r)[11]),                  \
          "=r"((r)[12]), "=r"((r)[13]), "=r"((r)[14]), "=r"((r)[15]),                  \
          "=r"((r)[16]), "=r"((r)[17]), "=r"((r)[18]), "=r"((r)[19]),                  \
          "=r"((r)[20]), "=r"((r)[21]), "=r"((r)[22]), "=r"((r)[23]),                  \
          "=r"((r)[24]), "=r"((r)[25]), "=r"((r)[26]), "=r"((r)[27]),                  \
          "=r"((r)[28]), "=r"((r)[29]), "=r"((r)[30]), "=r"((r)[31])                   \
        : "r"(tmem))

__device__ __forceinline__ void tc_mma_tf32_ss(uint32_t d, uint64_t ad, uint64_t bd,
                                               uint32_t idesc, uint32_t en)
{
    asm volatile("{\n\t.reg .pred p;\n\tsetp.ne.u32 p, %4, 0;\n\t"
        "tcgen05.mma.cta_group::1.kind::tf32 [%0], %1, %2, %3, {%5,%5,%5,%5}, p;\n\t}"
        :: "r"(d), "l"(ad), "l"(bd), "r"(idesc), "r"(en), "r"(0u) : "memory");
}
__device__ __forceinline__ uint64_t make_desc(uint32_t saddr)
{
    return (uint64_t(2) << 61) | (uint64_t(1) << 46) | (uint64_t(64) << 32)
         | (uint64_t(1) << 16) | ((uint64_t)(saddr >> 4) & 0x3FFF);
}
#define TC_IDESC ((1u<<4)|(2u<<7)|(2u<<10)|((128u/8u)<<17)|((128u/16u)<<24))
#endif  // HAS_TCGEN05

// ================= GroupNorm =================
__global__ void gn_stats_kernel(const float* __restrict__ x, float* __restrict__ stats)
{
    int bg = blockIdx.x;
    int b = bg / GROUPS, g = bg % GROUPS;
    const float* base = x + (size_t)b*CCH*HW + (size_t)g*CPG*HW;
    int tid = threadIdx.x;
    float s = 0.f, ss = 0.f;
    for (int i = tid; i < CPG*HW; i += 256) { float v = base[i]; s += v; ss += v*v; }
    __shared__ float r1[256], r2[256];
    r1[tid] = s; r2[tid] = ss; __syncthreads();
    for (int st = 128; st > 0; st >>= 1) {
        if (tid < st) { r1[tid] += r1[tid+st]; r2[tid] += r2[tid+st]; }
        __syncthreads();
    }
    if (tid == 0) {
        const float inv = 1.f / (float)(CPG*HW);
        float mean = r1[0]*inv;
        float var  = r2[0]*inv - mean*mean;
        stats[bg*2]   = mean;
        stats[bg*2+1] = rsqrtf(var + 1e-6f);
    }
}

__global__ void gn_apply_kernel(const float* __restrict__ x,
                                const float* __restrict__ gamma,
                                const float* __restrict__ beta,
                                const float* __restrict__ stats,
                                float* __restrict__ out)
{
    __shared__ float tile[32][33];
    int b  = blockIdx.z;
    int c0 = blockIdx.y*32, hw0 = blockIdx.x*32;
    int tx = threadIdx.x, ty = threadIdx.y;
    #pragma unroll
    for (int i = 0; i < 32; i += 8) {
        int c = c0 + ty + i;
        int bg = b*GROUPS + c/CPG;
        float mean = stats[bg*2], rstd = stats[bg*2+1];
        float v = x[((size_t)b*CCH + c)*HW + hw0 + tx];
        tile[ty+i][tx] = (v - mean)*rstd*gamma[c] + beta[c];
    }
    __syncthreads();
    #pragma unroll
    for (int i = 0; i < 32; i += 8) {
        int hw = hw0 + ty + i;
        out[((size_t)b*HW + hw)*CCH + c0 + tx] = tile[tx][ty+i];
    }
}

// ================= weight transpose w[K][N] -> wt[N][K] =================
__global__ void transpose_w(const float* __restrict__ w, float* __restrict__ wt, int K, int N)
{
    __shared__ float t[32][33];
    int k0 = blockIdx.y*32, n0 = blockIdx.x*32;
    int tx = threadIdx.x, ty = threadIdx.y;
    #pragma unroll
    for (int i = 0; i < 32; i += 8)
        t[ty+i][tx] = w[(size_t)(k0+ty+i)*N + n0 + tx];
    __syncthreads();
    #pragma unroll
    for (int i = 0; i < 32; i += 8)
        wt[(size_t)(n0+ty+i)*K + k0 + tx] = t[tx][ty+i];
}

// ================= half conversion kernels =================
// dst[m][0..639] = half(src[m*srcStride + c] * scale)
__global__ void cvt_half_kernel(const float* __restrict__ src, int srcStride,
                                float scale, __half* __restrict__ dst, int M)
{
    size_t idx = (size_t)blockIdx.x*256 + threadIdx.x;
    if (idx >= (size_t)M*320) return;
    int m = (int)(idx / 320), c = (int)(idx % 320)*2;
    float2 v = *(const float2*)(src + (size_t)m*srcStride + c);
    __half2 h = __floats2half2_rn(v.x*scale, v.y*scale);
    *(__half2*)(dst + (size_t)m*CCH + c) = h;
}

// dst[(bh*80 + d)*Lpad + j] = half(src[(b*Lk + j)*srcStride + colOff + h*80 + d]); j>=Lk -> 0
__global__ void cvt_vt_kernel(const float* __restrict__ src, int srcStride, int colOff,
                              __half* __restrict__ dst, int Lk, int Lpad)
{
    __shared__ float tile[32][33];
    int bh = blockIdx.z;
    int b = bh >> 3, h = bh & 7;
    int j0 = blockIdx.x*32, d0 = blockIdx.y*32;
    int tx = threadIdx.x, ty = threadIdx.y;   // 32 x 8
    #pragma unroll
    for (int i = 0; i < 32; i += 8) {
        int j = j0 + ty + i, d = d0 + tx;
        float v = 0.f;
        if (j < Lk && d < DH)
            v = src[((size_t)b*Lk + j)*srcStride + colOff + h*DH + d];
        tile[ty+i][tx] = v;
    }
    __syncthreads();
    #pragma unroll
    for (int i = 0; i < 32; i += 8) {
        int d = d0 + ty + i, j = j0 + tx;
        if (d < DH)
            dst[((size_t)(bh*DH + d))*Lpad + j] = __float2half(tile[tx][ty+i]);
    }
}

// ================= GEMM 128x128 (proven): C = A @ Bt^T (+bias)(+=) =====
#define TCG_STAGE 65536
#define TCG_CTRL  (3*TCG_STAGE)
#define GEMM_SMEM (3*TCG_STAGE + 64)

__global__ __launch_bounds__(256, 1)
void gemm_tc_kernel(const float* __restrict__ A, const float* __restrict__ Bt,
                    const float* __restrict__ bias, float* __restrict__ C,
                    int M, int N, int K, int accumulate)
{
    extern __shared__ float smem[];
    int tid = threadIdx.x, lane = tid & 31;
    int m0 = blockIdx.y * 128, n0 = blockIdx.x * 128;

#if HAS_TCGEN05
    char* sbase = (char*)smem;
    uint32_t sb = smem_u32(smem);
    int w = tid >> 5;
    int rows_valid = M - m0; if (rows_valid > 128) rows_valid = 128;

    if (w == 0) {
        TCGEN05_ALLOC(sb + TCG_CTRL + 24, 128);
        TCGEN05_RELINQ();
    }
    if (tid == 0) {
        #pragma unroll
        for (int s = 0; s < 3; s++) MBARRIER_INIT(sb + TCG_CTRL + s*8, 1);
    }
    __syncthreads();
    uint32_t tmem;
    asm volatile("ld.shared.b32 %0, [%1];" : "=r"(tmem) : "r"(sb + TCG_CTRL + 24));

    const float* Ab = A  + (size_t)m0*K;
    const float* Bb = Bt + (size_t)n0*K;
    int r_ld = tid >> 3, c_ld = tid & 7;

    auto load_tiles = [&](int slot, int k0) {
        char* st = sbase + slot*TCG_STAGE;
        #pragma unroll
        for (int p = 0; p < 4; p++) {
            int r = r_ld + p*32;
            uint32_t off = (uint32_t)(r*128 + c_ld*16);
            off ^= ((off >> 3) & 0x70);
            int gr = (r < rows_valid) ? r : (rows_valid - 1);
            const float* arow = Ab + (size_t)gr*K + k0 + c_ld*4;
            const float* brow = Bb + (size_t)r*K  + k0 + c_ld*4;
            bool ap = (r < rows_valid);
            cp_async16(st + off,         arow,      ap);
            cp_async16(st + 16384 + off, arow + 32, ap);
            cp_async16(st + 32768 + off, brow,      true);
            cp_async16(st + 49152 + off, brow + 32, true);
        }
    };

    int nk = K / 64;
    uint32_t ph = 0;
    load_tiles(0, 0);   cp_commit();
    load_tiles(1, 64);  cp_commit();

    for (int it = 0; it < nk; it++) {
        int slot = it % 3;
        int rem = nk - 1 - it;
        if (rem >= 1) cp_wait1(); else cp_wait0();
        __syncthreads();
        FENCE_ASYNC_SHARED();

        if (w == 0 && elect_one()) {
            uint32_t stb = sb + slot*TCG_STAGE;
            #pragma unroll
            for (int s = 0; s < 8; s++) {
                uint64_t ad = make_desc(stb + (s >> 2)*16384)         + (uint64_t)(s & 3)*2;
                uint64_t bd = make_desc(stb + 32768 + (s >> 2)*16384) + (uint64_t)(s & 3)*2;
                tc_mma_tf32_ss(tmem, ad, bd, TC_IDESC, (it > 0 || s > 0));
            }
            TCGEN05_COMMIT(sb + TCG_CTRL + slot*8);
        }

        int j = it + 2;
        if (j < nk) {
            int ns = j % 3;
            if (j >= 3) {
                MBARRIER_WAIT_PARITY(sb + TCG_CTRL + ns*8, (ph >> ns) & 1);
                ph ^= (1u << ns);
            }
            load_tiles(ns, j*64);
            cp_commit();
        }
    }
    {
        int sl = (nk - 1) % 3;
        MBARRIER_WAIT_PARITY(sb + TCG_CTRL + sl*8, (ph >> sl) & 1);
    }
    TCGEN05_FENCE_AFTER();
    __syncthreads();

    float* tile = smem;
    {
        int subp = w & 3, half = w >> 2;
        int erow = subp*32 + lane;
        uint32_t ra[32], rb[32];
        TCGEN05_LD_X32(ra, tmem + half*64);
        TCGEN05_LD_X32(rb, tmem + half*64 + 32);
        TCGEN05_WAIT_LD();
        float* dst = tile + (size_t)erow*129 + half*64;
        #pragma unroll
        for (int c = 0; c < 32; c++) {
            dst[c]      = __uint_as_float(ra[c]);
            dst[32 + c] = __uint_as_float(rb[c]);
        }
    }
    __syncthreads();
    {
        float4 bv = make_float4(0.f, 0.f, 0.f, 0.f);
        if (bias) bv = *(const float4*)(bias + n0 + lane*4);
        #pragma unroll
        for (int p = 0; p < 16; p++) {
            int r = p*8 + w;
            int gm = m0 + r;
            if (gm < M) {
                const float* src = tile + (size_t)r*129 + lane*4;
                float4 v = make_float4(src[0]+bv.x, src[1]+bv.y, src[2]+bv.z, src[3]+bv.w);
                float4* op = (float4*)(C + (size_t)gm*N + n0 + lane*4);
                if (accumulate) {
                    float4 o = *op;
                    v.x += o.x; v.y += o.y; v.z += o.z; v.w += o.w;
                }
                *op = v;
            }
        }
    }
    if (w == 0) TCGEN05_DEALLOC(tmem, 128);

#else
    // mma.sync fallback — PTX pass only
    float* Abuf = smem;
    float* Bbuf = smem + 2*(128*36);
    int warp = tid >> 5;
    int wm = warp & 1, wn = warp >> 1;
    int grp = lane >> 2, tg = lane & 3;

    float acc[4][4][4];
    #pragma unroll
    for (int mi = 0; mi < 4; mi++)
        #pragma unroll
        for (int ni = 0; ni < 4; ni++)
            #pragma unroll
            for (int r = 0; r < 4; r++) acc[mi][ni][r] = 0.f;

    int r_ld = tid >> 3, c_ld = tid & 7;
    auto load_tile = [&](int buf, int k0) {
        float* as = Abuf + buf*(128*36);
        float* bs = Bbuf + buf*(128*36);
        #pragma unroll
        for (int p = 0; p < 4; p++) {
            int r = r_ld + p*32;
            int gm = m0 + r;
            int gmc = (gm < M) ? gm : (M-1);
            cp_async16(as + r*36 + c_ld*4, A  + (size_t)gmc*K + k0 + c_ld*4, gm < M);
            cp_async16(bs + r*36 + c_ld*4, Bt + (size_t)(n0+r)*K + k0 + c_ld*4, true);
        }
    };

    int nk = K / 32;
    load_tile(0, 0);
    cp_commit();
    for (int it = 0; it < nk; it++) {
        int buf = it & 1;
        cp_wait0();
        __syncthreads();
        if (it + 1 < nk) { load_tile(buf^1, (it+1)*32); cp_commit(); }

        float* as = Abuf + buf*(128*36);
        float* bs = Bbuf + buf*(128*36);
        #pragma unroll
        for (int kk = 0; kk < 32; kk += 8) {
            uint32_t af[4][4], bf[4][2];
            #pragma unroll
            for (int mi = 0; mi < 4; mi++) {
                int m = wm*64 + mi*16 + grp;
                af[mi][0] = __float_as_uint(as[m*36 + kk + tg]);
                af[mi][1] = __float_as_uint(as[(m+8)*36 + kk + tg]);
                af[mi][2] = __float_as_uint(as[m*36 + kk + tg + 4]);
                af[mi][3] = __float_as_uint(as[(m+8)*36 + kk + tg + 4]);
            }
            #pragma unroll
            for (int ni = 0; ni < 4; ni++) {
                int n = wn*32 + ni*8 + grp;
                bf[ni][0] = __float_as_uint(bs[n*36 + kk + tg]);
                bf[ni][1] = __float_as_uint(bs[n*36 + kk + tg + 4]);
            }
            #pragma unroll
            for (int mi = 0; mi < 4; mi++)
                #pragma unroll
                for (int ni = 0; ni < 4; ni++)
                    mma_tf32(acc[mi][ni][0], acc[mi][ni][1], acc[mi][ni][2], acc[mi][ni][3],
                             af[mi][0], af[mi][1], af[mi][2], af[mi][3],
                             bf[ni][0], bf[ni][1]);
        }
    }

    #pragma unroll
    for (int mi = 0; mi < 4; mi++) {
        int r0 = m0 + wm*64 + mi*16 + grp;
        #pragma unroll
        for (int ni = 0; ni < 4; ni++) {
            int c0 = n0 + wn*32 + ni*8 + tg*2;
            float bv0 = bias ? bias[c0]   : 0.f;
            float bv1 = bias ? bias[c0+1] : 0.f;
            if (r0 < M) {
                size_t o = (size_t)r0*N + c0;
                float v0 = acc[mi][ni][0] + bv0;
                float v1 = acc[mi][ni][1] + bv1;
                if (accumulate) { C[o] += v0; C[o+1] += v1; }
                else            { C[o]  = v0; C[o+1]  = v1; }
            }
            if (r0 + 8 < M) {
                size_t o = (size_t)(r0+8)*N + c0;
                float v2 = acc[mi][ni][2] + bv0;
                float v3 = acc[mi][ni][3] + bv1;
                if (accumulate) { C[o] += v2; C[o+1] += v3; }
                else            { C[o]  = v2; C[o+1]  = v3; }
            }
        }
    }
#endif
}

// ================= GEMM 128x128 with fused transpose+residual output ========
__global__ __launch_bounds__(256, 1)
void gemm_out_kernel(const float* __restrict__ A, const float* __restrict__ Bt,
                     const float* __restrict__ bias, const float* __restrict__ x,
                     float* __restrict__ outp, int K)
{
    extern __shared__ float smem[];
    int tid = threadIdx.x, lane = tid & 31;
    int m0 = blockIdx.y * 128, n0 = blockIdx.x * 128;

#if HAS_TCGEN05
    char* sbase = (char*)smem;
    uint32_t sb = smem_u32(smem);
    int w = tid >> 5;

    if (w == 0) {
        TCGEN05_ALLOC(sb + TCG_CTRL + 24, 128);
        TCGEN05_RELINQ();
    }
    if (tid == 0) {
        #pragma unroll
        for (int s = 0; s < 3; s++) MBARRIER_INIT(sb + TCG_CTRL + s*8, 1);
    }
    __syncthreads();
    uint32_t tmem;
    asm volatile("ld.shared.b32 %0, [%1];" : "=r"(tmem) : "r"(sb + TCG_CTRL + 24));

    const float* Ab = A  + (size_t)m0*K;
    const float* Bb = Bt + (size_t)n0*K;
    int r_ld = tid >> 3, c_ld = tid & 7;

    auto load_tiles = [&](int slot, int k0) {
        char* st = sbase + slot*TCG_STAGE;
        #pragma unroll
        for (int p = 0; p < 4; p++) {
            int r = r_ld + p*32;
            uint32_t off = (uint32_t)(r*128 + c_ld*16);
            off ^= ((off >> 3) & 0x70);
            const float* arow = Ab + (size_t)r*K + k0 + c_ld*4;
            const float* brow = Bb + (size_t)r*K + k0 + c_ld*4;
            cp_async16(st + off,         arow,      true);
            cp_async16(st + 16384 + off, arow + 32, true);
            cp_async16(st + 32768 + off, brow,      true);
            cp_async16(st + 49152 + off, brow + 32, true);
        }
    };

    int nk = K / 64;
    uint32_t ph = 0;
    load_tiles(0, 0);   cp_commit();
    load_tiles(1, 64);  cp_commit();

    for (int it = 0; it < nk; it++) {
        int slot = it % 3;
        int rem = nk - 1 - it;
        if (rem >= 1) cp_wait1(); else cp_wait0();
        __syncthreads();
        FENCE_ASYNC_SHARED();

        if (w == 0 && elect_one()) {
            uint32_t stb = sb + slot*TCG_STAGE;
            #pragma unroll
            for (int s = 0; s < 8; s++) {
                uint64_t ad = make_desc(stb + (s >> 2)*16384)         + (uint64_t)(s & 3)*2;
                uint64_t bd = make_desc(stb + 32768 + (s >> 2)*16384) + (uint64_t)(s & 3)*2;
                tc_mma_tf32_ss(tmem, ad, bd, TC_IDESC, (it > 0 || s > 0));
            }
            TCGEN05_COMMIT(sb + TCG_CTRL + slot*8);
        }

        int j = it + 2;
        if (j < nk) {
            int ns = j % 3;
            if (j >= 3) {
                MBARRIER_WAIT_PARITY(sb + TCG_CTRL + ns*8, (ph >> ns) & 1);
                ph ^= (1u << ns);
            }
            load_tiles(ns, j*64);
            cp_commit();
        }
    }
    {
        int sl = (nk - 1) % 3;
        MBARRIER_WAIT_PARITY(sb + TCG_CTRL + sl*8, (ph >> sl) & 1);
    }
    TCGEN05_FENCE_AFTER();
    __syncthreads();

    float* tile = smem;
    {
        int subp = w & 3, half = w >> 2;
        int erow = subp*32 + lane;
        uint32_t ra[32], rb[32];
        TCGEN05_LD_X32(ra, tmem + half*64);
        TCGEN05_LD_X32(rb, tmem + half*64 + 32);
        TCGEN05_WAIT_LD();
        float* dst = tile + (size_t)erow*129 + half*64;
        #pragma unroll
        for (int c = 0; c < 32; c++) {
            dst[c]      = __uint_as_float(ra[c]);
            dst[32 + c] = __uint_as_float(rb[c]);
        }
    }
    __syncthreads();

    {
        int b   = m0 >> 10;
        int hw0 = m0 & 1023;
        #pragma unroll
        for (int i = 0; i < 16; i++) {
            int cc = w*16 + i;
            int gc = n0 + cc;
            float bv = __ldg(bias + gc);
            size_t gbase = ((size_t)(b*CCH + gc))*HW + hw0 + lane*4;
            float4 xv = *(const float4*)(x + gbase);
            const float* src = tile + (size_t)(lane*4)*129 + cc;
            float4 v;
            v.x = src[0]     + bv + xv.x;
            v.y = src[129]   + bv + xv.y;
            v.z = src[258]   + bv + xv.z;
            v.w = src[387]   + bv + xv.w;
            *(float4*)(outp + gbase) = v;
        }
    }
    if (w == 0) TCGEN05_DEALLOC(tmem, 128);

#else
    for (int idx = tid; idx < 128*128; idx += 256) {
        int r = idx >> 7, c = idx & 127;
        int gm = m0 + r;
        int gc = n0 + c;
        float s = bias[gc];
        for (int k = 0; k < K; k++)
            s += A[(size_t)gm*K + k] * Bt[(size_t)gc*K + k];
        int b = gm / HW, hw = gm % HW;
        size_t o = ((size_t)(b*CCH + gc))*HW + hw;
        outp[o] = s + x[o];
    }
#endif
}

// ================= GEMM 256x128 (BM=256, K64 stages, 2-stage) ===============
#define T256_STAGE 98304
#define T256_CTRL  (2*T256_STAGE)
#define GEMM256_SMEM (2*T256_STAGE + 64)

__global__ __launch_bounds__(256, 1)
void gemm_tc256_kernel(const float* __restrict__ A, const float* __restrict__ Bt,
                       const float* __restrict__ bias, float* __restrict__ C,
                       int M, int N, int K, int accumulate)
{
    extern __shared__ float smem[];
    int tid = threadIdx.x, lane = tid & 31;
    int m0 = blockIdx.y * 256, n0 = blockIdx.x * 128;

#if HAS_TCGEN05
    char* sbase = (char*)smem;
    uint32_t sb = smem_u32(smem);
    int w = tid >> 5;

    if (w == 0) {
        TCGEN05_ALLOC(sb + T256_CTRL + 16, 256);
        TCGEN05_RELINQ();
    }
    if (tid == 0) {
        MBARRIER_INIT(sb + T256_CTRL,     1);
        MBARRIER_INIT(sb + T256_CTRL + 8, 1);
    }
    __syncthreads();
    uint32_t tmem;
    asm volatile("ld.shared.b32 %0, [%1];" : "=r"(tmem) : "r"(sb + T256_CTRL + 16));

    const float* Ab = A  + (size_t)m0*K;
    const float* Bb = Bt + (size_t)n0*K;
    int r_ld = tid >> 3, c_ld = tid & 7;

    auto load_tiles = [&](int slot, int k0) {
        char* st = sbase + slot*T256_STAGE;
        #pragma unroll
        for (int p = 0; p < 8; p++) {
            int r = r_ld + p*32;
            int half = r >> 7, rr = r & 127;
            uint32_t off = (uint32_t)(rr*128 + c_ld*16);
            off ^= ((off >> 3) & 0x70);
            const float* arow = Ab + (size_t)r*K + k0 + c_ld*4;
            cp_async16(st + half*32768 + off,         arow,      true);
            cp_async16(st + half*32768 + 16384 + off, arow + 32, true);
        }
        #pragma unroll
        for (int p = 0; p < 4; p++) {
            int r = r_ld + p*32;
            uint32_t off = (uint32_t)(r*128 + c_ld*16);
            off ^= ((off >> 3) & 0x70);
            const float* brow = Bb + (size_t)r*K + k0 + c_ld*4;
            cp_async16(st + 65536 + off, brow,      true);
            cp_async16(st + 81920 + off, brow + 32, true);
        }
    };

    int nk = K / 64;
    uint32_t ph = 0;
    load_tiles(0, 0);   cp_commit();
    if (nk > 1) { load_tiles(1, 64); cp_commit(); }

    for (int it = 0; it < nk; it++) {
        int slot = it & 1;
        int rem = nk - 1 - it;
        if (rem >= 1) cp_wait1(); else cp_wait0();
        __syncthreads();
        FENCE_ASYNC_SHARED();

        if (w == 0 && elect_one()) {
            uint32_t stb = sb + slot*T256_STAGE;
            #pragma unroll
            for (int s = 0; s < 8; s++) {
                int kb = s >> 2;
                uint64_t step = (uint64_t)(s & 3)*2;
                uint64_t ad0 = make_desc(stb + kb*16384)         + step;
                uint64_t ad1 = make_desc(stb + 32768 + kb*16384) + step;
                uint64_t bd  = make_desc(stb + 65536 + kb*16384) + step;
                uint32_t en = (it > 0 || s > 0);
                tc_mma_tf32_ss(tmem,       ad0, bd, TC_IDESC, en);
                tc_mma_tf32_ss(tmem + 128, ad1, bd, TC_IDESC, en);
            }
            TCGEN05_COMMIT(sb + T256_CTRL + slot*8);
        }

        int j = it + 2;
        if (j < nk) {
            int ns = j & 1;
            MBARRIER_WAIT_PARITY(sb + T256_CTRL + ns*8, (ph >> ns) & 1);
            ph ^= (1u << ns);
            load_tiles(ns, j*64);
            cp_commit();
        }
    }
    {
        int sl = (nk - 1) & 1;
        MBARRIER_WAIT_PARITY(sb + T256_CTRL + sl*8, (ph >> sl) & 1);
    }
    TCGEN05_FENCE_AFTER();
    __syncthreads();

    float* tile = smem;
    float4 bv = make_float4(0.f, 0.f, 0.f, 0.f);
    if (bias) bv = *(const float4*)(bias + n0 + lane*4);

    for (int acc = 0; acc < 2; acc++) {
        {
            int subp = w & 3, half = w >> 2;
            int erow = subp*32 + lane;
            uint32_t ra[32], rb[32];
            TCGEN05_LD_X32(ra, tmem + acc*128 + half*64);
            TCGEN05_LD_X32(rb, tmem + acc*128 + half*64 + 32);
            TCGEN05_WAIT_LD();
            float* dst = tile + (size_t)erow*129 + half*64;
            #pragma unroll
            for (int c = 0; c < 32; c++) {
                dst[c]      = __uint_as_float(ra[c]);
                dst[32 + c] = __uint_as_float(rb[c]);
            }
        }
        __syncthreads();
        #pragma unroll
        for (int p = 0; p < 16; p++) {
            int r = p*8 + w;
            int gm = m0 + acc*128 + r;
            const float* src = tile + (size_t)r*129 + lane*4;
            float4 v = make_float4(src[0]+bv.x, src[1]+bv.y, src[2]+bv.z, src[3]+bv.w);
            float4* op = (float4*)(C + (size_t)gm*N + n0 + lane*4);
            if (accumulate) {
                float4 o = *op;
                v.x += o.x; v.y += o.y; v.z += o.z; v.w += o.w;
            }
            *op = v;
        }
        __syncthreads();
    }
    if (w == 0) TCGEN05_DEALLOC(tmem, 256);

#else
    for (int idx = tid; idx < 256*128; idx += 256) {
        int r = idx >> 7, c = idx & 127;
        float s = bias ? bias[n0 + c] : 0.f;
        for (int k = 0; k < K; k++)
            s += A[(size_t)(m0 + r)*K + k] * Bt[(size_t)(n0 + c)*K + k];
        size_t o = (size_t)(m0 + r)*N + n0 + c;
        if (accumulate) C[o] += s; else C[o] = s;
    }
#endif
}

// ================= fused GEGLU GEMM: ff = a * gelu(gate) ====================
#define GG_STAGE 65536
#define GG_CTRL  (3*GG_STAGE)
#define GEGLU_SMEM (3*GG_STAGE + 64)

__global__ __launch_bounds__(256, 1)
void geglu_tc_kernel(const float* __restrict__ A, const float* __restrict__ Bta,
                     const float* __restrict__ Btg, const float* __restrict__ bias,
                     float* __restrict__ FFo, int M, int K)
{
    extern __shared__ float smem[];
    int tid = threadIdx.x, lane = tid & 31;
    int m0 = blockIdx.y * 256, n0 = blockIdx.x * 128;

#if HAS_TCGEN05
    char* sbase = (char*)smem;
    uint32_t sb = smem_u32(smem);
    int w = tid >> 5;

    if (w == 0) {
        TCGEN05_ALLOC(sb + GG_CTRL + 24, 512);
        TCGEN05_RELINQ();
    }
    if (tid == 0) {
        #pragma unroll
        for (int s = 0; s < 3; s++) MBARRIER_INIT(sb + GG_CTRL + s*8, 1);
    }
    __syncthreads();
    uint32_t tmem;
    asm volatile("ld.shared.b32 %0, [%1];" : "=r"(tmem) : "r"(sb + GG_CTRL + 24));

    const float* Ab  = A   + (size_t)m0*K;
    const float* Bab = Bta + (size_t)n0*K;
    const float* Bgb = Btg + (size_t)n0*K;
    int r_ld = tid >> 3, c_ld = tid & 7;

    auto load_tiles = [&](int slot, int k0) {
        char* st = sbase + slot*GG_STAGE;
        #pragma unroll
        for (int p = 0; p < 8; p++) {
            int r = r_ld + p*32;
            int blk = r >> 7, rr = r & 127;
            uint32_t off = (uint32_t)(rr*128 + c_ld*16);
            off ^= ((off >> 3) & 0x70);
            cp_async16(st + blk*16384 + off, Ab + (size_t)r*K + k0 + c_ld*4, true);
        }
        #pragma unroll
        for (int p = 0; p < 4; p++) {
            int r = r_ld + p*32;
            uint32_t off = (uint32_t)(r*128 + c_ld*16);
            off ^= ((off >> 3) & 0x70);
            cp_async16(st + 32768 + off, Bab + (size_t)r*K + k0 + c_ld*4, true);
            cp_async16(st + 49152 + off, Bgb + (size_t)r*K + k0 + c_ld*4, true);
        }
    };

    int nk = K / 32;
    uint32_t ph = 0;
    load_tiles(0, 0);   cp_commit();
    load_tiles(1, 32);  cp_commit();

    for (int it = 0; it < nk; it++) {
        int slot = it % 3;
        int rem = nk - 1 - it;
        if (rem >= 1) cp_wait1(); else cp_wait0();
        __syncthreads();
        FENCE_ASYNC_SHARED();

        if (w == 0 && elect_one()) {
            uint32_t stb = sb + slot*GG_STAGE;
            #pragma unroll
            for (int s = 0; s < 4; s++) {
                uint64_t ad0 = make_desc(stb)          + (uint64_t)s*2;
                uint64_t ad1 = make_desc(stb + 16384)  + (uint64_t)s*2;
                uint64_t bad = make_desc(stb + 32768)  + (uint64_t)s*2;
                uint64_t bgd = make_desc(stb + 49152)  + (uint64_t)s*2;
                uint32_t en = (it > 0 || s > 0);
                tc_mma_tf32_ss(tmem,       ad0, bad, TC_IDESC, en);
                tc_mma_tf32_ss(tmem + 128, ad1, bad, TC_IDESC, en);
                tc_mma_tf32_ss(tmem + 256, ad0, bgd, TC_IDESC, en);
                tc_mma_tf32_ss(tmem + 384, ad1, bgd, TC_IDESC, en);
            }
            TCGEN05_COMMIT(sb + GG_CTRL + slot*8);
        }

        int j = it + 2;
        if (j < nk) {
            int ns = j % 3;
            if (j >= 3) {
                MBARRIER_WAIT_PARITY(sb + GG_CTRL + ns*8, (ph >> ns) & 1);
                ph ^= (1u << ns);
            }
            load_tiles(ns, j*32);
            cp_commit();
        }
    }
    {
        int sl = (nk - 1) % 3;
        MBARRIER_WAIT_PARITY(sb + GG_CTRL + sl*8, (ph >> sl) & 1);
    }
    TCGEN05_FENCE_AFTER();
    __syncthreads();

    float* tile = smem;
    const float inv_sqrt2 = 0.70710678118654752f;

    for (int h = 0; h < 2; h++) {
        {
            int subp = w & 3, ch = w >> 2;
            int erow = subp*32 + lane;
            float* dst = tile + (size_t)erow*129 + ch*64;
            #pragma unroll
            for (int cc = 0; cc < 2; cc++) {
                uint32_t ra[32], rg[32];
                TCGEN05_LD_X32(ra, tmem + h*128 + ch*64 + cc*32);
                TCGEN05_LD_X32(rg, tmem + 256 + h*128 + ch*64 + cc*32);
                TCGEN05_WAIT_LD();
                #pragma unroll
                for (int c = 0; c < 32; c++) {
                    int col = ch*64 + cc*32 + c;
                    float av = __uint_as_float(ra[c]) + __ldg(bias + n0 + col);
                    float gv = __uint_as_float(rg[c]) + __ldg(bias + FF + n0 + col);
                    float gel = 0.5f*gv*(1.f + erff(gv*inv_sqrt2));
                    dst[cc*32 + c] = av * gel;
                }
            }
        }
        __syncthreads();
        #pragma unroll
        for (int p = 0; p < 16; p++) {
            int r = p*8 + w;
            int gm = m0 + h*128 + r;
            const float* src = tile + (size_t)r*129 + lane*4;
            *(float4*)(FFo + (size_t)gm*FF + n0 + lane*4) =
                make_float4(src[0], src[1], src[2], src[3]);
        }
        __syncthreads();
    }
    if (w == 0) TCGEN05_DEALLOC(tmem, 512);

#else
    for (int idx = tid; idx < 256*128; idx += 256) {
        int r = idx >> 7, c = idx & 127;
        float sa = bias[n0 + c], sg = bias[FF + n0 + c];
        for (int k = 0; k < K; k++) {
            float av = A[(size_t)(m0 + r)*K + k];
            sa += av * Bta[(size_t)(n0 + c)*K + k];
            sg += av * Btg[(size_t)(n0 + c)*K + k];
        }
        float gel = 0.5f*sg*(1.f + erff(sg*0.70710678118654752f));
        FFo[(size_t)(m0 + r)*FF + n0 + c] = sa * gel;
    }
#endif
}

// ================= LayerNorm (warp per row) =================
__global__ void layernorm_kernel(const float* __restrict__ in,
                                 const float* __restrict__ g,
                                 const float* __restrict__ bta,
                                 float* __restrict__ out)
{
    int w = threadIdx.x >> 5, lane = threadIdx.x & 31;
    size_t row = (size_t)blockIdx.x*8 + w;
    const float4* p = (const float4*)(in + row*CCH);
    float4 v[5];
    float s = 0.f, ss = 0.f;
    #pragma unroll
    for (int i = 0; i < 5; i++) {
        v[i] = p[lane + 32*i];
        s  += v[i].x + v[i].y + v[i].z + v[i].w;
        ss += v[i].x*v[i].x + v[i].y*v[i].y + v[i].z*v[i].z + v[i].w*v[i].w;
    }
    #pragma unroll
    for (int o = 16; o >= 1; o >>= 1) {
        s  += __shfl_xor_sync(0xffffffffu, s, o);
        ss += __shfl_xor_sync(0xffffffffu, ss, o);
    }
    float mean = s * (1.f/CCH);
    float rstd = rsqrtf(ss * (1.f/CCH) - mean*mean + 1e-5f);
    const float4* g4 = (const float4*)g;
    const float4* b4 = (const float4*)bta;
    float4* o4 = (float4*)(out + row*CCH);
    #pragma unroll
    for (int i = 0; i < 5; i++) {
        float4 gg = g4[lane + 32*i], bb = b4[lane + 32*i];
        float4 r;
        r.x = (v[i].x - mean)*rstd*gg.x + bb.x;
        r.y = (v[i].y - mean)*rstd*gg.y + bb.y;
        r.z = (v[i].z - mean)*rstd*gg.z + bb.z;
        r.w = (v[i].w - mean)*rstd*gg.w + bb.w;
        o4[lane + 32*i] = r;
    }
}

// ============ flash attention (fp16 m16n8k16 mma, double-buffered KV) =======
// Q: half [M][640] pre-scaled; K: half [b][Lk][640]; Vt: half [bh][80][Lpad].
#define FTQ 128
#define FTJ 64
#define AQ_STR 88
#define AK_STR 88
#define AV_STR 72
#define AP_STR 72
#define AKV_BUF (FTJ*AK_STR + DH*AV_STR)
#define FLASH_SMEM ((FTQ*AQ_STR + 2*AKV_BUF) * (int)sizeof(__half))

__global__ __launch_bounds__(256, 1)
void flash_attn_f16_kernel(const __half* __restrict__ Q, const __half* __restrict__ K,
                           const __half* __restrict__ Vt, float* __restrict__ O,
                           int Lk, int Lpad)
{
    extern __shared__ __half smh[];
    __half* QPs = smh;                       // Qs[128][88] then reused as Ps[128][72]
    __half* KV0 = smh + FTQ*AQ_STR;

    int tid = threadIdx.x, lane = tid & 31, w = tid >> 5;
    int qr = lane >> 2, qc = lane & 3;       // grp, tg
    int bh = blockIdx.y;
    int b = bh / HEADS, h = bh % HEADS;
    int i0 = blockIdx.x * FTQ;

    const __half* qb  = Q  + ((size_t)(b*HW) + i0)*CCH + h*DH;
    const __half* kb  = K  + (size_t)b*Lk*CCH + h*DH;
    const __half* vtb = Vt + (size_t)bh*DH*Lpad;

    int kv_r = tid >> 2, kv_c = tid & 3;
    auto load_kv = [&](int buf, int j0) {
        __half* Ks = KV0 + buf*AKV_BUF;
        __half* Vs = Ks + FTJ*AK_STR;
        {
            int gj = j0 + kv_r;
            int gjc = (gj < Lk) ? gj : (Lk - 1);
            const __half* src = kb + (size_t)gjc*CCH;
            for (int c = kv_c; c < 10; c += 4)
                cp_async16(Ks + kv_r*AK_STR + c*8, src + c*8, true);
        }
        for (int d = kv_r; d < DH; d += 64) {
            const __half* src = vtb + (size_t)d*Lpad + j0;
            for (int c = kv_c; c < 8; c += 4)
                cp_async16(Vs + d*AV_STR + c*8, src + c*8, true);
        }
    };

    load_kv(0, 0);
    cp_commit();
    // stage Q tile (half, coalesced 16B copies)
    for (int idx = tid; idx < FTQ*10; idx += 256) {
        int i = idx / 10, c = idx % 10;
        *(uint4*)(QPs + (size_t)i*AQ_STR + c*8) = *(const uint4*)(qb + (size_t)i*CCH + c*8);
    }
    __syncthreads();

    int r0 = w*16 + qr;
    uint32_t qf[5][4];
    #pragma unroll
    for (int kk = 0; kk < 5; kk++) {
        int d0 = kk*16 + 2*qc;
        qf[kk][0] = *(const uint32_t*)(QPs + (size_t)r0*AQ_STR + d0);
        qf[kk][1] = *(const uint32_t*)(QPs + (size_t)(r0+8)*AQ_STR + d0);
        qf[kk][2] = *(const uint32_t*)(QPs + (size_t)r0*AQ_STR + d0 + 8);
        qf[kk][3] = *(const uint32_t*)(QPs + (size_t)(r0+8)*AQ_STR + d0 + 8);
    }
    __syncthreads();   // QPs now reusable as Ps

    float m0v = -1e30f, m1v = -1e30f, l0 = 0.f, l1 = 0.f;
    float oacc[10][4];
    #pragma unroll
    for (int nt = 0; nt < 10; nt++)
        #pragma unroll
        for (int r = 0; r < 4; r++) oacc[nt][r] = 0.f;

    int nchunks = (Lk + FTJ - 1) / FTJ;
    for (int c = 0; c < nchunks; c++) {
        int buf = c & 1;
        if (c + 1 < nchunks) {
            load_kv(buf ^ 1, (c + 1)*FTJ);
            cp_commit();
            cp_wait1();
        } else {
            cp_wait0();
        }
        __syncthreads();

        __half* Ks = KV0 + buf*AKV_BUF;
        __half* Vs = Ks + FTJ*AK_STR;
        int j0 = c*FTJ;

        // ---- S = Q K^T : 5 k-blocks x 8 n-tiles of fp16 m16n8k16 ----
        float sc[8][4];
        #pragma unroll
        for (int nt = 0; nt < 8; nt++)
            #pragma unroll
            for (int r = 0; r < 4; r++) sc[nt][r] = 0.f;

        #pragma unroll
        for (int kk = 0; kk < 5; kk++) {
            int d0 = kk*16 + 2*qc;
            #pragma unroll
            for (int nt = 0; nt < 8; nt++) {
                int j = nt*8 + qr;
                uint32_t b0 = *(const uint32_t*)(Ks + (size_t)j*AK_STR + d0);
                uint32_t b1 = *(const uint32_t*)(Ks + (size_t)j*AK_STR + d0 + 8);
                mma_f16(sc[nt][0], sc[nt][1], sc[nt][2], sc[nt][3],
                        qf[kk][0], qf[kk][1], qf[kk][2], qf[kk][3], b0, b1);
            }
        }

        if (j0 + FTJ > Lk) {
            #pragma unroll
            for (int nt = 0; nt < 8; nt++) {
                int jc = j0 + nt*8 + qc*2;
                if (jc   >= Lk) { sc[nt][0] = -1e30f; sc[nt][2] = -1e30f; }
                if (jc+1 >= Lk) { sc[nt][1] = -1e30f; sc[nt][3] = -1e30f; }
            }
        }

        float mx0 = -1e30f, mx1 = -1e30f;
        #pragma unroll
        for (int nt = 0; nt < 8; nt++) {
            mx0 = fmaxf(mx0, fmaxf(sc[nt][0], sc[nt][1]));
            mx1 = fmaxf(mx1, fmaxf(sc[nt][2], sc[nt][3]));
        }
        mx0 = fmaxf(mx0, __shfl_xor_sync(0xffffffffu, mx0, 1));
        mx0 = fmaxf(mx0, __shfl_xor_sync(0xffffffffu, mx0, 2));
        mx1 = fmaxf(mx1, __shfl_xor_sync(0xffffffffu, mx1, 1));
        mx1 = fmaxf(mx1, __shfl_xor_sync(0xffffffffu, mx1, 2));

        float mn0 = fmaxf(m0v, mx0), mn1 = fmaxf(m1v, mx1);
        float al0 = __expf(m0v - mn0), al1 = __expf(m1v - mn1);
        float rs0 = 0.f, rs1 = 0.f;
        #pragma unroll
        for (int nt = 0; nt < 8; nt++) {
            sc[nt][0] = __expf(sc[nt][0] - mn0);
            sc[nt][1] = __expf(sc[nt][1] - mn0);
            sc[nt][2] = __expf(sc[nt][2] - mn1);
            sc[nt][3] = __expf(sc[nt][3] - mn1);
            rs0 += sc[nt][0] + sc[nt][1];
            rs1 += sc[nt][2] + sc[nt][3];
        }
        rs0 += __shfl_xor_sync(0xffffffffu, rs0, 1);
        rs0 += __shfl_xor_sync(0xffffffffu, rs0, 2);
        rs1 += __shfl_xor_sync(0xffffffffu, rs1, 1);
        rs1 += __shfl_xor_sync(0xffffffffu, rs1, 2);

        l0 = l0*al0 + rs0;  m0v = mn0;
        l1 = l1*al1 + rs1;  m1v = mn1;

        #pragma unroll
        for (int nt = 0; nt < 10; nt++) {
            oacc[nt][0] *= al0; oacc[nt][1] *= al0;
            oacc[nt][2] *= al1; oacc[nt][3] *= al1;
        }

        // ---- write P tile (half2) to per-warp Ps region ----
        __half* Ps = QPs;
        #pragma unroll
        for (int nt = 0; nt < 8; nt++) {
            int jc = nt*8 + qc*2;
            __half2 p01 = __floats2half2_rn(sc[nt][0], sc[nt][1]);
            __half2 p23 = __floats2half2_rn(sc[nt][2], sc[nt][3]);
            *(__half2*)(Ps + (size_t)r0*AP_STR + jc)     = p01;
            *(__half2*)(Ps + (size_t)(r0+8)*AP_STR + jc) = p23;
        }
        __syncwarp();

        // ---- O += P V : 4 j-blocks x 10 d-tiles ----
        #pragma unroll
        for (int kk = 0; kk < 4; kk++) {
            int jb = kk*16 + 2*qc;
            uint32_t a0 = *(const uint32_t*)(Ps + (size_t)r0*AP_STR + jb);
            uint32_t a1 = *(const uint32_t*)(Ps + (size_t)(r0+8)*AP_STR + jb);
            uint32_t a2 = *(const uint32_t*)(Ps + (size_t)r0*AP_STR + jb + 8);
            uint32_t a3 = *(const uint32_t*)(Ps + (size_t)(r0+8)*AP_STR + jb + 8);
            #pragma unroll
            for (int nt = 0; nt < 10; nt++) {
                int d = nt*8 + qr;
                uint32_t b0 = *(const uint32_t*)(Vs + (size_t)d*AV_STR + jb);
                uint32_t b1 = *(const uint32_t*)(Vs + (size_t)d*AV_STR + jb + 8);
                mma_f16(oacc[nt][0], oacc[nt][1], oacc[nt][2], oacc[nt][3],
                        a0, a1, a2, a3, b0, b1);
            }
        }
        __syncthreads();
    }

    float inv0 = 1.f / l0, inv1 = 1.f / l1;
    float* ob = O + ((size_t)(b*HW) + i0 + r0)*CCH + h*DH;
    #pragma unroll
    for (int nt = 0; nt < 10; nt++) {
        int dc = nt*8 + qc*2;
        *(float2*)(ob + dc)                  = make_float2(oacc[nt][0]*inv0, oacc[nt][1]*inv0);
        *(float2*)(ob + (size_t)8*CCH + dc)  = make_float2(oacc[nt][2]*inv1, oacc[nt][3]*inv1);
    }
}

extern "C" void kernel_launch(void* const* d_in, const int* in_sizes, int n_in,
                              void* d_out, int out_size)
{
    const float* x       = (const float*)d_in[0];
    const float* context = (const float*)d_in[1];
    const float* gn_g    = (const float*)d_in[2];
    const float* gn_b    = (const float*)d_in[3];
    const float* w_in    = (const float*)d_in[4];
    const float* b_in    = (const float*)d_in[5];
    const float* ln1_g   = (const float*)d_in[6];
    const float* ln1_b   = (const float*)d_in[7];
    const float* wq1     = (const float*)d_in[8];
    const float* wk1     = (const float*)d_in[9];
    const float* wv1     = (const float*)d_in[10];
    const float* wo1     = (const float*)d_in[11];
    const float* bo1     = (const float*)d_in[12];
    const float* ln2_g   = (const float*)d_in[13];
    const float* ln2_b   = (const float*)d_in[14];
    const float* wq2     = (const float*)d_in[15];
    const float* wk2     = (const float*)d_in[16];
    const float* wv2     = (const float*)d_in[17];
    const float* wo2     = (const float*)d_in[18];
    const float* bo2     = (const float*)d_in[19];
    const float* ln3_g   = (const float*)d_in[20];
    const float* ln3_b   = (const float*)d_in[21];
    const float* w_geglu = (const float*)d_in[22];
    const float* b_geglu = (const float*)d_in[23];
    const float* w_ffo   = (const float*)d_in[24];
    const float* b_ffo   = (const float*)d_in[25];
    const float* w_out   = (const float*)d_in[26];
    const float* b_out   = (const float*)d_in[27];
    float* out = (float*)d_out;

    float *p_t, *p_tn, *p_q, *p_ao, *p_qkv, *p_kv, *p_ff, *p_wt, *p_stats;
    __half *p_qh, *p_kh, *p_vth;
    cudaGetSymbolAddress((void**)&p_t,    g_t);
    cudaGetSymbolAddress((void**)&p_tn,   g_tn);
    cudaGetSymbolAddress((void**)&p_q,    g_q);
    cudaGetSymbolAddress((void**)&p_ao,   g_ao);
    cudaGetSymbolAddress((void**)&p_qkv,  g_qkv);
    cudaGetSymbolAddress((void**)&p_kv,   g_kv);
    cudaGetSymbolAddress((void**)&p_ff,   g_ff);
    cudaGetSymbolAddress((void**)&p_wt,   g_wt);
    cudaGetSymbolAddress((void**)&p_stats,g_stats);
    cudaGetSymbolAddress((void**)&p_qh,   g_qh);
    cudaGetSymbolAddress((void**)&p_kh,   g_kh);
    cudaGetSymbolAddress((void**)&p_vth,  g_vth);

    cudaFuncSetAttribute(flash_attn_f16_kernel,
                         cudaFuncAttributeMaxDynamicSharedMemorySize, FLASH_SMEM);
    cudaFuncSetAttribute(gemm_tc_kernel,
                         cudaFuncAttributeMaxDynamicSharedMemorySize, GEMM_SMEM);
    cudaFuncSetAttribute(gemm_out_kernel,
                         cudaFuncAttributeMaxDynamicSharedMemorySize, GEMM_SMEM);
    cudaFuncSetAttribute(gemm_tc256_kernel,
                         cudaFuncAttributeMaxDynamicSharedMemorySize, GEMM256_SMEM);
    cudaFuncSetAttribute(geglu_tc_kernel,
                         cudaFuncAttributeMaxDynamicSharedMemorySize, GEGLU_SMEM);

    dim3 tb(32, 8);
    dim3 tp_grid(HW/32, CCH/32, BATCH);
    const float qscale = 0.1118033988749895f;

    #define TW(w_, dst_, K_, N_) \
        transpose_w<<<dim3((N_)/32, (K_)/32), tb>>>(w_, dst_, K_, N_)
    #define GEMM_TC(A_, Bt_, bias_, C_, M_, N_, K_, acc_) \
        gemm_tc_kernel<<<dim3((N_)/128, ((M_)+127)/128), 256, GEMM_SMEM>>>( \
            A_, Bt_, bias_, C_, M_, N_, K_, acc_)

    // 1) GroupNorm -> token-major
    gn_stats_kernel<<<BATCH*GROUPS, 256>>>(x, p_stats);
    gn_apply_kernel<<<tp_grid, tb>>>(x, gn_g, gn_b, p_stats, p_tn);

    // 2) proj_in
    TW(w_in, p_wt, CCH, CCH);
    GEMM_TC(p_tn, p_wt, b_in, p_t, MTOK, CCH, CCH, 0);

    // 3) self-attention (packed QKV; fp16 flash)
    layernorm_kernel<<<MTOK/8, 256>>>(p_t, ln1_g, ln1_b, p_tn);
    TW(wq1, p_wt,             CCH, CCH);
    TW(wk1, p_wt + 640*640,   CCH, CCH);
    TW(wv1, p_wt + 2*640*640, CCH, CCH);
    gemm_tc256_kernel<<<dim3(1920/128, MTOK/256), 256, GEMM256_SMEM>>>(
        p_tn, p_wt, nullptr, p_qkv, MTOK, 1920, CCH, 0);
    cvt_half_kernel<<<(MTOK*320 + 255)/256, 256>>>(p_qkv,        1920, qscale, p_qh, MTOK);
    cvt_half_kernel<<<(MTOK*320 + 255)/256, 256>>>(p_qkv + 640,  1920, 1.0f,   p_kh, MTOK);
    cvt_vt_kernel<<<dim3(HW/32, 3, 64), tb>>>(p_qkv, 1920, 1280, p_vth, HW, HW);
    flash_attn_f16_kernel<<<dim3(HW/FTQ, BATCH*HEADS), 256, FLASH_SMEM>>>(
        p_qh, p_kh, p_vth, p_ao, HW, HW);
    TW(wo1, p_wt, CCH, CCH);
    GEMM_TC(p_ao, p_wt, bo1, p_t, MTOK, CCH, CCH, 1);

    // 4) cross-attention (fp16 flash)
    layernorm_kernel<<<MTOK/8, 256>>>(p_t, ln2_g, ln2_b, p_tn);
    TW(wq2, p_wt, CCH, CCH);
    GEMM_TC(p_tn, p_wt, nullptr, p_q, MTOK, CCH, CCH, 0);
    TW(wk2, p_wt,           CTXD, CCH);
    TW(wv2, p_wt + 640*768, CTXD, CCH);
    GEMM_TC(context, p_wt, nullptr, p_kv, BATCH*CTX, 1280, CTXD, 0);
    cvt_half_kernel<<<(MTOK*320 + 255)/256, 256>>>(p_q, 640, qscale, p_qh, MTOK);
    cvt_half_kernel<<<(BATCH*CTX*320 + 255)/256, 256>>>(p_kv, 1280, 1.0f, p_kh, BATCH*CTX);
    cvt_vt_kernel<<<dim3(128/32, 3, 64), tb>>>(p_kv, 1280, 640, p_vth, CTX, 128);
    flash_attn_f16_kernel<<<dim3(HW/FTQ, BATCH*HEADS), 256, FLASH_SMEM>>>(
        p_qh, p_kh, p_vth, p_ao, CTX, 128);
    TW(wo2, p_wt, CCH, CCH);
    GEMM_TC(p_ao, p_wt, bo2, p_t, MTOK, CCH, CCH, 1);

    // 5) GEGLU FF (fused) + FFO
    layernorm_kernel<<<MTOK/8, 256>>>(p_t, ln3_g, ln3_b, p_tn);
    TW(w_geglu, p_wt, CCH, 2*FF);
    geglu_tc_kernel<<<dim3(FF/128, MTOK/256), 256, GEGLU_SMEM>>>(
        p_tn, p_wt, p_wt + (size_t)FF*CCH, b_geglu, p_ff, MTOK, CCH);
    TW(w_ffo, p_wt, FF, CCH);
    GEMM_TC(p_ff, p_wt, b_ffo, p_t, MTOK, CCH, FF, 1);

    // 6) proj_out fused with transpose + input residual
    TW(w_out, p_wt, CCH, CCH);
    gemm_out_kernel<<<dim3(CCH/128, MTOK/128), 256, GEMM_SMEM>>>(
        p_t, p_wt, b_out, x, out, CCH);
}

// round 17
// speedup vs baseline: 1.5344x; 1.3065x over previous
#include <cuda_runtime.h>
#include <cuda_fp16.h>
#include <math.h>
#include <stdint.h>

// ---------------- problem constants ----------------
#define BATCH   8
#define CCH     640
#define HW      1024
#define MTOK    (BATCH*HW)
#define HEADS   8
#define DH      80
#define CTX     77
#define CTXD    768
#define FF      2560
#define GROUPS  32
#define CPG     (CCH/GROUPS)

#if defined(__CUDA_ARCH__) && (defined(__CUDA_ARCH_FEAT_SM103_ALL) || defined(__CUDA_ARCH_SPECIFIC__))
#define HAS_TCGEN05 1
#else
#define HAS_TCGEN05 0
#endif

// ---------------- scratch ----------------
__device__ float  g_t   [MTOK*CCH];                 // fp32 residual stream
__device__ float  g_q   [MTOK*CCH];                 // fp32 cross-attn Q
__device__ float  g_qkv [(size_t)MTOK*1920];
__device__ float  g_kv  [BATCH*CTX*1280];
__device__ float  g_stats[BATCH*GROUPS*2];
__device__ __half g_tnh [(size_t)MTOK*CCH];         // LN/GN outputs (GEMM A)
__device__ __half g_aoh [(size_t)MTOK*CCH];         // attention output (GEMM A)
__device__ __half g_ffh [(size_t)MTOK*FF];          // geglu output (GEMM A)
__device__ __half g_th  [(size_t)MTOK*CCH];         // t half copy for proj_out
__device__ __half g_ctxh[BATCH*CTX*CTXD];
__device__ __half g_wth [(size_t)5120*640];         // transposed half weights
__device__ __half g_qh  [(size_t)MTOK*CCH];
__device__ __half g_kh  [(size_t)MTOK*CCH];
__device__ __half g_vth [(size_t)64*80*1024];

// ================= common PTX helpers =================
__device__ __forceinline__ uint32_t smem_u32(const void* p) {
    uint32_t a;
    asm("{ .reg .u64 t; cvta.to.shared.u64 t, %1; cvt.u32.u64 %0, t; }" : "=r"(a) : "l"(p));
    return a;
}
__device__ __forceinline__ void cp_async16(void* smem_ptr, const void* gptr, bool pred)
{
    uint32_t saddr = smem_u32(smem_ptr);
    int sz = pred ? 16 : 0;
    asm volatile("cp.async.cg.shared.global [%0], [%1], 16, %2;\n"
                 :: "r"(saddr), "l"(gptr), "r"(sz));
}
__device__ __forceinline__ void cp_commit() { asm volatile("cp.async.commit_group;\n" ::: "memory"); }
__device__ __forceinline__ void cp_wait0()  { asm volatile("cp.async.wait_group 0;\n" ::: "memory"); }
__device__ __forceinline__ void cp_wait1()  { asm volatile("cp.async.wait_group 1;\n" ::: "memory"); }

__device__ __forceinline__ void mma_f16(float& d0, float& d1, float& d2, float& d3,
                                        uint32_t a0, uint32_t a1, uint32_t a2, uint32_t a3,
                                        uint32_t b0, uint32_t b1)
{
    asm volatile(
        "mma.sync.aligned.m16n8k16.row.col.f32.f16.f16.f32 "
        "{%0,%1,%2,%3}, {%4,%5,%6,%7}, {%8,%9}, {%0,%1,%2,%3};\n"
        : "+f"(d0), "+f"(d1), "+f"(d2), "+f"(d3)
        : "r"(a0), "r"(a1), "r"(a2), "r"(a3), "r"(b0), "r"(b1));
}

#if HAS_TCGEN05
__device__ __forceinline__ uint32_t elect_one() {
    uint32_t p;
    asm volatile("{\n\t.reg .pred p;\n\telect.sync _|p, 0xFFFFFFFF;\n\tselp.b32 %0, 1, 0, p;\n\t}" : "=r"(p));
    return p;
}
#define TCGEN05_ALLOC(smem_addr, nCols) \
    asm volatile("tcgen05.alloc.cta_group::1.sync.aligned.shared::cta.b32 [%0], %1;" \
                 :: "r"((uint32_t)(smem_addr)), "r"((uint32_t)(nCols)) : "memory")
#define TCGEN05_DEALLOC(tmem, nCols) \
    asm volatile("tcgen05.dealloc.cta_group::1.sync.aligned.b32 %0, %1;" :: "r"(tmem), "r"((uint32_t)(nCols)))
#define TCGEN05_RELINQ() \
    asm volatile("tcgen05.relinquish_alloc_permit.cta_group::1.sync.aligned;")
#define TCGEN05_COMMIT(mbar) \
    asm volatile("tcgen05.commit.cta_group::1.mbarrier::arrive::one.shared::cluster.b64 [%0];" \
                 :: "r"((uint32_t)(mbar)) : "memory")
#define TCGEN05_FENCE_AFTER() asm volatile("tcgen05.fence::after_thread_sync;" ::: "memory")
#define TCGEN05_WAIT_LD()     asm volatile("tcgen05.wait::ld.sync.aligned;" ::: "memory")
#define FENCE_ASYNC_SHARED()  asm volatile("fence.proxy.async.shared::cta;" ::: "memory")
#define MBARRIER_INIT(mbar, cnt) \
    asm volatile("mbarrier.init.shared.b64 [%0], %1;" :: "r"((uint32_t)(mbar)), "r"((uint32_t)(cnt)) : "memory")
#define MBARRIER_WAIT_PARITY(mbar, ph) do {                                           \
    uint32_t _m = (uint32_t)(mbar), _p = (uint32_t)(ph), _d;                          \
    asm volatile("{\n\t.reg .pred p;\n\t"                                             \
        "mbarrier.try_wait.parity.acquire.cta.shared::cta.b64 p, [%1], %2;\n\t"       \
        "selp.b32 %0, 1, 0, p;\n\t}" : "=r"(_d) : "r"(_m), "r"(_p) : "memory");       \
    if (!_d) {                                                                        \
        asm volatile("{\n\t.reg .pred P1;\n\t"                                        \
            "WL_%=:\n\t"                                                              \
            "mbarrier.try_wait.parity.acquire.cta.shared::cta.b64 P1, [%0], %1, 0x989680;\n\t" \
            "@P1 bra.uni WD_%=;\n\t"                                                  \
            "bra.uni WL_%=;\n\t"                                                      \
            "WD_%=:\n\t}" :: "r"(_m), "r"(_p) : "memory");                            \
    }                                                                                 \
} while (0)
#define TCGEN05_LD_X32(r, tmem)                                                        \
    asm volatile("tcgen05.ld.sync.aligned.32x32b.x32.b32 "                             \
        "{%0, %1, %2, %3, %4, %5, %6, %7, "                                            \
        " %8, %9, %10, %11, %12, %13, %14, %15, "                                      \
        " %16, %17, %18, %19, %20, %21, %22, %23, "                                    \
        " %24, %25, %26, %27, %28, %29, %30, %31}, [%32];"                             \
        : "=r"((r)[0]),  "=r"((r)[1]),  "=r"((r)[2]),  "=r"((r)[3]),                   \
          "=r"((r)[4]),  "=r"((r)[5]),  "=r"((r)[6]),  "=r"((r)[7]),                   \
          "=r"((r)[8]),  "=r"((r)[9]),  "=r"((r)[10]), "=r"((r)[11]),                  \
          "=r"((r)[12]), "=r"((r)[13]), "=r"((r)[14]), "=r"((r)[15]),                  \
          "=r"((r)[16]), "=r"((r)[17]), "=r"((r)[18]), "=r"((r)[19]),                  \
          "=r"((r)[20]), "=r"((r)[21]), "=r"((r)[22]), "=r"((r)[23]),                  \
          "=r"((r)[24]), "=r"((r)[25]), "=r"((r)[26]), "=r"((r)[27]),                  \
          "=r"((r)[28]), "=r"((r)[29]), "=r"((r)[30]), "=r"((r)[31])                   \
        : "r"(tmem))

__device__ __forceinline__ void tc_mma_f16_ss(uint32_t d, uint64_t ad, uint64_t bd,
                                              uint32_t idesc, uint32_t en)
{
    asm volatile("{\n\t.reg .pred p;\n\tsetp.ne.u32 p, %4, 0;\n\t"
        "tcgen05.mma.cta_group::1.kind::f16 [%0], %1, %2, %3, {%5,%5,%5,%5}, p;\n\t}"
        :: "r"(d), "l"(ad), "l"(bd), "r"(idesc), "r"(en), "r"(0u) : "memory");
}
__device__ __forceinline__ uint64_t make_desc(uint32_t saddr)
{
    return (uint64_t(2) << 61) | (uint64_t(1) << 46) | (uint64_t(64) << 32)
         | (uint64_t(1) << 16) | ((uint64_t)(saddr >> 4) & 0x3FFF);
}
// kind::f16 idesc: dtype=F32(1)@4, atype=FP16(0)@7, btype=FP16(0)@10, N/8@17, M/16@24
#define IDESC_F16 ((1u<<4)|((128u/8u)<<17)|((128u/16u)<<24))
#endif  // HAS_TCGEN05

// ================= GroupNorm =================
__global__ void gn_stats_kernel(const float* __restrict__ x, float* __restrict__ stats)
{
    int bg = blockIdx.x;
    int b = bg / GROUPS, g = bg % GROUPS;
    const float* base = x + (size_t)b*CCH*HW + (size_t)g*CPG*HW;
    int tid = threadIdx.x;
    float s = 0.f, ss = 0.f;
    for (int i = tid; i < CPG*HW; i += 256) { float v = base[i]; s += v; ss += v*v; }
    __shared__ float r1[256], r2[256];
    r1[tid] = s; r2[tid] = ss; __syncthreads();
    for (int st = 128; st > 0; st >>= 1) {
        if (tid < st) { r1[tid] += r1[tid+st]; r2[tid] += r2[tid+st]; }
        __syncthreads();
    }
    if (tid == 0) {
        const float inv = 1.f / (float)(CPG*HW);
        float mean = r1[0]*inv;
        float var  = r2[0]*inv - mean*mean;
        stats[bg*2]   = mean;
        stats[bg*2+1] = rsqrtf(var + 1e-6f);
    }
}

__global__ void gn_apply_kernel(const float* __restrict__ x,
                                const float* __restrict__ gamma,
                                const float* __restrict__ beta,
                                const float* __restrict__ stats,
                                __half* __restrict__ out)
{
    __shared__ float tile[32][33];
    int b  = blockIdx.z;
    int c0 = blockIdx.y*32, hw0 = blockIdx.x*32;
    int tx = threadIdx.x, ty = threadIdx.y;
    #pragma unroll
    for (int i = 0; i < 32; i += 8) {
        int c = c0 + ty + i;
        int bg = b*GROUPS + c/CPG;
        float mean = stats[bg*2], rstd = stats[bg*2+1];
        float v = x[((size_t)b*CCH + c)*HW + hw0 + tx];
        tile[ty+i][tx] = (v - mean)*rstd*gamma[c] + beta[c];
    }
    __syncthreads();
    #pragma unroll
    for (int i = 0; i < 32; i += 8) {
        int hw = hw0 + ty + i;
        out[((size_t)b*HW + hw)*CCH + c0 + tx] = __float2half(tile[tx][ty+i]);
    }
}

// ================= weight transpose w[K][N] -> wt[N][K] (half out) ==========
__global__ void transpose_wh(const float* __restrict__ w, __half* __restrict__ wt, int K, int N)
{
    __shared__ float t[32][33];
    int k0 = blockIdx.y*32, n0 = blockIdx.x*32;
    int tx = threadIdx.x, ty = threadIdx.y;
    #pragma unroll
    for (int i = 0; i < 32; i += 8)
        t[ty+i][tx] = w[(size_t)(k0+ty+i)*N + n0 + tx];
    __syncthreads();
    #pragma unroll
    for (int i = 0; i < 32; i += 8)
        wt[(size_t)(n0+ty+i)*K + k0 + tx] = __float2half(t[tx][ty+i]);
}

// ================= f32 -> f16 converts =================
__global__ void cvt_f2h(const float* __restrict__ src, __half* __restrict__ dst, size_t n)
{
    size_t i = ((size_t)blockIdx.x*256 + threadIdx.x)*2;
    if (i < n) {
        float2 v = *(const float2*)(src + i);
        *(__half2*)(dst + i) = __floats2half2_rn(v.x, v.y);
    }
}
// dst[m][0..639] = half(src[m*srcStride + c] * scale)
__global__ void cvt_half_kernel(const float* __restrict__ src, int srcStride,
                                float scale, __half* __restrict__ dst, int M)
{
    size_t idx = (size_t)blockIdx.x*256 + threadIdx.x;
    if (idx >= (size_t)M*320) return;
    int m = (int)(idx / 320), c = (int)(idx % 320)*2;
    float2 v = *(const float2*)(src + (size_t)m*srcStride + c);
    *(__half2*)(dst + (size_t)m*CCH + c) = __floats2half2_rn(v.x*scale, v.y*scale);
}
// dst[(bh*80 + d)*Lpad + j] = half(src[(b*Lk + j)*srcStride + colOff + h*80 + d]); pad->0
__global__ void cvt_vt_kernel(const float* __restrict__ src, int srcStride, int colOff,
                              __half* __restrict__ dst, int Lk, int Lpad)
{
    __shared__ float tile[32][33];
    int bh = blockIdx.z;
    int b = bh >> 3, h = bh & 7;
    int j0 = blockIdx.x*32, d0 = blockIdx.y*32;
    int tx = threadIdx.x, ty = threadIdx.y;
    #pragma unroll
    for (int i = 0; i < 32; i += 8) {
        int j = j0 + ty + i, d = d0 + tx;
        float v = 0.f;
        if (j < Lk && d < DH)
            v = src[((size_t)b*Lk + j)*srcStride + colOff + h*DH + d];
        tile[ty+i][tx] = v;
    }
    __syncthreads();
    #pragma unroll
    for (int i = 0; i < 32; i += 8) {
        int d = d0 + ty + i, j = j0 + tx;
        if (d < DH)
            dst[((size_t)(bh*DH + d))*Lpad + j] = __float2half(tile[tx][ty+i]);
    }
}

// ================= fp16 GEMM 128x128: C_f32 = Ah @ Bth^T (+bias)(+=) ========
// Stage (32KB): A[128][K64] SW128 @ +0, B[128][K64] @ +16K. 3-stage ring.
#define H_STAGE 32768
#define H_CTRL  (3*H_STAGE)
#define GEMMH_SMEM (3*H_STAGE + 64)

__global__ __launch_bounds__(256, 1)
void gemm_h_kernel(const __half* __restrict__ A, const __half* __restrict__ Bt,
                   const float* __restrict__ bias, float* __restrict__ C,
                   int M, int N, int K, int accumulate)
{
    extern __shared__ float smem[];
    int tid = threadIdx.x, lane = tid & 31;
    int m0 = blockIdx.y * 128, n0 = blockIdx.x * 128;

#if HAS_TCGEN05
    char* sbase = (char*)smem;
    uint32_t sb = smem_u32(smem);
    int w = tid >> 5;
    int rows_valid = M - m0; if (rows_valid > 128) rows_valid = 128;

    if (w == 0) {
        TCGEN05_ALLOC(sb + H_CTRL + 24, 128);
        TCGEN05_RELINQ();
    }
    if (tid == 0) {
        #pragma unroll
        for (int s = 0; s < 3; s++) MBARRIER_INIT(sb + H_CTRL + s*8, 1);
    }
    __syncthreads();
    uint32_t tmem;
    asm volatile("ld.shared.b32 %0, [%1];" : "=r"(tmem) : "r"(sb + H_CTRL + 24));

    const __half* Ab = A  + (size_t)m0*K;
    const __half* Bb = Bt + (size_t)n0*K;
    int r_ld = tid >> 3, c_ld = tid & 7;   // 32 rows/pass, chunk of 8 halves

    auto load_tiles = [&](int slot, int k0) {
        char* st = sbase + slot*H_STAGE;
        #pragma unroll
        for (int p = 0; p < 4; p++) {
            int r = r_ld + p*32;
            uint32_t off = (uint32_t)(r*128 + c_ld*16);
            off ^= ((off >> 3) & 0x70);
            int gr = (r < rows_valid) ? r : (rows_valid - 1);
            bool ap = (r < rows_valid);
            cp_async16(st + off,         Ab + (size_t)gr*K + k0 + c_ld*8, ap);
            cp_async16(st + 16384 + off, Bb + (size_t)r*K  + k0 + c_ld*8, true);
        }
    };

    int nk = K / 64;
    uint32_t ph = 0;
    load_tiles(0, 0);   cp_commit();
    load_tiles(1, 64);  cp_commit();

    for (int it = 0; it < nk; it++) {
        int slot = it % 3;
        int rem = nk - 1 - it;
        if (rem >= 1) cp_wait1(); else cp_wait0();
        __syncthreads();
        FENCE_ASYNC_SHARED();

        if (w == 0 && elect_one()) {
            uint32_t stb = sb + slot*H_STAGE;
            #pragma unroll
            for (int s = 0; s < 4; s++) {
                uint64_t ad = make_desc(stb)         + (uint64_t)s*2;
                uint64_t bd = make_desc(stb + 16384) + (uint64_t)s*2;
                tc_mma_f16_ss(tmem, ad, bd, IDESC_F16, (it > 0 || s > 0));
            }
            TCGEN05_COMMIT(sb + H_CTRL + slot*8);
        }

        int j = it + 2;
        if (j < nk) {
            int ns = j % 3;
            if (j >= 3) {
                MBARRIER_WAIT_PARITY(sb + H_CTRL + ns*8, (ph >> ns) & 1);
                ph ^= (1u << ns);
            }
            load_tiles(ns, j*64);
            cp_commit();
        }
    }
    {
        int sl = (nk - 1) % 3;
        MBARRIER_WAIT_PARITY(sb + H_CTRL + sl*8, (ph >> sl) & 1);
    }
    TCGEN05_FENCE_AFTER();
    __syncthreads();

    float* tile = smem;
    {
        int subp = w & 3, half = w >> 2;
        int erow = subp*32 + lane;
        uint32_t ra[32], rb[32];
        TCGEN05_LD_X32(ra, tmem + half*64);
        TCGEN05_LD_X32(rb, tmem + half*64 + 32);
        TCGEN05_WAIT_LD();
        float* dst = tile + (size_t)erow*129 + half*64;
        #pragma unroll
        for (int c = 0; c < 32; c++) {
            dst[c]      = __uint_as_float(ra[c]);
            dst[32 + c] = __uint_as_float(rb[c]);
        }
    }
    __syncthreads();
    {
        float4 bv = make_float4(0.f, 0.f, 0.f, 0.f);
        if (bias) bv = *(const float4*)(bias + n0 + lane*4);
        #pragma unroll
        for (int p = 0; p < 16; p++) {
            int r = p*8 + w;
            int gm = m0 + r;
            if (gm < M) {
                const float* src = tile + (size_t)r*129 + lane*4;
                float4 v = make_float4(src[0]+bv.x, src[1]+bv.y, src[2]+bv.z, src[3]+bv.w);
                float4* op = (float4*)(C + (size_t)gm*N + n0 + lane*4);
                if (accumulate) {
                    float4 o = *op;
                    v.x += o.x; v.y += o.y; v.z += o.z; v.w += o.w;
                }
                *op = v;
            }
        }
    }
    if (w == 0) TCGEN05_DEALLOC(tmem, 128);

#else
    for (int idx = tid; idx < 128*128; idx += 256) {
        int r = idx >> 7, c = idx & 127;
        int gm = m0 + r; if (gm >= M) continue;
        float s = bias ? bias[n0 + c] : 0.f;
        for (int k = 0; k < K; k++)
            s += __half2float(A[(size_t)gm*K + k]) * __half2float(Bt[(size_t)(n0+c)*K + k]);
        size_t o = (size_t)gm*N + n0 + c;
        if (accumulate) C[o] += s; else C[o] = s;
    }
#endif
}

// ============ fp16 GEMM 128x128 with fused transpose+residual output ========
__global__ __launch_bounds__(256, 1)
void gemm_out_h_kernel(const __half* __restrict__ A, const __half* __restrict__ Bt,
                       const float* __restrict__ bias, const float* __restrict__ x,
                       float* __restrict__ outp, int K)
{
    extern __shared__ float smem[];
    int tid = threadIdx.x, lane = tid & 31;
    int m0 = blockIdx.y * 128, n0 = blockIdx.x * 128;

#if HAS_TCGEN05
    char* sbase = (char*)smem;
    uint32_t sb = smem_u32(smem);
    int w = tid >> 5;

    if (w == 0) {
        TCGEN05_ALLOC(sb + H_CTRL + 24, 128);
        TCGEN05_RELINQ();
    }
    if (tid == 0) {
        #pragma unroll
        for (int s = 0; s < 3; s++) MBARRIER_INIT(sb + H_CTRL + s*8, 1);
    }
    __syncthreads();
    uint32_t tmem;
    asm volatile("ld.shared.b32 %0, [%1];" : "=r"(tmem) : "r"(sb + H_CTRL + 24));

    const __half* Ab = A  + (size_t)m0*K;
    const __half* Bb = Bt + (size_t)n0*K;
    int r_ld = tid >> 3, c_ld = tid & 7;

    auto load_tiles = [&](int slot, int k0) {
        char* st = sbase + slot*H_STAGE;
        #pragma unroll
        for (int p = 0; p < 4; p++) {
            int r = r_ld + p*32;
            uint32_t off = (uint32_t)(r*128 + c_ld*16);
            off ^= ((off >> 3) & 0x70);
            cp_async16(st + off,         Ab + (size_t)r*K + k0 + c_ld*8, true);
            cp_async16(st + 16384 + off, Bb + (size_t)r*K + k0 + c_ld*8, true);
        }
    };

    int nk = K / 64;
    uint32_t ph = 0;
    load_tiles(0, 0);   cp_commit();
    load_tiles(1, 64);  cp_commit();

    for (int it = 0; it < nk; it++) {
        int slot = it % 3;
        int rem = nk - 1 - it;
        if (rem >= 1) cp_wait1(); else cp_wait0();
        __syncthreads();
        FENCE_ASYNC_SHARED();

        if (w == 0 && elect_one()) {
            uint32_t stb = sb + slot*H_STAGE;
            #pragma unroll
            for (int s = 0; s < 4; s++) {
                uint64_t ad = make_desc(stb)         + (uint64_t)s*2;
                uint64_t bd = make_desc(stb + 16384) + (uint64_t)s*2;
                tc_mma_f16_ss(tmem, ad, bd, IDESC_F16, (it > 0 || s > 0));
            }
            TCGEN05_COMMIT(sb + H_CTRL + slot*8);
        }

        int j = it + 2;
        if (j < nk) {
            int ns = j % 3;
            if (j >= 3) {
                MBARRIER_WAIT_PARITY(sb + H_CTRL + ns*8, (ph >> ns) & 1);
                ph ^= (1u << ns);
            }
            load_tiles(ns, j*64);
            cp_commit();
        }
    }
    {
        int sl = (nk - 1) % 3;
        MBARRIER_WAIT_PARITY(sb + H_CTRL + sl*8, (ph >> sl) & 1);
    }
    TCGEN05_FENCE_AFTER();
    __syncthreads();

    float* tile = smem;
    {
        int subp = w & 3, half = w >> 2;
        int erow = subp*32 + lane;
        uint32_t ra[32], rb[32];
        TCGEN05_LD_X32(ra, tmem + half*64);
        TCGEN05_LD_X32(rb, tmem + half*64 + 32);
        TCGEN05_WAIT_LD();
        float* dst = tile + (size_t)erow*129 + half*64;
        #pragma unroll
        for (int c = 0; c < 32; c++) {
            dst[c]      = __uint_as_float(ra[c]);
            dst[32 + c] = __uint_as_float(rb[c]);
        }
    }
    __syncthreads();

    {
        int b   = m0 >> 10;
        int hw0 = m0 & 1023;
        #pragma unroll
        for (int i = 0; i < 16; i++) {
            int cc = w*16 + i;
            int gc = n0 + cc;
            float bv = __ldg(bias + gc);
            size_t gbase = ((size_t)(b*CCH + gc))*HW + hw0 + lane*4;
            float4 xv = *(const float4*)(x + gbase);
            const float* src = tile + (size_t)(lane*4)*129 + cc;
            float4 v;
            v.x = src[0]   + bv + xv.x;
            v.y = src[129] + bv + xv.y;
            v.z = src[258] + bv + xv.z;
            v.w = src[387] + bv + xv.w;
            *(float4*)(outp + gbase) = v;
        }
    }
    if (w == 0) TCGEN05_DEALLOC(tmem, 128);

#else
    for (int idx = tid; idx < 128*128; idx += 256) {
        int r = idx >> 7, c = idx & 127;
        int gm = m0 + r, gc = n0 + c;
        float s = bias[gc];
        for (int k = 0; k < K; k++)
            s += __half2float(A[(size_t)gm*K + k]) * __half2float(Bt[(size_t)gc*K + k]);
        int b = gm / HW, hw = gm % HW;
        size_t o = ((size_t)(b*CCH + gc))*HW + hw;
        outp[o] = s + x[o];
    }
#endif
}

// ============ fp16 GEMM 256x128 (dual accumulator, K64 stages) ==============
// Stage (48KB): A_lo(16K) A_hi(16K) B(16K). 2-stage.
#define H256_STAGE 49152
#define H256_CTRL  (2*H256_STAGE)
#define GEMMH256_SMEM (2*H256_STAGE + 64)

__global__ __launch_bounds__(256, 1)
void gemm_h256_kernel(const __half* __restrict__ A, const __half* __restrict__ Bt,
                      const float* __restrict__ bias, float* __restrict__ C,
                      int M, int N, int K, int accumulate)
{
    extern __shared__ float smem[];
    int tid = threadIdx.x, lane = tid & 31;
    int m0 = blockIdx.y * 256, n0 = blockIdx.x * 128;

#if HAS_TCGEN05
    char* sbase = (char*)smem;
    uint32_t sb = smem_u32(smem);
    int w = tid >> 5;

    if (w == 0) {
        TCGEN05_ALLOC(sb + H256_CTRL + 16, 256);
        TCGEN05_RELINQ();
    }
    if (tid == 0) {
        MBARRIER_INIT(sb + H256_CTRL,     1);
        MBARRIER_INIT(sb + H256_CTRL + 8, 1);
    }
    __syncthreads();
    uint32_t tmem;
    asm volatile("ld.shared.b32 %0, [%1];" : "=r"(tmem) : "r"(sb + H256_CTRL + 16));

    const __half* Ab = A  + (size_t)m0*K;
    const __half* Bb = Bt + (size_t)n0*K;
    int r_ld = tid >> 3, c_ld = tid & 7;

    auto load_tiles = [&](int slot, int k0) {
        char* st = sbase + slot*H256_STAGE;
        #pragma unroll
        for (int p = 0; p < 8; p++) {          // A: 256 rows
            int r = r_ld + p*32;
            int half = r >> 7, rr = r & 127;
            uint32_t off = (uint32_t)(rr*128 + c_ld*16);
            off ^= ((off >> 3) & 0x70);
            cp_async16(st + half*16384 + off, Ab + (size_t)r*K + k0 + c_ld*8, true);
        }
        #pragma unroll
        for (int p = 0; p < 4; p++) {          // B: 128 rows
            int r = r_ld + p*32;
            uint32_t off = (uint32_t)(r*128 + c_ld*16);
            off ^= ((off >> 3) & 0x70);
            cp_async16(st + 32768 + off, Bb + (size_t)r*K + k0 + c_ld*8, true);
        }
    };

    int nk = K / 64;
    uint32_t ph = 0;
    load_tiles(0, 0);   cp_commit();
    if (nk > 1) { load_tiles(1, 64); cp_commit(); }

    for (int it = 0; it < nk; it++) {
        int slot = it & 1;
        int rem = nk - 1 - it;
        if (rem >= 1) cp_wait1(); else cp_wait0();
        __syncthreads();
        FENCE_ASYNC_SHARED();

        if (w == 0 && elect_one()) {
            uint32_t stb = sb + slot*H256_STAGE;
            #pragma unroll
            for (int s = 0; s < 4; s++) {
                uint64_t step = (uint64_t)s*2;
                uint64_t ad0 = make_desc(stb)         + step;
                uint64_t ad1 = make_desc(stb + 16384) + step;
                uint64_t bd  = make_desc(stb + 32768) + step;
                uint32_t en = (it > 0 || s > 0);
                tc_mma_f16_ss(tmem,       ad0, bd, IDESC_F16, en);
                tc_mma_f16_ss(tmem + 128, ad1, bd, IDESC_F16, en);
            }
            TCGEN05_COMMIT(sb + H256_CTRL + slot*8);
        }

        int j = it + 2;
        if (j < nk) {
            int ns = j & 1;
            MBARRIER_WAIT_PARITY(sb + H256_CTRL + ns*8, (ph >> ns) & 1);
            ph ^= (1u << ns);
            load_tiles(ns, j*64);
            cp_commit();
        }
    }
    {
        int sl = (nk - 1) & 1;
        MBARRIER_WAIT_PARITY(sb + H256_CTRL + sl*8, (ph >> sl) & 1);
    }
    TCGEN05_FENCE_AFTER();
    __syncthreads();

    float* tile = smem;
    float4 bv = make_float4(0.f, 0.f, 0.f, 0.f);
    if (bias) bv = *(const float4*)(bias + n0 + lane*4);

    for (int acc = 0; acc < 2; acc++) {
        {
            int subp = w & 3, half = w >> 2;
            int erow = subp*32 + lane;
            uint32_t ra[32], rb[32];
            TCGEN05_LD_X32(ra, tmem + acc*128 + half*64);
            TCGEN05_LD_X32(rb, tmem + acc*128 + half*64 + 32);
            TCGEN05_WAIT_LD();
            float* dst = tile + (size_t)erow*129 + half*64;
            #pragma unroll
            for (int c = 0; c < 32; c++) {
                dst[c]      = __uint_as_float(ra[c]);
                dst[32 + c] = __uint_as_float(rb[c]);
            }
        }
        __syncthreads();
        #pragma unroll
        for (int p = 0; p < 16; p++) {
            int r = p*8 + w;
            int gm = m0 + acc*128 + r;
            const float* src = tile + (size_t)r*129 + lane*4;
            float4 v = make_float4(src[0]+bv.x, src[1]+bv.y, src[2]+bv.z, src[3]+bv.w);
            float4* op = (float4*)(C + (size_t)gm*N + n0 + lane*4);
            if (accumulate) {
                float4 o = *op;
                v.x += o.x; v.y += o.y; v.z += o.z; v.w += o.w;
            }
            *op = v;
        }
        __syncthreads();
    }
    if (w == 0) TCGEN05_DEALLOC(tmem, 256);

#else
    for (int idx = tid; idx < 256*128; idx += 256) {
        int r = idx >> 7, c = idx & 127;
        float s = bias ? bias[n0 + c] : 0.f;
        for (int k = 0; k < K; k++)
            s += __half2float(A[(size_t)(m0 + r)*K + k]) * __half2float(Bt[(size_t)(n0 + c)*K + k]);
        size_t o = (size_t)(m0 + r)*N + n0 + c;
        if (accumulate) C[o] += s; else C[o] = s;
    }
#endif
}

// ============ fp16 fused GEGLU GEMM: ffh = half(a * gelu(gate)) =============
// Stage (64KB): A_lo A_hi Ba Bg (16KB each). 2-stage. TMEM 512 cols.
#define GGH_STAGE 65536
#define GGH_CTRL  (2*GGH_STAGE)
#define GEGLUH_SMEM (2*GGH_STAGE + 64)

__global__ __launch_bounds__(256, 1)
void geglu_h_kernel(const __half* __restrict__ A, const __half* __restrict__ Bta,
                    const __half* __restrict__ Btg, const float* __restrict__ bias,
                    __half* __restrict__ FFo, int M, int K)
{
    extern __shared__ float smem[];
    int tid = threadIdx.x, lane = tid & 31;
    int m0 = blockIdx.y * 256, n0 = blockIdx.x * 128;

#if HAS_TCGEN05
    char* sbase = (char*)smem;
    uint32_t sb = smem_u32(smem);
    int w = tid >> 5;

    if (w == 0) {
        TCGEN05_ALLOC(sb + GGH_CTRL + 16, 512);
        TCGEN05_RELINQ();
    }
    if (tid == 0) {
        MBARRIER_INIT(sb + GGH_CTRL,     1);
        MBARRIER_INIT(sb + GGH_CTRL + 8, 1);
    }
    __syncthreads();
    uint32_t tmem;
    asm volatile("ld.shared.b32 %0, [%1];" : "=r"(tmem) : "r"(sb + GGH_CTRL + 16));

    const __half* Ab  = A   + (size_t)m0*K;
    const __half* Bab = Bta + (size_t)n0*K;
    const __half* Bgb = Btg + (size_t)n0*K;
    int r_ld = tid >> 3, c_ld = tid & 7;

    auto load_tiles = [&](int slot, int k0) {
        char* st = sbase + slot*GGH_STAGE;
        #pragma unroll
        for (int p = 0; p < 8; p++) {
            int r = r_ld + p*32;
            int half = r >> 7, rr = r & 127;
            uint32_t off = (uint32_t)(rr*128 + c_ld*16);
            off ^= ((off >> 3) & 0x70);
            cp_async16(st + half*16384 + off, Ab + (size_t)r*K + k0 + c_ld*8, true);
        }
        #pragma unroll
        for (int p = 0; p < 4; p++) {
            int r = r_ld + p*32;
            uint32_t off = (uint32_t)(r*128 + c_ld*16);
            off ^= ((off >> 3) & 0x70);
            cp_async16(st + 32768 + off, Bab + (size_t)r*K + k0 + c_ld*8, true);
            cp_async16(st + 49152 + off, Bgb + (size_t)r*K + k0 + c_ld*8, true);
        }
    };

    int nk = K / 64;
    uint32_t ph = 0;
    load_tiles(0, 0);   cp_commit();
    if (nk > 1) { load_tiles(1, 64); cp_commit(); }

    for (int it = 0; it < nk; it++) {
        int slot = it & 1;
        int rem = nk - 1 - it;
        if (rem >= 1) cp_wait1(); else cp_wait0();
        __syncthreads();
        FENCE_ASYNC_SHARED();

        if (w == 0 && elect_one()) {
            uint32_t stb = sb + slot*GGH_STAGE;
            #pragma unroll
            for (int s = 0; s < 4; s++) {
                uint64_t step = (uint64_t)s*2;
                uint64_t ad0 = make_desc(stb)         + step;
                uint64_t ad1 = make_desc(stb + 16384) + step;
                uint64_t bad = make_desc(stb + 32768) + step;
                uint64_t bgd = make_desc(stb + 49152) + step;
                uint32_t en = (it > 0 || s > 0);
                tc_mma_f16_ss(tmem,       ad0, bad, IDESC_F16, en);
                tc_mma_f16_ss(tmem + 128, ad1, bad, IDESC_F16, en);
                tc_mma_f16_ss(tmem + 256, ad0, bgd, IDESC_F16, en);
                tc_mma_f16_ss(tmem + 384, ad1, bgd, IDESC_F16, en);
            }
            TCGEN05_COMMIT(sb + GGH_CTRL + slot*8);
        }

        int j = it + 2;
        if (j < nk) {
            int ns = j & 1;
            MBARRIER_WAIT_PARITY(sb + GGH_CTRL + ns*8, (ph >> ns) & 1);
            ph ^= (1u << ns);
            load_tiles(ns, j*64);
            cp_commit();
        }
    }
    {
        int sl = (nk - 1) & 1;
        MBARRIER_WAIT_PARITY(sb + GGH_CTRL + sl*8, (ph >> sl) & 1);
    }
    TCGEN05_FENCE_AFTER();
    __syncthreads();

    float* tile = smem;
    const float inv_sqrt2 = 0.70710678118654752f;

    for (int h = 0; h < 2; h++) {
        {
            int subp = w & 3, ch = w >> 2;
            int erow = subp*32 + lane;
            float* dst = tile + (size_t)erow*129 + ch*64;
            #pragma unroll
            for (int cc = 0; cc < 2; cc++) {
                uint32_t ra[32], rg[32];
                TCGEN05_LD_X32(ra, tmem + h*128 + ch*64 + cc*32);
                TCGEN05_LD_X32(rg, tmem + 256 + h*128 + ch*64 + cc*32);
                TCGEN05_WAIT_LD();
                #pragma unroll
                for (int c = 0; c < 32; c++) {
                    int col = ch*64 + cc*32 + c;
                    float av = __uint_as_float(ra[c]) + __ldg(bias + n0 + col);
                    float gv = __uint_as_float(rg[c]) + __ldg(bias + FF + n0 + col);
                    float gel = 0.5f*gv*(1.f + erff(gv*inv_sqrt2));
                    dst[cc*32 + c] = av * gel;
                }
            }
        }
        __syncthreads();
        #pragma unroll
        for (int p = 0; p < 16; p++) {
            int r = p*8 + w;
            int gm = m0 + h*128 + r;
            const float* src = tile + (size_t)r*129 + lane*4;
            __half2 h01 = __floats2half2_rn(src[0], src[1]);
            __half2 h23 = __floats2half2_rn(src[2], src[3]);
            uint2 u;
            u.x = *(uint32_t*)&h01;
            u.y = *(uint32_t*)&h23;
            *(uint2*)(FFo + (size_t)gm*FF + n0 + lane*4) = u;
        }
        __syncthreads();
    }
    if (w == 0) TCGEN05_DEALLOC(tmem, 512);

#else
    for (int idx = tid; idx < 256*128; idx += 256) {
        int r = idx >> 7, c = idx & 127;
        float sa = bias[n0 + c], sg = bias[FF + n0 + c];
        for (int k = 0; k < K; k++) {
            float av = __half2float(A[(size_t)(m0 + r)*K + k]);
            sa += av * __half2float(Bta[(size_t)(n0 + c)*K + k]);
            sg += av * __half2float(Btg[(size_t)(n0 + c)*K + k]);
        }
        float gel = 0.5f*sg*(1.f + erff(sg*0.70710678118654752f));
        FFo[(size_t)(m0 + r)*FF + n0 + c] = __float2half(sa * gel);
    }
#endif
}

// ================= LayerNorm (warp per row, half out) =================
__global__ void layernorm_kernel(const float* __restrict__ in,
                                 const float* __restrict__ g,
                                 const float* __restrict__ bta,
                                 __half* __restrict__ out)
{
    int w = threadIdx.x >> 5, lane = threadIdx.x & 31;
    size_t row = (size_t)blockIdx.x*8 + w;
    const float4* p = (const float4*)(in + row*CCH);
    float4 v[5];
    float s = 0.f, ss = 0.f;
    #pragma unroll
    for (int i = 0; i < 5; i++) {
        v[i] = p[lane + 32*i];
        s  += v[i].x + v[i].y + v[i].z + v[i].w;
        ss += v[i].x*v[i].x + v[i].y*v[i].y + v[i].z*v[i].z + v[i].w*v[i].w;
    }
    #pragma unroll
    for (int o = 16; o >= 1; o >>= 1) {
        s  += __shfl_xor_sync(0xffffffffu, s, o);
        ss += __shfl_xor_sync(0xffffffffu, ss, o);
    }
    float mean = s * (1.f/CCH);
    float rstd = rsqrtf(ss * (1.f/CCH) - mean*mean + 1e-5f);
    const float4* g4 = (const float4*)g;
    const float4* b4 = (const float4*)bta;
    __half* o = out + row*CCH;
    #pragma unroll
    for (int i = 0; i < 5; i++) {
        float4 gg = g4[lane + 32*i], bb = b4[lane + 32*i];
        __half2 h01 = __floats2half2_rn((v[i].x - mean)*rstd*gg.x + bb.x,
                                        (v[i].y - mean)*rstd*gg.y + bb.y);
        __half2 h23 = __floats2half2_rn((v[i].z - mean)*rstd*gg.z + bb.z,
                                        (v[i].w - mean)*rstd*gg.w + bb.w);
        uint2 u;
        u.x = *(uint32_t*)&h01;
        u.y = *(uint32_t*)&h23;
        *(uint2*)(o + (size_t)(lane + 32*i)*4) = u;
    }
}

// ============ flash attention (fp16 m16n8k16, double-buffered KV, half out) =
#define FTQ 128
#define FTJ 64
#define AQ_STR 88
#define AK_STR 88
#define AV_STR 72
#define AP_STR 72
#define AKV_BUF (FTJ*AK_STR + DH*AV_STR)
#define FLASH_SMEM ((FTQ*AQ_STR + 2*AKV_BUF) * (int)sizeof(__half))

__global__ __launch_bounds__(256, 1)
void flash_attn_f16_kernel(const __half* __restrict__ Q, const __half* __restrict__ K,
                           const __half* __restrict__ Vt, __half* __restrict__ O,
                           int Lk, int Lpad)
{
    extern __shared__ __half smh[];
    __half* QPs = smh;
    __half* KV0 = smh + FTQ*AQ_STR;

    int tid = threadIdx.x, lane = tid & 31, w = tid >> 5;
    int qr = lane >> 2, qc = lane & 3;
    int bh = blockIdx.y;
    int b = bh / HEADS, h = bh % HEADS;
    int i0 = blockIdx.x * FTQ;

    const __half* qb  = Q  + ((size_t)(b*HW) + i0)*CCH + h*DH;
    const __half* kb  = K  + (size_t)b*Lk*CCH + h*DH;
    const __half* vtb = Vt + (size_t)bh*DH*Lpad;

    int kv_r = tid >> 2, kv_c = tid & 3;
    auto load_kv = [&](int buf, int j0) {
        __half* Ks = KV0 + buf*AKV_BUF;
        __half* Vs = Ks + FTJ*AK_STR;
        {
            int gj = j0 + kv_r;
            int gjc = (gj < Lk) ? gj : (Lk - 1);
            const __half* src = kb + (size_t)gjc*CCH;
            for (int c = kv_c; c < 10; c += 4)
                cp_async16(Ks + kv_r*AK_STR + c*8, src + c*8, true);
        }
        for (int d = kv_r; d < DH; d += 64) {
            const __half* src = vtb + (size_t)d*Lpad + j0;
            for (int c = kv_c; c < 8; c += 4)
                cp_async16(Vs + d*AV_STR + c*8, src + c*8, true);
        }
    };

    load_kv(0, 0);
    cp_commit();
    for (int idx = tid; idx < FTQ*10; idx += 256) {
        int i = idx / 10, c = idx % 10;
        *(uint4*)(QPs + (size_t)i*AQ_STR + c*8) = *(const uint4*)(qb + (size_t)i*CCH + c*8);
    }
    __syncthreads();

    int r0 = w*16 + qr;
    uint32_t qf[5][4];
    #pragma unroll
    for (int kk = 0; kk < 5; kk++) {
        int d0 = kk*16 + 2*qc;
        qf[kk][0] = *(const uint32_t*)(QPs + (size_t)r0*AQ_STR + d0);
        qf[kk][1] = *(const uint32_t*)(QPs + (size_t)(r0+8)*AQ_STR + d0);
        qf[kk][2] = *(const uint32_t*)(QPs + (size_t)r0*AQ_STR + d0 + 8);
        qf[kk][3] = *(const uint32_t*)(QPs + (size_t)(r0+8)*AQ_STR + d0 + 8);
    }
    __syncthreads();

    float m0v = -1e30f, m1v = -1e30f, l0 = 0.f, l1 = 0.f;
    float oacc[10][4];
    #pragma unroll
    for (int nt = 0; nt < 10; nt++)
        #pragma unroll
        for (int r = 0; r < 4; r++) oacc[nt][r] = 0.f;

    int nchunks = (Lk + FTJ - 1) / FTJ;
    for (int c = 0; c < nchunks; c++) {
        int buf = c & 1;
        if (c + 1 < nchunks) {
            load_kv(buf ^ 1, (c + 1)*FTJ);
            cp_commit();
            cp_wait1();
        } else {
            cp_wait0();
        }
        __syncthreads();

        __half* Ks = KV0 + buf*AKV_BUF;
        __half* Vs = Ks + FTJ*AK_STR;
        int j0 = c*FTJ;

        float sc[8][4];
        #pragma unroll
        for (int nt = 0; nt < 8; nt++)
            #pragma unroll
            for (int r = 0; r < 4; r++) sc[nt][r] = 0.f;

        #pragma unroll
        for (int kk = 0; kk < 5; kk++) {
            int d0 = kk*16 + 2*qc;
            #pragma unroll
            for (int nt = 0; nt < 8; nt++) {
                int j = nt*8 + qr;
                uint32_t b0 = *(const uint32_t*)(Ks + (size_t)j*AK_STR + d0);
                uint32_t b1 = *(const uint32_t*)(Ks + (size_t)j*AK_STR + d0 + 8);
                mma_f16(sc[nt][0], sc[nt][1], sc[nt][2], sc[nt][3],
                        qf[kk][0], qf[kk][1], qf[kk][2], qf[kk][3], b0, b1);
            }
        }

        if (j0 + FTJ > Lk) {
            #pragma unroll
            for (int nt = 0; nt < 8; nt++) {
                int jc = j0 + nt*8 + qc*2;
                if (jc   >= Lk) { sc[nt][0] = -1e30f; sc[nt][2] = -1e30f; }
                if (jc+1 >= Lk) { sc[nt][1] = -1e30f; sc[nt][3] = -1e30f; }
            }
        }

        float mx0 = -1e30f, mx1 = -1e30f;
        #pragma unroll
        for (int nt = 0; nt < 8; nt++) {
            mx0 = fmaxf(mx0, fmaxf(sc[nt][0], sc[nt][1]));
            mx1 = fmaxf(mx1, fmaxf(sc[nt][2], sc[nt][3]));
        }
        mx0 = fmaxf(mx0, __shfl_xor_sync(0xffffffffu, mx0, 1));
        mx0 = fmaxf(mx0, __shfl_xor_sync(0xffffffffu, mx0, 2));
        mx1 = fmaxf(mx1, __shfl_xor_sync(0xffffffffu, mx1, 1));
        mx1 = fmaxf(mx1, __shfl_xor_sync(0xffffffffu, mx1, 2));

        float mn0 = fmaxf(m0v, mx0), mn1 = fmaxf(m1v, mx1);
        float al0 = __expf(m0v - mn0), al1 = __expf(m1v - mn1);
        float rs0 = 0.f, rs1 = 0.f;
        #pragma unroll
        for (int nt = 0; nt < 8; nt++) {
            sc[nt][0] = __expf(sc[nt][0] - mn0);
            sc[nt][1] = __expf(sc[nt][1] - mn0);
            sc[nt][2] = __expf(sc[nt][2] - mn1);
            sc[nt][3] = __expf(sc[nt][3] - mn1);
            rs0 += sc[nt][0] + sc[nt][1];
            rs1 += sc[nt][2] + sc[nt][3];
        }
        rs0 += __shfl_xor_sync(0xffffffffu, rs0, 1);
        rs0 += __shfl_xor_sync(0xffffffffu, rs0, 2);
        rs1 += __shfl_xor_sync(0xffffffffu, rs1, 1);
        rs1 += __shfl_xor_sync(0xffffffffu, rs1, 2);

        l0 = l0*al0 + rs0;  m0v = mn0;
        l1 = l1*al1 + rs1;  m1v = mn1;

        #pragma unroll
        for (int nt = 0; nt < 10; nt++) {
            oacc[nt][0] *= al0; oacc[nt][1] *= al0;
            oacc[nt][2] *= al1; oacc[nt][3] *= al1;
        }

        __half* Ps = QPs;
        #pragma unroll
        for (int nt = 0; nt < 8; nt++) {
            int jc = nt*8 + qc*2;
            *(__half2*)(Ps + (size_t)r0*AP_STR + jc)     = __floats2half2_rn(sc[nt][0], sc[nt][1]);
            *(__half2*)(Ps + (size_t)(r0+8)*AP_STR + jc) = __floats2half2_rn(sc[nt][2], sc[nt][3]);
        }
        __syncwarp();

        #pragma unroll
        for (int kk = 0; kk < 4; kk++) {
            int jb = kk*16 + 2*qc;
            uint32_t a0 = *(const uint32_t*)(Ps + (size_t)r0*AP_STR + jb);
            uint32_t a1 = *(const uint32_t*)(Ps + (size_t)(r0+8)*AP_STR + jb);
            uint32_t a2 = *(const uint32_t*)(Ps + (size_t)r0*AP_STR + jb + 8);
            uint32_t a3 = *(const uint32_t*)(Ps + (size_t)(r0+8)*AP_STR + jb + 8);
            #pragma unroll
            for (int nt = 0; nt < 10; nt++) {
                int d = nt*8 + qr;
                uint32_t b0 = *(const uint32_t*)(Vs + (size_t)d*AV_STR + jb);
                uint32_t b1 = *(const uint32_t*)(Vs + (size_t)d*AV_STR + jb + 8);
                mma_f16(oacc[nt][0], oacc[nt][1], oacc[nt][2], oacc[nt][3],
                        a0, a1, a2, a3, b0, b1);
            }
        }
        __syncthreads();
    }

    float inv0 = 1.f / l0, inv1 = 1.f / l1;
    __half* ob = O + ((size_t)(b*HW) + i0 + r0)*CCH + h*DH;
    #pragma unroll
    for (int nt = 0; nt < 10; nt++) {
        int dc = nt*8 + qc*2;
        *(__half2*)(ob + dc)                 = __floats2half2_rn(oacc[nt][0]*inv0, oacc[nt][1]*inv0);
        *(__half2*)(ob + (size_t)8*CCH + dc) = __floats2half2_rn(oacc[nt][2]*inv1, oacc[nt][3]*inv1);
    }
}

extern "C" void kernel_launch(void* const* d_in, const int* in_sizes, int n_in,
                              void* d_out, int out_size)
{
    const float* x       = (const float*)d_in[0];
    const float* context = (const float*)d_in[1];
    const float* gn_g    = (const float*)d_in[2];
    const float* gn_b    = (const float*)d_in[3];
    const float* w_in    = (const float*)d_in[4];
    const float* b_in    = (const float*)d_in[5];
    const float* ln1_g   = (const float*)d_in[6];
    const float* ln1_b   = (const float*)d_in[7];
    const float* wq1     = (const float*)d_in[8];
    const float* wk1     = (const float*)d_in[9];
    const float* wv1     = (const float*)d_in[10];
    const float* wo1     = (const float*)d_in[11];
    const float* bo1     = (const float*)d_in[12];
    const float* ln2_g   = (const float*)d_in[13];
    const float* ln2_b   = (const float*)d_in[14];
    const float* wq2     = (const float*)d_in[15];
    const float* wk2     = (const float*)d_in[16];
    const float* wv2     = (const float*)d_in[17];
    const float* wo2     = (const float*)d_in[18];
    const float* bo2     = (const float*)d_in[19];
    const float* ln3_g   = (const float*)d_in[20];
    const float* ln3_b   = (const float*)d_in[21];
    const float* w_geglu = (const float*)d_in[22];
    const float* b_geglu = (const float*)d_in[23];
    const float* w_ffo   = (const float*)d_in[24];
    const float* b_ffo   = (const float*)d_in[25];
    const float* w_out   = (const float*)d_in[26];
    const float* b_out   = (const float*)d_in[27];
    float* out = (float*)d_out;

    float *p_t, *p_q, *p_qkv, *p_kv, *p_stats;
    __half *p_tnh, *p_aoh, *p_ffh, *p_th, *p_ctxh, *p_wth, *p_qh, *p_kh, *p_vth;
    cudaGetSymbolAddress((void**)&p_t,    g_t);
    cudaGetSymbolAddress((void**)&p_q,    g_q);
    cudaGetSymbolAddress((void**)&p_qkv,  g_qkv);
    cudaGetSymbolAddress((void**)&p_kv,   g_kv);
    cudaGetSymbolAddress((void**)&p_stats,g_stats);
    cudaGetSymbolAddress((void**)&p_tnh,  g_tnh);
    cudaGetSymbolAddress((void**)&p_aoh,  g_aoh);
    cudaGetSymbolAddress((void**)&p_ffh,  g_ffh);
    cudaGetSymbolAddress((void**)&p_th,   g_th);
    cudaGetSymbolAddress((void**)&p_ctxh, g_ctxh);
    cudaGetSymbolAddress((void**)&p_wth,  g_wth);
    cudaGetSymbolAddress((void**)&p_qh,   g_qh);
    cudaGetSymbolAddress((void**)&p_kh,   g_kh);
    cudaGetSymbolAddress((void**)&p_vth,  g_vth);

    cudaFuncSetAttribute(flash_attn_f16_kernel,
                         cudaFuncAttributeMaxDynamicSharedMemorySize, FLASH_SMEM);
    cudaFuncSetAttribute(gemm_h_kernel,
                         cudaFuncAttributeMaxDynamicSharedMemorySize, GEMMH_SMEM);
    cudaFuncSetAttribute(gemm_out_h_kernel,
                         cudaFuncAttributeMaxDynamicSharedMemorySize, GEMMH_SMEM);
    cudaFuncSetAttribute(gemm_h256_kernel,
                         cudaFuncAttributeMaxDynamicSharedMemorySize, GEMMH256_SMEM);
    cudaFuncSetAttribute(geglu_h_kernel,
                         cudaFuncAttributeMaxDynamicSharedMemorySize, GEGLUH_SMEM);

    dim3 tb(32, 8);
    dim3 tp_grid(HW/32, CCH/32, BATCH);
    const float qscale = 0.1118033988749895f;

    #define TWH(w_, dst_, K_, N_) \
        transpose_wh<<<dim3((N_)/32, (K_)/32), tb>>>(w_, dst_, K_, N_)
    #define GEMM_H(A_, Bt_, bias_, C_, M_, N_, K_, acc_) \
        gemm_h_kernel<<<dim3((N_)/128, ((M_)+127)/128), 256, GEMMH_SMEM>>>( \
            A_, Bt_, bias_, C_, M_, N_, K_, acc_)

    // 1) GroupNorm -> token-major half
    gn_stats_kernel<<<BATCH*GROUPS, 256>>>(x, p_stats);
    gn_apply_kernel<<<tp_grid, tb>>>(x, gn_g, gn_b, p_stats, p_tnh);
    cvt_f2h<<<(BATCH*CTX*CTXD/2 + 255)/256, 256>>>(context, p_ctxh, (size_t)BATCH*CTX*CTXD);

    // 2) proj_in
    TWH(w_in, p_wth, CCH, CCH);
    GEMM_H(p_tnh, p_wth, b_in, p_t, MTOK, CCH, CCH, 0);

    // 3) self-attention (packed QKV, fp16 flash)
    layernorm_kernel<<<MTOK/8, 256>>>(p_t, ln1_g, ln1_b, p_tnh);
    TWH(wq1, p_wth,             CCH, CCH);
    TWH(wk1, p_wth + 640*640,   CCH, CCH);
    TWH(wv1, p_wth + 2*640*640, CCH, CCH);
    gemm_h256_kernel<<<dim3(1920/128, MTOK/256), 256, GEMMH256_SMEM>>>(
        p_tnh, p_wth, nullptr, p_qkv, MTOK, 1920, CCH, 0);
    cvt_half_kernel<<<(MTOK*320 + 255)/256, 256>>>(p_qkv,       1920, qscale, p_qh, MTOK);
    cvt_half_kernel<<<(MTOK*320 + 255)/256, 256>>>(p_qkv + 640, 1920, 1.0f,   p_kh, MTOK);
    cvt_vt_kernel<<<dim3(HW/32, 3, 64), tb>>>(p_qkv, 1920, 1280, p_vth, HW, HW);
    flash_attn_f16_kernel<<<dim3(HW/FTQ, BATCH*HEADS), 256, FLASH_SMEM>>>(
        p_qh, p_kh, p_vth, p_aoh, HW, HW);
    TWH(wo1, p_wth, CCH, CCH);
    GEMM_H(p_aoh, p_wth, bo1, p_t, MTOK, CCH, CCH, 1);

    // 4) cross-attention
    layernorm_kernel<<<MTOK/8, 256>>>(p_t, ln2_g, ln2_b, p_tnh);
    TWH(wq2, p_wth, CCH, CCH);
    GEMM_H(p_tnh, p_wth, nullptr, p_q, MTOK, CCH, CCH, 0);
    TWH(wk2, p_wth,           CTXD, CCH);
    TWH(wv2, p_wth + 640*768, CTXD, CCH);
    GEMM_H(p_ctxh, p_wth, nullptr, p_kv, BATCH*CTX, 1280, CTXD, 0);
    cvt_half_kernel<<<(MTOK*320 + 255)/256, 256>>>(p_q, 640, qscale, p_qh, MTOK);
    cvt_half_kernel<<<(BATCH*CTX*320 + 255)/256, 256>>>(p_kv, 1280, 1.0f, p_kh, BATCH*CTX);
    cvt_vt_kernel<<<dim3(128/32, 3, 64), tb>>>(p_kv, 1280, 640, p_vth, CTX, 128);
    flash_attn_f16_kernel<<<dim3(HW/FTQ, BATCH*HEADS), 256, FLASH_SMEM>>>(
        p_qh, p_kh, p_vth, p_aoh, CTX, 128);
    TWH(wo2, p_wth, CCH, CCH);
    GEMM_H(p_aoh, p_wth, bo2, p_t, MTOK, CCH, CCH, 1);

    // 5) GEGLU FF (fused, half out) + FFO
    layernorm_kernel<<<MTOK/8, 256>>>(p_t, ln3_g, ln3_b, p_tnh);
    TWH(w_geglu, p_wth, CCH, 2*FF);
    geglu_h_kernel<<<dim3(FF/128, MTOK/256), 256, GEGLUH_SMEM>>>(
        p_tnh, p_wth, p_wth + (size_t)FF*CCH, b_geglu, p_ffh, MTOK, CCH);
    TWH(w_ffo, p_wth, FF, CCH);
    GEMM_H(p_ffh, p_wth, b_ffo, p_t, MTOK, CCH, FF, 1);

    // 6) proj_out fused with transpose + input residual
    TWH(w_out, p_wth, CCH, CCH);
    cvt_f2h<<<(MTOK*CCH/2 + 255)/256, 256>>>(p_t, p_th, (size_t)MTOK*CCH);
    gemm_out_h_kernel<<<dim3(CCH/128, MTOK/128), 256, GEMMH_SMEM>>>(
        p_th, p_wth, b_out, x, out, CCH);
}